// round 1
// baseline (speedup 1.0000x reference)
#include <cuda_runtime.h>
#include <math.h>

// ---------------- problem constants ----------------
#define B   8
#define T   4096
#define D_IN 256
#define D   512
#define LQ  256
#define H   8
#define HD  64
#define NB  6
#define HID 2048

// ---------------- scratch (static device globals; no allocation) ----------------
__device__ float g_x   [B*T*D];          // projected tokens (B*T, D)
__device__ float g_kv  [B*T*2*D];        // per-block K|V    (B*T, 2D)
__device__ float g_lat [B*LQ*D];         // latents          (B*LQ, D)
__device__ float g_tmp [B*LQ*D];         // LN output
__device__ float g_q   [B*LQ*D];         // cross Q
__device__ float g_sqkv[B*LQ*3*D];       // self QKV
__device__ float g_S   [B*H*LQ*T];       // attention scores (largest: 268MB)
__device__ float g_attn[B*LQ*D];         // attention output
__device__ float g_hid [B*LQ*HID];       // MLP hidden

// ---------------- reductions ----------------
__device__ __forceinline__ float block_sum256(float v, float* sh) {
    #pragma unroll
    for (int o = 16; o; o >>= 1) v += __shfl_xor_sync(0xffffffffu, v, o);
    if ((threadIdx.x & 31) == 0) sh[threadIdx.x >> 5] = v;
    __syncthreads();
    float t = (threadIdx.x < 8) ? sh[threadIdx.x] : 0.f;
    if (threadIdx.x < 32) {
        #pragma unroll
        for (int o = 4; o; o >>= 1) t += __shfl_xor_sync(0xffffffffu, t, o);
        if (threadIdx.x == 0) sh[0] = t;
    }
    __syncthreads();
    float r = sh[0];
    __syncthreads();
    return r;
}

// ---------------- GEMM: C[m,n] = A[m,:]·W[n,:] + bias[n]  (+gelu)(+res) ----------------
// 128x128 tile, BK=8, 8x8 microtile, 256 threads. K % 8 == 0, M % 128 == 0, N % 128 == 0.
template<bool GELU>
__global__ void gemm128(const float* __restrict__ A, const float* __restrict__ W,
                        const float* __restrict__ bias, float* __restrict__ C,
                        const float* __restrict__ res, int M, int N, int K)
{
    __shared__ __align__(16) float As[8][128];
    __shared__ __align__(16) float Ws[8][128];
    const int bm = blockIdx.y * 128, bn = blockIdx.x * 128;
    const int tid = threadIdx.x;
    const int tx = tid & 15, ty = tid >> 4;
    const int lr = tid >> 1, lc = (tid & 1) * 4;
    float acc[8][8];
    #pragma unroll
    for (int i = 0; i < 8; i++)
        #pragma unroll
        for (int j = 0; j < 8; j++) acc[i][j] = 0.f;

    for (int k0 = 0; k0 < K; k0 += 8) {
        float4 av = *(const float4*)&A[(size_t)(bm + lr) * K + k0 + lc];
        As[lc + 0][lr] = av.x; As[lc + 1][lr] = av.y; As[lc + 2][lr] = av.z; As[lc + 3][lr] = av.w;
        float4 wv = *(const float4*)&W[(size_t)(bn + lr) * K + k0 + lc];
        Ws[lc + 0][lr] = wv.x; Ws[lc + 1][lr] = wv.y; Ws[lc + 2][lr] = wv.z; Ws[lc + 3][lr] = wv.w;
        __syncthreads();
        #pragma unroll
        for (int k = 0; k < 8; k++) {
            float a[8], bb[8];
            *(float4*)&a[0]  = *(const float4*)&As[k][ty * 8];
            *(float4*)&a[4]  = *(const float4*)&As[k][ty * 8 + 4];
            *(float4*)&bb[0] = *(const float4*)&Ws[k][tx * 8];
            *(float4*)&bb[4] = *(const float4*)&Ws[k][tx * 8 + 4];
            #pragma unroll
            for (int i = 0; i < 8; i++)
                #pragma unroll
                for (int j = 0; j < 8; j++) acc[i][j] += a[i] * bb[j];
        }
        __syncthreads();
    }
    #pragma unroll
    for (int i = 0; i < 8; i++) {
        size_t m = bm + ty * 8 + i;
        float* crow = C + m * (size_t)N + bn + tx * 8;
        const float* brow = bias + bn + tx * 8;
        const float* rrow = res ? res + m * (size_t)N + bn + tx * 8 : (const float*)0;
        #pragma unroll
        for (int j = 0; j < 8; j++) {
            float v = acc[i][j] + brow[j];
            if (GELU) v = 0.5f * v * (1.0f + erff(v * 0.70710678118654752f));
            if (rrow) v += rrow[j];
            crow[j] = v;
        }
    }
}

// 64x64 tile, BK=16, 4x4 microtile, 256 threads. K % 16 == 0, M % 64 == 0, N % 64 == 0.
template<bool GELU>
__global__ void gemm64(const float* __restrict__ A, const float* __restrict__ W,
                       const float* __restrict__ bias, float* __restrict__ C,
                       const float* __restrict__ res, int M, int N, int K)
{
    __shared__ __align__(16) float As[16][64];
    __shared__ __align__(16) float Ws[16][64];
    const int bm = blockIdx.y * 64, bn = blockIdx.x * 64;
    const int tid = threadIdx.x;
    const int tx = tid & 15, ty = tid >> 4;
    const int lr = tid >> 2, lc = (tid & 3) * 4;
    float acc[4][4];
    #pragma unroll
    for (int i = 0; i < 4; i++)
        #pragma unroll
        for (int j = 0; j < 4; j++) acc[i][j] = 0.f;

    for (int k0 = 0; k0 < K; k0 += 16) {
        float4 av = *(const float4*)&A[(size_t)(bm + lr) * K + k0 + lc];
        As[lc + 0][lr] = av.x; As[lc + 1][lr] = av.y; As[lc + 2][lr] = av.z; As[lc + 3][lr] = av.w;
        float4 wv = *(const float4*)&W[(size_t)(bn + lr) * K + k0 + lc];
        Ws[lc + 0][lr] = wv.x; Ws[lc + 1][lr] = wv.y; Ws[lc + 2][lr] = wv.z; Ws[lc + 3][lr] = wv.w;
        __syncthreads();
        #pragma unroll
        for (int k = 0; k < 16; k++) {
            float a[4], bb[4];
            *(float4*)&a[0]  = *(const float4*)&As[k][ty * 4];
            *(float4*)&bb[0] = *(const float4*)&Ws[k][tx * 4];
            #pragma unroll
            for (int i = 0; i < 4; i++)
                #pragma unroll
                for (int j = 0; j < 4; j++) acc[i][j] += a[i] * bb[j];
        }
        __syncthreads();
    }
    #pragma unroll
    for (int i = 0; i < 4; i++) {
        size_t m = bm + ty * 4 + i;
        float* crow = C + m * (size_t)N + bn + tx * 4;
        const float* brow = bias + bn + tx * 4;
        const float* rrow = res ? res + m * (size_t)N + bn + tx * 4 : (const float*)0;
        #pragma unroll
        for (int j = 0; j < 4; j++) {
            float v = acc[i][j] + brow[j];
            if (GELU) v = 0.5f * v * (1.0f + erff(v * 0.70710678118654752f));
            if (rrow) v += rrow[j];
            crow[j] = v;
        }
    }
}

// ---------------- LayerNorm over D=512 ; one block (256 thr) per row ----------------
__global__ void ln_kernel(const float* __restrict__ x, const float* __restrict__ g,
                          const float* __restrict__ b, float* __restrict__ y)
{
    __shared__ float sh[32];
    const int row = blockIdx.x, tid = threadIdx.x;
    const float* xr = x + (size_t)row * D;
    float2 v = *(const float2*)&xr[tid * 2];
    float total = block_sum256(v.x + v.y, sh);
    float mean = total * (1.0f / D);
    float d0 = v.x - mean, d1 = v.y - mean;
    float sq = block_sum256(d0 * d0 + d1 * d1, sh);
    float inv = rsqrtf(sq * (1.0f / D) + 1e-5f);
    float2 go = *(const float2*)&g[tid * 2];
    float2 bo = *(const float2*)&b[tid * 2];
    float2 o;
    o.x = d0 * inv * go.x + bo.x;
    o.y = d1 * inv * go.y + bo.y;
    *(float2*)&y[(size_t)row * D + tid * 2] = o;
}

// ---------------- attention scores: S[bh,q,k] = scale*Qh·Kh (+ mask) ----------------
// grid (Tk/64, LQ/32, B*H), 256 threads; each thread 2q x 4k outputs.
__global__ void scores_kernel(const float* __restrict__ Q, int ldq,
                              const float* __restrict__ Km, int ldk,
                              float* __restrict__ S, int Tk,
                              const float* __restrict__ relbias,
                              const float* __restrict__ msp, float scale)
{
    __shared__ __align__(16) float Qs[HD][32];
    __shared__ __align__(16) float Ks[HD][64];
    const int bh = blockIdx.z, b = bh >> 3, h = bh & 7;
    const int q0 = blockIdx.y * 32, k0 = blockIdx.x * 64;
    const int tid = threadIdx.x;
    {   // load Q tile: 32 x 64
        int q = tid >> 3, d = (tid & 7) * 8;
        const float* src = Q + ((size_t)(b * LQ + q0 + q) * ldq + h * HD + d);
        float4 v0 = *(const float4*)src;
        float4 v1 = *(const float4*)(src + 4);
        Qs[d + 0][q] = v0.x; Qs[d + 1][q] = v0.y; Qs[d + 2][q] = v0.z; Qs[d + 3][q] = v0.w;
        Qs[d + 4][q] = v1.x; Qs[d + 5][q] = v1.y; Qs[d + 6][q] = v1.z; Qs[d + 7][q] = v1.w;
    }
    {   // load K tile: 64 x 64
        int k = tid >> 2, d = (tid & 3) * 16;
        const float* src = Km + ((size_t)((size_t)b * Tk + k0 + k) * ldk + h * HD + d);
        #pragma unroll
        for (int u = 0; u < 4; u++) {
            float4 v = *(const float4*)(src + u * 4);
            Ks[d + u * 4 + 0][k] = v.x; Ks[d + u * 4 + 1][k] = v.y;
            Ks[d + u * 4 + 2][k] = v.z; Ks[d + u * 4 + 3][k] = v.w;
        }
    }
    __syncthreads();
    const int tx = tid & 15, ty = tid >> 4;
    float acc[2][4];
    #pragma unroll
    for (int i = 0; i < 2; i++)
        #pragma unroll
        for (int j = 0; j < 4; j++) acc[i][j] = 0.f;
    #pragma unroll
    for (int d = 0; d < HD; d++) {
        float a0 = Qs[d][ty], a1 = Qs[d][ty + 16];
        float4 bv = *(const float4*)&Ks[d][tx * 4];
        acc[0][0] += a0 * bv.x; acc[0][1] += a0 * bv.y; acc[0][2] += a0 * bv.z; acc[0][3] += a0 * bv.w;
        acc[1][0] += a1 * bv.x; acc[1][1] += a1 * bv.y; acc[1][2] += a1 * bv.z; acc[1][3] += a1 * bv.w;
    }
    const float msv = msp ? *msp : 0.f;
    #pragma unroll
    for (int qi = 0; qi < 2; qi++) {
        int q = q0 + ty + qi * 16;
        float tau = (float)q * (4095.0f / 255.0f);   // linspace(0, T-1, LQ) step
        #pragma unroll
        for (int j = 0; j < 4; j++) {
            int kk = k0 + tx * 4 + j;
            float v = acc[qi][j] * scale;
            if (relbias) {
                float dt = (float)kk - tau;
                float c = fminf(fmaxf(dt, -128.f), 128.f);
                int idx = (int)c + 128;                  // trunc toward zero, matches astype(int32)
                float z = dt * (1.0f / 32.0f);
                float lg = logf(expf(-0.5f * z * z) + 1e-6f);
                v += msv * (relbias[idx] + lg);
            }
            S[((size_t)bh * LQ + q) * (size_t)Tk + kk] = v;
        }
    }
}

// ---------------- softmax over last dim; one block per row ----------------
__global__ void softmax_kernel(float* __restrict__ S, int Tk)
{
    __shared__ float sh[32];
    float* r = S + (size_t)blockIdx.x * Tk;
    const int tid = threadIdx.x;
    float m = -3.4e38f;
    for (int i = tid; i < Tk; i += 256) m = fmaxf(m, r[i]);
    #pragma unroll
    for (int o = 16; o; o >>= 1) m = fmaxf(m, __shfl_xor_sync(0xffffffffu, m, o));
    if ((tid & 31) == 0) sh[tid >> 5] = m;
    __syncthreads();
    if (tid < 32) {
        float t = (tid < 8) ? sh[tid] : -3.4e38f;
        #pragma unroll
        for (int o = 4; o; o >>= 1) t = fmaxf(t, __shfl_xor_sync(0xffffffffu, t, o));
        if (tid == 0) sh[0] = t;
    }
    __syncthreads();
    float M = sh[0];
    __syncthreads();
    float s = 0.f;
    for (int i = tid; i < Tk; i += 256) { float e = expf(r[i] - M); r[i] = e; s += e; }
    float total = block_sum256(s, sh);
    float inv = 1.0f / total;
    for (int i = tid; i < Tk; i += 256) r[i] *= inv;
}

// ---------------- O[b,q,h*64+d] = sum_k A[bh,q,k] * V[b,k,h*64+d] ----------------
// grid (LQ/32, B*H), 256 threads.
__global__ void av_kernel(const float* __restrict__ A, int Tk,
                          const float* __restrict__ V, int ldv,
                          float* __restrict__ O)
{
    __shared__ float Asm[32][33];
    __shared__ __align__(16) float Vs[32][HD];
    const int bh = blockIdx.y, b = bh >> 3, h = bh & 7;
    const int q0 = blockIdx.x * 32;
    const int tid = threadIdx.x;
    const int tx = tid & 15, ty = tid >> 4;
    float acc[2][4];
    #pragma unroll
    for (int i = 0; i < 2; i++)
        #pragma unroll
        for (int j = 0; j < 4; j++) acc[i][j] = 0.f;

    for (int kt = 0; kt < Tk; kt += 32) {
        {
            int q = tid >> 3, k = (tid & 7) * 4;
            float4 v = *(const float4*)&A[((size_t)bh * LQ + q0 + q) * (size_t)Tk + kt + k];
            Asm[q][k] = v.x; Asm[q][k + 1] = v.y; Asm[q][k + 2] = v.z; Asm[q][k + 3] = v.w;
        }
        {
            int k = tid >> 3, d = (tid & 7) * 8;
            const float* src = V + ((size_t)((size_t)b * Tk + kt + k) * ldv + h * HD + d);
            float4 v0 = *(const float4*)src;
            float4 v1 = *(const float4*)(src + 4);
            Vs[k][d + 0] = v0.x; Vs[k][d + 1] = v0.y; Vs[k][d + 2] = v0.z; Vs[k][d + 3] = v0.w;
            Vs[k][d + 4] = v1.x; Vs[k][d + 5] = v1.y; Vs[k][d + 6] = v1.z; Vs[k][d + 7] = v1.w;
        }
        __syncthreads();
        #pragma unroll
        for (int k = 0; k < 32; k++) {
            float a0 = Asm[ty][k], a1 = Asm[ty + 16][k];
            float4 bv = *(const float4*)&Vs[k][tx * 4];
            acc[0][0] += a0 * bv.x; acc[0][1] += a0 * bv.y; acc[0][2] += a0 * bv.z; acc[0][3] += a0 * bv.w;
            acc[1][0] += a1 * bv.x; acc[1][1] += a1 * bv.y; acc[1][2] += a1 * bv.z; acc[1][3] += a1 * bv.w;
        }
        __syncthreads();
    }
    #pragma unroll
    for (int qi = 0; qi < 2; qi++) {
        int q = q0 + ty + qi * 16;
        float* dst = O + ((size_t)(b * LQ + q) * D + h * HD + tx * 4);
        dst[0] = acc[qi][0]; dst[1] = acc[qi][1]; dst[2] = acc[qi][2]; dst[3] = acc[qi][3];
    }
}

// ---------------- misc ----------------
__global__ void bcast_latents(const float* __restrict__ src, float* __restrict__ dst)
{
    int i = blockIdx.x * 256 + threadIdx.x;
    dst[i] = src[i % (LQ * D)];
}

__global__ void mean_kernel(const float* __restrict__ x, float* __restrict__ out)
{
    int i = blockIdx.x * 256 + threadIdx.x;   // B*D total
    int b = i / D, d = i % D;
    float s = 0.f;
    for (int q = 0; q < LQ; q++) s += x[((size_t)b * LQ + q) * D + d];
    out[i] = s * (1.0f / LQ);
}

// ---------------- host orchestration ----------------
extern "C" void kernel_launch(void* const* d_in, const int* in_sizes, int n_in,
                              void* d_out, int out_size)
{
    (void)in_sizes; (void)n_in; (void)out_size;
    const float* tokens     = (const float*)d_in[0];
    const float* proj_w     = (const float*)d_in[1];
    const float* proj_b     = (const float*)d_in[2];
    const float* latents    = (const float*)d_in[3];
    const float* lnx_g      = (const float*)d_in[4];
    const float* lnx_b      = (const float*)d_in[5];
    const float* xw_qkv     = (const float*)d_in[6];
    const float* xb_qkv     = (const float*)d_in[7];
    const float* xw_o       = (const float*)d_in[8];
    const float* xb_o       = (const float*)d_in[9];
    const float* rel_bias   = (const float*)d_in[10];
    const float* mask_scale = (const float*)d_in[11];
    const float* mx_w1      = (const float*)d_in[12];
    const float* mx_b1      = (const float*)d_in[13];
    const float* mx_w2      = (const float*)d_in[14];
    const float* mx_b2      = (const float*)d_in[15];
    const float* lns_g      = (const float*)d_in[16];
    const float* lns_b      = (const float*)d_in[17];
    const float* sw_qkv     = (const float*)d_in[18];
    const float* sb_qkv     = (const float*)d_in[19];
    const float* sw_o       = (const float*)d_in[20];
    const float* sb_o       = (const float*)d_in[21];
    const float* ms_w1      = (const float*)d_in[22];
    const float* ms_b1      = (const float*)d_in[23];
    const float* ms_w2      = (const float*)d_in[24];
    const float* ms_b2      = (const float*)d_in[25];
    const float* lno_g      = (const float*)d_in[26];
    const float* lno_b      = (const float*)d_in[27];
    float* out = (float*)d_out;

    float *px, *pkv, *plat, *ptmp, *pq, *psq, *pS, *pat, *phid;
    cudaGetSymbolAddress((void**)&px,   g_x);
    cudaGetSymbolAddress((void**)&pkv,  g_kv);
    cudaGetSymbolAddress((void**)&plat, g_lat);
    cudaGetSymbolAddress((void**)&ptmp, g_tmp);
    cudaGetSymbolAddress((void**)&pq,   g_q);
    cudaGetSymbolAddress((void**)&psq,  g_sqkv);
    cudaGetSymbolAddress((void**)&pS,   g_S);
    cudaGetSymbolAddress((void**)&pat,  g_attn);
    cudaGetSymbolAddress((void**)&phid, g_hid);

    const float scale = 0.125f;  // 1/sqrt(64)

    // x = tokens @ proj_w.T + proj_b
    gemm128<false><<<dim3(D / 128, (B * T) / 128), 256>>>(tokens, proj_w, proj_b, px, nullptr, B * T, D, D_IN);
    // latents broadcast
    bcast_latents<<<(B * LQ * D) / 256, 256>>>(latents, plat);

    for (int i = 0; i < NB; i++) {
        const float* wqkv = xw_qkv + (size_t)i * 3 * D * D;
        const float* bqkv = xb_qkv + (size_t)i * 3 * D;

        // ---- cross attention ----
        ln_kernel<<<B * LQ, 256>>>(plat, lnx_g + i * D, lnx_b + i * D, ptmp);
        gemm64<false><<<dim3(D / 64, (B * LQ) / 64), 256>>>(ptmp, wqkv, bqkv, pq, nullptr, B * LQ, D, D);
        gemm128<false><<<dim3((2 * D) / 128, (B * T) / 128), 256>>>(px, wqkv + D * D, bqkv + D, pkv, nullptr, B * T, 2 * D, D);
        scores_kernel<<<dim3(T / 64, LQ / 32, B * H), 256>>>(pq, D, pkv, 2 * D, pS, T,
                                                             rel_bias + i * (2 * 128 + 1), mask_scale + i, scale);
        softmax_kernel<<<B * H * LQ, 256>>>(pS, T);
        av_kernel<<<dim3(LQ / 32, B * H), 256>>>(pS, T, pkv + D, 2 * D, pat);
        gemm64<false><<<dim3(D / 64, (B * LQ) / 64), 256>>>(pat, xw_o + (size_t)i * D * D, xb_o + i * D,
                                                            plat, plat, B * LQ, D, D);
        // ---- cross MLP (pre-LN reuses lnx params) ----
        ln_kernel<<<B * LQ, 256>>>(plat, lnx_g + i * D, lnx_b + i * D, ptmp);
        gemm128<true><<<dim3(HID / 128, (B * LQ) / 128), 256>>>(ptmp, mx_w1 + (size_t)i * HID * D, mx_b1 + i * HID,
                                                                phid, nullptr, B * LQ, HID, D);
        gemm64<false><<<dim3(D / 64, (B * LQ) / 64), 256>>>(phid, mx_w2 + (size_t)i * D * HID, mx_b2 + i * D,
                                                            plat, plat, B * LQ, D, HID);
        // ---- self attention ----
        ln_kernel<<<B * LQ, 256>>>(plat, lns_g + i * D, lns_b + i * D, ptmp);
        gemm128<false><<<dim3((3 * D) / 128, (B * LQ) / 128), 256>>>(ptmp, sw_qkv + (size_t)i * 3 * D * D,
                                                                     sb_qkv + (size_t)i * 3 * D, psq, nullptr,
                                                                     B * LQ, 3 * D, D);
        scores_kernel<<<dim3(LQ / 64, LQ / 32, B * H), 256>>>(psq, 3 * D, psq + D, 3 * D, pS, LQ,
                                                              nullptr, nullptr, scale);
        softmax_kernel<<<B * H * LQ, 256>>>(pS, LQ);
        av_kernel<<<dim3(LQ / 32, B * H), 256>>>(pS, LQ, psq + 2 * D, 3 * D, pat);
        gemm64<false><<<dim3(D / 64, (B * LQ) / 64), 256>>>(pat, sw_o + (size_t)i * D * D, sb_o + i * D,
                                                            plat, plat, B * LQ, D, D);
        // ---- self MLP ----
        ln_kernel<<<B * LQ, 256>>>(plat, lns_g + i * D, lns_b + i * D, ptmp);
        gemm128<true><<<dim3(HID / 128, (B * LQ) / 128), 256>>>(ptmp, ms_w1 + (size_t)i * HID * D, ms_b1 + i * HID,
                                                                phid, nullptr, B * LQ, HID, D);
        gemm64<false><<<dim3(D / 64, (B * LQ) / 64), 256>>>(phid, ms_w2 + (size_t)i * D * HID, ms_b2 + i * D,
                                                            plat, plat, B * LQ, D, HID);
    }

    // final LN + mean over latents
    ln_kernel<<<B * LQ, 256>>>(plat, lno_g, lno_b, ptmp);
    mean_kernel<<<(B * D) / 256, 256>>>(ptmp, out);
}

// round 4
// speedup vs baseline: 1.4706x; 1.4706x over previous
#include <cuda_runtime.h>
#include <cuda_bf16.h>
#include <cstdint>
#include <math.h>

// ---------------- problem constants ----------------
#define B   8
#define T   4096
#define D_IN 256
#define D   512
#define LQ  256
#define H   8
#define HD  64
#define NB  6
#define HID 2048

// ---------------- mma.sync helpers (sm_80+ PTX; no tcgen05) ----------------
__device__ __forceinline__ uint32_t smem_u32(const void* p) {
    uint32_t a;
    asm("{ .reg .u64 t; cvta.to.shared.u64 t, %1; cvt.u32.u64 %0, t; }" : "=r"(a) : "l"(p));
    return a;
}
__device__ __forceinline__ void cp16(uint32_t dst, const void* src) {
    asm volatile("cp.async.cg.shared.global [%0], [%1], 16;\n" :: "r"(dst), "l"(src));
}
__device__ __forceinline__ void ldsm4(uint32_t& r0, uint32_t& r1, uint32_t& r2, uint32_t& r3,
                                      uint32_t addr) {
    asm volatile("ldmatrix.sync.aligned.m8n8.x4.shared.b16 {%0,%1,%2,%3}, [%4];"
        : "=r"(r0), "=r"(r1), "=r"(r2), "=r"(r3) : "r"(addr));
}
__device__ __forceinline__ void mma16816(float* c, const uint32_t* a, uint32_t b0, uint32_t b1) {
    asm volatile("mma.sync.aligned.m16n8k16.row.col.f32.bf16.bf16.f32 "
        "{%0,%1,%2,%3}, {%4,%5,%6,%7}, {%8,%9}, {%0,%1,%2,%3};"
        : "+f"(c[0]), "+f"(c[1]), "+f"(c[2]), "+f"(c[3])
        : "r"(a[0]), "r"(a[1]), "r"(a[2]), "r"(a[3]), "r"(b0), "r"(b1));
}

// ---------------- scratch (static device globals; no allocation) ----------------
__device__ float g_kv  [B*T*2*D];        // per-block K|V (fp32)
__device__ float g_lat [B*LQ*D];
__device__ float g_tmpf[B*LQ*D];
__device__ float g_q   [B*LQ*D];
__device__ float g_sqkv[B*LQ*3*D];
__device__ float g_S   [B*H*LQ*T];
__device__ float g_mask[LQ*T];

// bf16 hi|lo split buffers (row layout: [hi(K) | lo(K)])
__device__ __align__(256) __nv_bfloat16 g_tok2 [B*T*2*D_IN];
__device__ __align__(256) __nv_bfloat16 g_x2   [B*T*2*D];
__device__ __align__(256) __nv_bfloat16 g_tmp2 [B*LQ*2*D];
__device__ __align__(256) __nv_bfloat16 g_hid2 [B*LQ*2*HID];
__device__ __align__(256) __nv_bfloat16 g_at2  [B*LQ*2*D];
__device__ __align__(256) __nv_bfloat16 g_wproj2[D*2*D_IN];
__device__ __align__(256) __nv_bfloat16 g_wxqkv2[NB*3*D*2*D];
__device__ __align__(256) __nv_bfloat16 g_wxo2  [NB*D*2*D];
__device__ __align__(256) __nv_bfloat16 g_wmx1  [NB*HID*2*D];
__device__ __align__(256) __nv_bfloat16 g_wmx2  [NB*D*2*HID];
__device__ __align__(256) __nv_bfloat16 g_wsqkv2[NB*3*D*2*D];
__device__ __align__(256) __nv_bfloat16 g_wso2  [NB*D*2*D];
__device__ __align__(256) __nv_bfloat16 g_wms1  [NB*HID*2*D];
__device__ __align__(256) __nv_bfloat16 g_wms2  [NB*D*2*HID];

__device__ __forceinline__ void split2(float x, __nv_bfloat16& h, __nv_bfloat16& l) {
    h = __float2bfloat16(x);
    l = __float2bfloat16(x - __bfloat162float(h));
}

// ---------------- reductions ----------------
__device__ __forceinline__ float block_sum256(float v, float* sh) {
    #pragma unroll
    for (int o = 16; o; o >>= 1) v += __shfl_xor_sync(0xffffffffu, v, o);
    if ((threadIdx.x & 31) == 0) sh[threadIdx.x >> 5] = v;
    __syncthreads();
    float t = (threadIdx.x < 8) ? sh[threadIdx.x] : 0.f;
    if (threadIdx.x < 32) {
        #pragma unroll
        for (int o = 4; o; o >>= 1) t += __shfl_xor_sync(0xffffffffu, t, o);
        if (threadIdx.x == 0) sh[0] = t;
    }
    __syncthreads();
    float r = sh[0];
    __syncthreads();
    return r;
}

// ================= tensor-core GEMM (HMMA): C[M,N] = A·W^T + bias =================
// A2 [M, 2K] = [hi | lo] bf16, W2 [N, 2K] likewise. 3 K-passes (hh, hl, lh).
// Block 128x128, BK=32, 4-stage cp.async pipeline, 8 warps (4 along M x 2 along N),
// warp tile 32x64 via m16n8k16 mma.sync.
// EPI: 0 = bias->fp32 C   1 = bias+gelu->split C2   2 = bias+res(inplace fp32 C)
//      3 = bias->split C2
#define BK 32
#define AST 40                               // halves per smem row (80B: conflict-free ldmatrix)
#define STG (128 * AST * 2)                  // 10240 B per matrix per stage
#define NSTAGE 4
#define GSM (NSTAGE * 2 * STG)               // 81920 B

template<int EPI>
__global__ __launch_bounds__(256)
void gemm_mma(const __nv_bfloat16* __restrict__ A2, int ldA,
              const __nv_bfloat16* __restrict__ W2, int ldW,
              const float* __restrict__ bias,
              float* __restrict__ C, __nv_bfloat16* __restrict__ C2,
              int N, int K)
{
    extern __shared__ __align__(256) char smraw[];
    const uint32_t base = smem_u32(smraw);
    const int tid = threadIdx.x;
    const int bm = blockIdx.y * 128, bn = blockIdx.x * 128;
    const int lane = tid & 31, warp = tid >> 5;
    const int wm = warp & 3, wn = warp >> 2;

    const int nkc = K / BK;
    const int nch = 3 * nkc;

    float acc[2][8][4];
    #pragma unroll
    for (int i = 0; i < 2; i++)
        #pragma unroll
        for (int j = 0; j < 8; j++)
            #pragma unroll
            for (int k = 0; k < 4; k++) acc[i][j][k] = 0.f;

    auto issue_load = [&](int i, int st) {
        int s = i / nkc, kc = i - s * nkc;
        int ao = ((s == 2) ? K : 0) + kc * BK;
        int wo = ((s == 1) ? K : 0) + kc * BK;
        uint32_t smA = base + st * (2 * STG);
        uint32_t smB = smA + STG;
        const __nv_bfloat16* As = A2 + (size_t)bm * ldA + ao;
        const __nv_bfloat16* Ws = W2 + (size_t)bn * ldW + wo;
        #pragma unroll
        for (int j = 0; j < 2; j++) {
            int u = j * 256 + tid;
            int r = u >> 2, cc = (u & 3) * 8;        // 8 halves = 16B
            cp16(smA + (uint32_t)(r * AST + cc) * 2, As + (size_t)r * ldA + cc);
            cp16(smB + (uint32_t)(r * AST + cc) * 2, Ws + (size_t)r * ldW + cc);
        }
        asm volatile("cp.async.commit_group;\n" ::: "memory");
    };

    // lane-derived ldmatrix addresses
    const int arow = wm * 32 + ((lane >> 3) & 1) * 8 + (lane & 7);
    const int akof = ((lane >> 4) & 1) * 8;
    const int brow = wn * 64 + ((lane >> 4) & 1) * 8 + (lane & 7);
    const int bkof = ((lane >> 3) & 1) * 8;

    #pragma unroll
    for (int s = 0; s < NSTAGE - 1; s++) issue_load(s, s);

    for (int i = 0; i < nch; i++) {
        int rem = nch - 1 - i;
        if (rem >= 2)      asm volatile("cp.async.wait_group 2;\n" ::: "memory");
        else if (rem == 1) asm volatile("cp.async.wait_group 1;\n" ::: "memory");
        else               asm volatile("cp.async.wait_group 0;\n" ::: "memory");
        __syncthreads();
        if (i + NSTAGE - 1 < nch) issue_load(i + NSTAGE - 1, (i + NSTAGE - 1) % NSTAGE);

        uint32_t smA = base + (i % NSTAGE) * (2 * STG);
        uint32_t smB = smA + STG;
        #pragma unroll
        for (int kk = 0; kk < 2; kk++) {
            const int k0 = kk * 16;
            uint32_t a[2][4], b[4][4];
            #pragma unroll
            for (int fm = 0; fm < 2; fm++)
                ldsm4(a[fm][0], a[fm][1], a[fm][2], a[fm][3],
                      smA + (uint32_t)((arow + fm * 16) * AST + k0 + akof) * 2);
            #pragma unroll
            for (int fb = 0; fb < 4; fb++)
                ldsm4(b[fb][0], b[fb][1], b[fb][2], b[fb][3],
                      smB + (uint32_t)((brow + fb * 16) * AST + k0 + bkof) * 2);
            #pragma unroll
            for (int fm = 0; fm < 2; fm++)
                #pragma unroll
                for (int fn = 0; fn < 8; fn++)
                    mma16816(acc[fm][fn], a[fm], b[fn >> 1][(fn & 1) * 2],
                             b[fn >> 1][(fn & 1) * 2 + 1]);
        }
    }

    // ---- epilogue ----
    const int lr = lane >> 2, lc = (lane & 3) * 2;
    #pragma unroll
    for (int fm = 0; fm < 2; fm++) {
        #pragma unroll
        for (int fn = 0; fn < 8; fn++) {
            float* cc = acc[fm][fn];
            int m0 = bm + wm * 32 + fm * 16 + lr;
            int n0 = bn + wn * 64 + fn * 8 + lc;
            float b0 = bias[n0], b1 = bias[n0 + 1];
            float v00 = cc[0] + b0, v01 = cc[1] + b1;
            float v10 = cc[2] + b0, v11 = cc[3] + b1;
            if (EPI == 1) {
                v00 = 0.5f * v00 * (1.0f + erff(v00 * 0.70710678118654752f));
                v01 = 0.5f * v01 * (1.0f + erff(v01 * 0.70710678118654752f));
                v10 = 0.5f * v10 * (1.0f + erff(v10 * 0.70710678118654752f));
                v11 = 0.5f * v11 * (1.0f + erff(v11 * 0.70710678118654752f));
            }
            if (EPI == 0) {
                *(float2*)&C[(size_t)m0 * N + n0]       = make_float2(v00, v01);
                *(float2*)&C[(size_t)(m0 + 8) * N + n0] = make_float2(v10, v11);
            } else if (EPI == 2) {
                float2 r0 = *(const float2*)&C[(size_t)m0 * N + n0];
                float2 r1 = *(const float2*)&C[(size_t)(m0 + 8) * N + n0];
                *(float2*)&C[(size_t)m0 * N + n0]       = make_float2(v00 + r0.x, v01 + r0.y);
                *(float2*)&C[(size_t)(m0 + 8) * N + n0] = make_float2(v10 + r1.x, v11 + r1.y);
            } else {   // 1, 3 -> split bf16
                __nv_bfloat16 h0, l0, h1, l1;
                split2(v00, h0, l0); split2(v01, h1, l1);
                *(__nv_bfloat162*)&C2[(size_t)m0 * 2 * N + n0]     = __nv_bfloat162(h0, h1);
                *(__nv_bfloat162*)&C2[(size_t)m0 * 2 * N + N + n0] = __nv_bfloat162(l0, l1);
                split2(v10, h0, l0); split2(v11, h1, l1);
                *(__nv_bfloat162*)&C2[(size_t)(m0 + 8) * 2 * N + n0]     = __nv_bfloat162(h0, h1);
                *(__nv_bfloat162*)&C2[(size_t)(m0 + 8) * 2 * N + N + n0] = __nv_bfloat162(l0, l1);
            }
        }
    }
}

// ---------------- elementwise split: src[rows,K] fp32 -> dst[rows,2K] bf16 ----------------
__global__ void split_pair(const float* __restrict__ src, __nv_bfloat16* __restrict__ dst, int K)
{
    int c = blockIdx.x * 256 + threadIdx.x;
    int r = blockIdx.y;
    float x = src[(size_t)r * K + c];
    __nv_bfloat16 h, l; split2(x, h, l);
    dst[(size_t)r * 2 * K + c] = h;
    dst[(size_t)r * 2 * K + K + c] = l;
}

// ---------------- LayerNorm -> split bf16 (D=512, one block/row) ----------------
__global__ void ln_split(const float* __restrict__ x, const float* __restrict__ g,
                         const float* __restrict__ b, __nv_bfloat16* __restrict__ y2)
{
    __shared__ float sh[32];
    const int row = blockIdx.x, tid = threadIdx.x;
    const float* xr = x + (size_t)row * D;
    float2 v = *(const float2*)&xr[tid * 2];
    float total = block_sum256(v.x + v.y, sh);
    float mean = total * (1.0f / D);
    float d0 = v.x - mean, d1 = v.y - mean;
    float sq = block_sum256(d0 * d0 + d1 * d1, sh);
    float inv = rsqrtf(sq * (1.0f / D) + 1e-5f);
    float2 go = *(const float2*)&g[tid * 2];
    float2 bo = *(const float2*)&b[tid * 2];
    float o0 = d0 * inv * go.x + bo.x;
    float o1 = d1 * inv * go.y + bo.y;
    __nv_bfloat16 h0, l0, h1, l1;
    split2(o0, h0, l0); split2(o1, h1, l1);
    __nv_bfloat16* dst = y2 + (size_t)row * 2 * D;
    ((__nv_bfloat162*)dst)[tid] = __nv_bfloat162(h0, h1);
    ((__nv_bfloat162*)(dst + D))[tid] = __nv_bfloat162(l0, l1);
}

// ---------------- plain LayerNorm (final) ----------------
__global__ void ln_kernel(const float* __restrict__ x, const float* __restrict__ g,
                          const float* __restrict__ b, float* __restrict__ y)
{
    __shared__ float sh[32];
    const int row = blockIdx.x, tid = threadIdx.x;
    const float* xr = x + (size_t)row * D;
    float2 v = *(const float2*)&xr[tid * 2];
    float total = block_sum256(v.x + v.y, sh);
    float mean = total * (1.0f / D);
    float d0 = v.x - mean, d1 = v.y - mean;
    float sq = block_sum256(d0 * d0 + d1 * d1, sh);
    float inv = rsqrtf(sq * (1.0f / D) + 1e-5f);
    float2 go = *(const float2*)&g[tid * 2];
    float2 bo = *(const float2*)&b[tid * 2];
    float2 o;
    o.x = d0 * inv * go.x + bo.x;
    o.y = d1 * inv * go.y + bo.y;
    *(float2*)&y[(size_t)row * D + tid * 2] = o;
}

// ---------------- precomputed relative-time mask (Lq,T) for one block ----------------
__global__ void mask_kernel(const float* __restrict__ relbias, const float* __restrict__ msp,
                            float* __restrict__ pm)
{
    int k = blockIdx.x * 256 + threadIdx.x;
    int q = blockIdx.y;
    float tau = (float)q * (4095.0f / 255.0f);
    float dt = (float)k - tau;
    float c = fminf(fmaxf(dt, -128.f), 128.f);
    int idx = (int)c + 128;
    float z = dt * (1.0f / 32.0f);
    float lg = logf(expf(-0.5f * z * z) + 1e-6f);
    pm[(size_t)q * T + k] = msp[0] * (relbias[idx] + lg);
}

// ---------------- attention scores (fp32): S = scale*QK^T (+pm) ----------------
__global__ void scores_kernel(const float* __restrict__ Q, int ldq,
                              const float* __restrict__ Km, int ldk,
                              float* __restrict__ S, int Tk,
                              const float* __restrict__ pm, float scale)
{
    __shared__ __align__(16) float Qs[HD][32];
    __shared__ __align__(16) float Ks[HD][64];
    const int bh = blockIdx.z, b = bh >> 3, h = bh & 7;
    const int q0 = blockIdx.y * 32, k0 = blockIdx.x * 64;
    const int tid = threadIdx.x;
    {
        int q = tid >> 3, d = (tid & 7) * 8;
        const float* src = Q + ((size_t)(b * LQ + q0 + q) * ldq + h * HD + d);
        float4 v0 = *(const float4*)src;
        float4 v1 = *(const float4*)(src + 4);
        Qs[d + 0][q] = v0.x; Qs[d + 1][q] = v0.y; Qs[d + 2][q] = v0.z; Qs[d + 3][q] = v0.w;
        Qs[d + 4][q] = v1.x; Qs[d + 5][q] = v1.y; Qs[d + 6][q] = v1.z; Qs[d + 7][q] = v1.w;
    }
    {
        int k = tid >> 2, d = (tid & 3) * 16;
        const float* src = Km + ((size_t)((size_t)b * Tk + k0 + k) * ldk + h * HD + d);
        #pragma unroll
        for (int u = 0; u < 4; u++) {
            float4 v = *(const float4*)(src + u * 4);
            Ks[d + u * 4 + 0][k] = v.x; Ks[d + u * 4 + 1][k] = v.y;
            Ks[d + u * 4 + 2][k] = v.z; Ks[d + u * 4 + 3][k] = v.w;
        }
    }
    __syncthreads();
    const int tx = tid & 15, ty = tid >> 4;
    float acc[2][4];
    #pragma unroll
    for (int i = 0; i < 2; i++)
        #pragma unroll
        for (int j = 0; j < 4; j++) acc[i][j] = 0.f;
    #pragma unroll
    for (int d = 0; d < HD; d++) {
        float a0 = Qs[d][ty], a1 = Qs[d][ty + 16];
        float4 bv = *(const float4*)&Ks[d][tx * 4];
        acc[0][0] += a0 * bv.x; acc[0][1] += a0 * bv.y; acc[0][2] += a0 * bv.z; acc[0][3] += a0 * bv.w;
        acc[1][0] += a1 * bv.x; acc[1][1] += a1 * bv.y; acc[1][2] += a1 * bv.z; acc[1][3] += a1 * bv.w;
    }
    #pragma unroll
    for (int qi = 0; qi < 2; qi++) {
        int q = q0 + ty + qi * 16;
        #pragma unroll
        for (int j = 0; j < 4; j++) {
            int kk = k0 + tx * 4 + j;
            float v = acc[qi][j] * scale;
            if (pm) v += pm[(size_t)q * Tk + kk];
            S[((size_t)bh * LQ + q) * (size_t)Tk + kk] = v;
        }
    }
}

// ---------------- softmax over last dim ----------------
__global__ void softmax_kernel(float* __restrict__ S, int Tk)
{
    __shared__ float sh[32];
    float* r = S + (size_t)blockIdx.x * Tk;
    const int tid = threadIdx.x;
    float m = -3.4e38f;
    for (int i = tid; i < Tk; i += 256) m = fmaxf(m, r[i]);
    #pragma unroll
    for (int o = 16; o; o >>= 1) m = fmaxf(m, __shfl_xor_sync(0xffffffffu, m, o));
    if ((tid & 31) == 0) sh[tid >> 5] = m;
    __syncthreads();
    if (tid < 32) {
        float t = (tid < 8) ? sh[tid] : -3.4e38f;
        #pragma unroll
        for (int o = 4; o; o >>= 1) t = fmaxf(t, __shfl_xor_sync(0xffffffffu, t, o));
        if (tid == 0) sh[0] = t;
    }
    __syncthreads();
    float M = sh[0];
    __syncthreads();
    float s = 0.f;
    for (int i = tid; i < Tk; i += 256) { float e = __expf(r[i] - M); r[i] = e; s += e; }
    float total = block_sum256(s, sh);
    float inv = 1.0f / total;
    for (int i = tid; i < Tk; i += 256) r[i] *= inv;
}

// ---------------- AV: out -> split bf16 at2[(b*LQ+q), h*64+d] (ld=2D) ----------------
__global__ void av_kernel(const float* __restrict__ A, int Tk,
                          const float* __restrict__ V, int ldv,
                          __nv_bfloat16* __restrict__ O2)
{
    __shared__ float Asm[32][33];
    __shared__ __align__(16) float Vs[32][HD];
    const int bh = blockIdx.y, b = bh >> 3, h = bh & 7;
    const int q0 = blockIdx.x * 32;
    const int tid = threadIdx.x;
    const int tx = tid & 15, ty = tid >> 4;
    float acc[2][4];
    #pragma unroll
    for (int i = 0; i < 2; i++)
        #pragma unroll
        for (int j = 0; j < 4; j++) acc[i][j] = 0.f;

    for (int kt = 0; kt < Tk; kt += 32) {
        {
            int q = tid >> 3, k = (tid & 7) * 4;
            float4 v = *(const float4*)&A[((size_t)bh * LQ + q0 + q) * (size_t)Tk + kt + k];
            Asm[q][k] = v.x; Asm[q][k + 1] = v.y; Asm[q][k + 2] = v.z; Asm[q][k + 3] = v.w;
        }
        {
            int k = tid >> 3, d = (tid & 7) * 8;
            const float* src = V + ((size_t)((size_t)b * Tk + kt + k) * ldv + h * HD + d);
            float4 v0 = *(const float4*)src;
            float4 v1 = *(const float4*)(src + 4);
            Vs[k][d + 0] = v0.x; Vs[k][d + 1] = v0.y; Vs[k][d + 2] = v0.z; Vs[k][d + 3] = v0.w;
            Vs[k][d + 4] = v1.x; Vs[k][d + 5] = v1.y; Vs[k][d + 6] = v1.z; Vs[k][d + 7] = v1.w;
        }
        __syncthreads();
        #pragma unroll
        for (int k = 0; k < 32; k++) {
            float a0 = Asm[ty][k], a1 = Asm[ty + 16][k];
            float4 bv = *(const float4*)&Vs[k][tx * 4];
            acc[0][0] += a0 * bv.x; acc[0][1] += a0 * bv.y; acc[0][2] += a0 * bv.z; acc[0][3] += a0 * bv.w;
            acc[1][0] += a1 * bv.x; acc[1][1] += a1 * bv.y; acc[1][2] += a1 * bv.z; acc[1][3] += a1 * bv.w;
        }
        __syncthreads();
    }
    #pragma unroll
    for (int qi = 0; qi < 2; qi++) {
        int q = q0 + ty + qi * 16;
        __nv_bfloat16* dh = O2 + ((size_t)(b * LQ + q) * 2 * D + h * HD + tx * 4);
        __nv_bfloat16* dl = dh + D;
        #pragma unroll
        for (int j = 0; j < 4; j++) {
            __nv_bfloat16 h16, l16;
            split2(acc[qi][j], h16, l16);
            dh[j] = h16; dl[j] = l16;
        }
    }
}

// ---------------- misc ----------------
__global__ void bcast_latents(const float* __restrict__ src, float* __restrict__ dst)
{
    int i = blockIdx.x * 256 + threadIdx.x;
    dst[i] = src[i % (LQ * D)];
}

__global__ void mean_kernel(const float* __restrict__ x, float* __restrict__ out)
{
    int i = blockIdx.x * 256 + threadIdx.x;   // B*D total
    int b = i / D, d = i % D;
    float s = 0.f;
    for (int q = 0; q < LQ; q++) s += x[((size_t)b * LQ + q) * D + d];
    out[i] = s * (1.0f / LQ);
}

// ---------------- host orchestration ----------------
extern "C" void kernel_launch(void* const* d_in, const int* in_sizes, int n_in,
                              void* d_out, int out_size)
{
    (void)in_sizes; (void)n_in; (void)out_size;
    const float* tokens     = (const float*)d_in[0];
    const float* proj_w     = (const float*)d_in[1];
    const float* proj_b     = (const float*)d_in[2];
    const float* latents    = (const float*)d_in[3];
    const float* lnx_g      = (const float*)d_in[4];
    const float* lnx_b      = (const float*)d_in[5];
    const float* xw_qkv     = (const float*)d_in[6];
    const float* xb_qkv     = (const float*)d_in[7];
    const float* xw_o       = (const float*)d_in[8];
    const float* xb_o       = (const float*)d_in[9];
    const float* rel_bias   = (const float*)d_in[10];
    const float* mask_scale = (const float*)d_in[11];
    const float* mx_w1      = (const float*)d_in[12];
    const float* mx_b1      = (const float*)d_in[13];
    const float* mx_w2      = (const float*)d_in[14];
    const float* mx_b2      = (const float*)d_in[15];
    const float* lns_g      = (const float*)d_in[16];
    const float* lns_b      = (const float*)d_in[17];
    const float* sw_qkv     = (const float*)d_in[18];
    const float* sb_qkv     = (const float*)d_in[19];
    const float* sw_o       = (const float*)d_in[20];
    const float* sb_o       = (const float*)d_in[21];
    const float* ms_w1      = (const float*)d_in[22];
    const float* ms_b1      = (const float*)d_in[23];
    const float* ms_w2      = (const float*)d_in[24];
    const float* ms_b2      = (const float*)d_in[25];
    const float* lno_g      = (const float*)d_in[26];
    const float* lno_b      = (const float*)d_in[27];
    float* out = (float*)d_out;

    cudaFuncSetAttribute(gemm_mma<0>, cudaFuncAttributeMaxDynamicSharedMemorySize, GSM);
    cudaFuncSetAttribute(gemm_mma<1>, cudaFuncAttributeMaxDynamicSharedMemorySize, GSM);
    cudaFuncSetAttribute(gemm_mma<2>, cudaFuncAttributeMaxDynamicSharedMemorySize, GSM);
    cudaFuncSetAttribute(gemm_mma<3>, cudaFuncAttributeMaxDynamicSharedMemorySize, GSM);

    float *pkv, *plat, *ptmpf, *pq, *psq, *pS, *pmask;
    __nv_bfloat16 *ptok2, *px2, *ptmp2, *phid2, *pat2, *pwproj, *pwxqkv, *pwxo,
                  *pwmx1, *pwmx2, *pwsqkv, *pwso, *pwms1, *pwms2;
    cudaGetSymbolAddress((void**)&pkv,   g_kv);
    cudaGetSymbolAddress((void**)&plat,  g_lat);
    cudaGetSymbolAddress((void**)&ptmpf, g_tmpf);
    cudaGetSymbolAddress((void**)&pq,    g_q);
    cudaGetSymbolAddress((void**)&psq,   g_sqkv);
    cudaGetSymbolAddress((void**)&pS,    g_S);
    cudaGetSymbolAddress((void**)&pmask, g_mask);
    cudaGetSymbolAddress((void**)&ptok2, g_tok2);
    cudaGetSymbolAddress((void**)&px2,   g_x2);
    cudaGetSymbolAddress((void**)&ptmp2, g_tmp2);
    cudaGetSymbolAddress((void**)&phid2, g_hid2);
    cudaGetSymbolAddress((void**)&pat2,  g_at2);
    cudaGetSymbolAddress((void**)&pwproj, g_wproj2);
    cudaGetSymbolAddress((void**)&pwxqkv, g_wxqkv2);
    cudaGetSymbolAddress((void**)&pwxo,   g_wxo2);
    cudaGetSymbolAddress((void**)&pwmx1,  g_wmx1);
    cudaGetSymbolAddress((void**)&pwmx2,  g_wmx2);
    cudaGetSymbolAddress((void**)&pwsqkv, g_wsqkv2);
    cudaGetSymbolAddress((void**)&pwso,   g_wso2);
    cudaGetSymbolAddress((void**)&pwms1,  g_wms1);
    cudaGetSymbolAddress((void**)&pwms2,  g_wms2);

    const float scale = 0.125f;  // 1/sqrt(64)
    const int BT = B * T, BL = B * LQ;

    // ---- weight + token splits ----
    split_pair<<<dim3(D_IN / 256, D),         256>>>(proj_w, pwproj, D_IN);
    split_pair<<<dim3(D / 256,   NB * 3 * D), 256>>>(xw_qkv, pwxqkv, D);
    split_pair<<<dim3(D / 256,   NB * D),     256>>>(xw_o,   pwxo,   D);
    split_pair<<<dim3(D / 256,   NB * HID),   256>>>(mx_w1,  pwmx1,  D);
    split_pair<<<dim3(HID / 256, NB * D),     256>>>(mx_w2,  pwmx2,  HID);
    split_pair<<<dim3(D / 256,   NB * 3 * D), 256>>>(sw_qkv, pwsqkv, D);
    split_pair<<<dim3(D / 256,   NB * D),     256>>>(sw_o,   pwso,   D);
    split_pair<<<dim3(D / 256,   NB * HID),   256>>>(ms_w1,  pwms1,  D);
    split_pair<<<dim3(HID / 256, NB * D),     256>>>(ms_w2,  pwms2,  HID);
    split_pair<<<dim3(D_IN / 256, BT),        256>>>(tokens, ptok2,  D_IN);

    // x = tokens @ proj_w.T + proj_b -> split into x2
    gemm_mma<3><<<dim3(D / 128, BT / 128), 256, GSM>>>(
        ptok2, 2 * D_IN, pwproj, 2 * D_IN, proj_b, nullptr, px2, D, D_IN);
    bcast_latents<<<(BL * D) / 256, 256>>>(latents, plat);

    for (int i = 0; i < NB; i++) {
        const __nv_bfloat16* wq2 = pwxqkv + (size_t)i * 3 * D * 2 * D;
        const float* bqkv = xb_qkv + (size_t)i * 3 * D;

        // ---- cross attention ----
        mask_kernel<<<dim3(T / 256, LQ), 256>>>(rel_bias + i * (2 * 128 + 1), mask_scale + i, pmask);
        ln_split<<<BL, 256>>>(plat, lnx_g + i * D, lnx_b + i * D, ptmp2);
        gemm_mma<0><<<dim3(D / 128, BL / 128), 256, GSM>>>(
            ptmp2, 2 * D, wq2, 2 * D, bqkv, pq, nullptr, D, D);
        gemm_mma<0><<<dim3((2 * D) / 128, BT / 128), 256, GSM>>>(
            px2, 2 * D, wq2 + (size_t)D * 2 * D, 2 * D, bqkv + D, pkv, nullptr, 2 * D, D);
        scores_kernel<<<dim3(T / 64, LQ / 32, B * H), 256>>>(pq, D, pkv, 2 * D, pS, T, pmask, scale);
        softmax_kernel<<<B * H * LQ, 256>>>(pS, T);
        av_kernel<<<dim3(LQ / 32, B * H), 256>>>(pS, T, pkv + D, 2 * D, pat2);
        gemm_mma<2><<<dim3(D / 128, BL / 128), 256, GSM>>>(
            pat2, 2 * D, pwxo + (size_t)i * D * 2 * D, 2 * D, xb_o + i * D, plat, nullptr, D, D);

        // ---- cross MLP (pre-LN reuses lnx params) ----
        ln_split<<<BL, 256>>>(plat, lnx_g + i * D, lnx_b + i * D, ptmp2);
        gemm_mma<1><<<dim3(HID / 128, BL / 128), 256, GSM>>>(
            ptmp2, 2 * D, pwmx1 + (size_t)i * HID * 2 * D, 2 * D, mx_b1 + i * HID,
            nullptr, phid2, HID, D);
        gemm_mma<2><<<dim3(D / 128, BL / 128), 256, GSM>>>(
            phid2, 2 * HID, pwmx2 + (size_t)i * D * 2 * HID, 2 * HID, mx_b2 + i * D,
            plat, nullptr, D, HID);

        // ---- self attention ----
        ln_split<<<BL, 256>>>(plat, lns_g + i * D, lns_b + i * D, ptmp2);
        gemm_mma<0><<<dim3((3 * D) / 128, BL / 128), 256, GSM>>>(
            ptmp2, 2 * D, pwsqkv + (size_t)i * 3 * D * 2 * D, 2 * D,
            sb_qkv + (size_t)i * 3 * D, psq, nullptr, 3 * D, D);
        scores_kernel<<<dim3(LQ / 64, LQ / 32, B * H), 256>>>(psq, 3 * D, psq + D, 3 * D, pS, LQ,
                                                              nullptr, scale);
        softmax_kernel<<<B * H * LQ, 256>>>(pS, LQ);
        av_kernel<<<dim3(LQ / 32, B * H), 256>>>(pS, LQ, psq + 2 * D, 3 * D, pat2);
        gemm_mma<2><<<dim3(D / 128, BL / 128), 256, GSM>>>(
            pat2, 2 * D, pwso + (size_t)i * D * 2 * D, 2 * D, sb_o + i * D, plat, nullptr, D, D);

        // ---- self MLP ----
        ln_split<<<BL, 256>>>(plat, lns_g + i * D, lns_b + i * D, ptmp2);
        gemm_mma<1><<<dim3(HID / 128, BL / 128), 256, GSM>>>(
            ptmp2, 2 * D, pwms1 + (size_t)i * HID * 2 * D, 2 * D, ms_b1 + i * HID,
            nullptr, phid2, HID, D);
        gemm_mma<2><<<dim3(D / 128, BL / 128), 256, GSM>>>(
            phid2, 2 * HID, pwms2 + (size_t)i * D * 2 * HID, 2 * HID, ms_b2 + i * D,
            plat, nullptr, D, HID);
    }

    // final LN + mean over latents
    ln_kernel<<<BL, 256>>>(plat, lno_g, lno_b, ptmpf);
    mean_kernel<<<(B * D) / 256, 256>>>(ptmpf, out);
}

// round 5
// speedup vs baseline: 2.7889x; 1.8964x over previous
#include <cuda_runtime.h>
#include <cuda_bf16.h>
#include <cstdint>
#include <math.h>

// ---------------- problem constants ----------------
#define B   8
#define T   4096
#define D_IN 256
#define D   512
#define LQ  256
#define H   8
#define HD  64
#define NB  6
#define HID 2048

// ---------------- mma.sync helpers (sm_80+ PTX; no tcgen05) ----------------
__device__ __forceinline__ uint32_t smem_u32(const void* p) {
    uint32_t a;
    asm("{ .reg .u64 t; cvta.to.shared.u64 t, %1; cvt.u32.u64 %0, t; }" : "=r"(a) : "l"(p));
    return a;
}
__device__ __forceinline__ void cp16(uint32_t dst, const void* src) {
    asm volatile("cp.async.cg.shared.global [%0], [%1], 16;\n" :: "r"(dst), "l"(src));
}
__device__ __forceinline__ void ldsm4(uint32_t& r0, uint32_t& r1, uint32_t& r2, uint32_t& r3,
                                      uint32_t addr) {
    asm volatile("ldmatrix.sync.aligned.m8n8.x4.shared.b16 {%0,%1,%2,%3}, [%4];"
        : "=r"(r0), "=r"(r1), "=r"(r2), "=r"(r3) : "r"(addr));
}
__device__ __forceinline__ void ldsm4t(uint32_t& r0, uint32_t& r1, uint32_t& r2, uint32_t& r3,
                                       uint32_t addr) {
    asm volatile("ldmatrix.sync.aligned.m8n8.x4.trans.shared.b16 {%0,%1,%2,%3}, [%4];"
        : "=r"(r0), "=r"(r1), "=r"(r2), "=r"(r3) : "r"(addr));
}
__device__ __forceinline__ void mma16816(float* c, const uint32_t* a, uint32_t b0, uint32_t b1) {
    asm volatile("mma.sync.aligned.m16n8k16.row.col.f32.bf16.bf16.f32 "
        "{%0,%1,%2,%3}, {%4,%5,%6,%7}, {%8,%9}, {%0,%1,%2,%3};"
        : "+f"(c[0]), "+f"(c[1]), "+f"(c[2]), "+f"(c[3])
        : "r"(a[0]), "r"(a[1]), "r"(a[2]), "r"(a[3]), "r"(b0), "r"(b1));
}
__device__ __forceinline__ float ex2(float x) {
    float r; asm("ex2.approx.f32 %0, %1;" : "=f"(r) : "f"(x)); return r;
}

// ---------------- scratch (static device globals; no allocation) ----------------
__device__ float g_lat [B*LQ*D];
__device__ float g_tmpf[B*LQ*D];
__device__ float g_mask[LQ*T];

// bf16 hi|lo split buffers (row layout: [hi(K) | lo(K)])
__device__ __align__(256) __nv_bfloat16 g_tok2 [B*T*2*D_IN];
__device__ __align__(256) __nv_bfloat16 g_x2   [B*T*2*D];
__device__ __align__(256) __nv_bfloat16 g_tmp2 [B*LQ*2*D];
__device__ __align__(256) __nv_bfloat16 g_hid2 [B*LQ*2*HID];
__device__ __align__(256) __nv_bfloat16 g_at2  [B*LQ*2*D];
__device__ __align__(256) __nv_bfloat16 g_q2   [B*LQ*2*D];
__device__ __align__(256) __nv_bfloat16 g_kv2  [B*T*2*(2*D)];
__device__ __align__(256) __nv_bfloat16 g_sq2  [B*LQ*2*(3*D)];
__device__ __align__(256) __nv_bfloat16 g_wproj2[D*2*D_IN];
__device__ __align__(256) __nv_bfloat16 g_wxqkv2[NB*3*D*2*D];
__device__ __align__(256) __nv_bfloat16 g_wxo2  [NB*D*2*D];
__device__ __align__(256) __nv_bfloat16 g_wmx1  [NB*HID*2*D];
__device__ __align__(256) __nv_bfloat16 g_wmx2  [NB*D*2*HID];
__device__ __align__(256) __nv_bfloat16 g_wsqkv2[NB*3*D*2*D];
__device__ __align__(256) __nv_bfloat16 g_wso2  [NB*D*2*D];
__device__ __align__(256) __nv_bfloat16 g_wms1  [NB*HID*2*D];
__device__ __align__(256) __nv_bfloat16 g_wms2  [NB*D*2*HID];

__device__ __forceinline__ void split2(float x, __nv_bfloat16& h, __nv_bfloat16& l) {
    h = __float2bfloat16(x);
    l = __float2bfloat16(x - __bfloat162float(h));
}
__device__ __forceinline__ uint32_t pk2(__nv_bfloat16 a, __nv_bfloat16 b) {
    __nv_bfloat162 t(a, b);
    return *(uint32_t*)&t;
}

// ---------------- reductions ----------------
__device__ __forceinline__ float block_sum256(float v, float* sh) {
    #pragma unroll
    for (int o = 16; o; o >>= 1) v += __shfl_xor_sync(0xffffffffu, v, o);
    if ((threadIdx.x & 31) == 0) sh[threadIdx.x >> 5] = v;
    __syncthreads();
    float t = (threadIdx.x < 8) ? sh[threadIdx.x] : 0.f;
    if (threadIdx.x < 32) {
        #pragma unroll
        for (int o = 4; o; o >>= 1) t += __shfl_xor_sync(0xffffffffu, t, o);
        if (threadIdx.x == 0) sh[0] = t;
    }
    __syncthreads();
    float r = sh[0];
    __syncthreads();
    return r;
}

// ================= tensor-core GEMM (HMMA): C[M,N] = A·W^T + bias =================
// A2 [M, 2K] = [hi | lo] bf16, W2 [N, 2K] likewise. 3 K-passes (hh, hl, lh).
// EPI: 1 = bias+gelu->split C2   2 = bias+res(inplace fp32 C)   3 = bias->split C2
#define BK 32
#define AST 40
#define STG (128 * AST * 2)
#define NSTAGE 4
#define GSM (NSTAGE * 2 * STG)

template<int EPI>
__global__ __launch_bounds__(256)
void gemm_mma(const __nv_bfloat16* __restrict__ A2, int ldA,
              const __nv_bfloat16* __restrict__ W2, int ldW,
              const float* __restrict__ bias,
              float* __restrict__ C, __nv_bfloat16* __restrict__ C2,
              int N, int K)
{
    extern __shared__ __align__(256) char smraw[];
    const uint32_t base = smem_u32(smraw);
    const int tid = threadIdx.x;
    const int bm = blockIdx.y * 128, bn = blockIdx.x * 128;
    const int lane = tid & 31, warp = tid >> 5;
    const int wm = warp & 3, wn = warp >> 2;

    const int nkc = K / BK;
    const int nch = 3 * nkc;

    float acc[2][8][4];
    #pragma unroll
    for (int i = 0; i < 2; i++)
        #pragma unroll
        for (int j = 0; j < 8; j++)
            #pragma unroll
            for (int k = 0; k < 4; k++) acc[i][j][k] = 0.f;

    auto issue_load = [&](int i, int st) {
        int s = i / nkc, kc = i - s * nkc;
        int ao = ((s == 2) ? K : 0) + kc * BK;
        int wo = ((s == 1) ? K : 0) + kc * BK;
        uint32_t smA = base + st * (2 * STG);
        uint32_t smB = smA + STG;
        const __nv_bfloat16* As = A2 + (size_t)bm * ldA + ao;
        const __nv_bfloat16* Ws = W2 + (size_t)bn * ldW + wo;
        #pragma unroll
        for (int j = 0; j < 2; j++) {
            int u = j * 256 + tid;
            int r = u >> 2, cc = (u & 3) * 8;
            cp16(smA + (uint32_t)(r * AST + cc) * 2, As + (size_t)r * ldA + cc);
            cp16(smB + (uint32_t)(r * AST + cc) * 2, Ws + (size_t)r * ldW + cc);
        }
        asm volatile("cp.async.commit_group;\n" ::: "memory");
    };

    const int arow = wm * 32 + ((lane >> 3) & 1) * 8 + (lane & 7);
    const int akof = ((lane >> 4) & 1) * 8;
    const int brow = wn * 64 + ((lane >> 4) & 1) * 8 + (lane & 7);
    const int bkof = ((lane >> 3) & 1) * 8;

    #pragma unroll
    for (int s = 0; s < NSTAGE - 1; s++) issue_load(s, s);

    for (int i = 0; i < nch; i++) {
        int rem = nch - 1 - i;
        if (rem >= 2)      asm volatile("cp.async.wait_group 2;\n" ::: "memory");
        else if (rem == 1) asm volatile("cp.async.wait_group 1;\n" ::: "memory");
        else               asm volatile("cp.async.wait_group 0;\n" ::: "memory");
        __syncthreads();
        if (i + NSTAGE - 1 < nch) issue_load(i + NSTAGE - 1, (i + NSTAGE - 1) % NSTAGE);

        uint32_t smA = base + (i % NSTAGE) * (2 * STG);
        uint32_t smB = smA + STG;
        #pragma unroll
        for (int kk = 0; kk < 2; kk++) {
            const int k0 = kk * 16;
            uint32_t a[2][4], b[4][4];
            #pragma unroll
            for (int fm = 0; fm < 2; fm++)
                ldsm4(a[fm][0], a[fm][1], a[fm][2], a[fm][3],
                      smA + (uint32_t)((arow + fm * 16) * AST + k0 + akof) * 2);
            #pragma unroll
            for (int fb = 0; fb < 4; fb++)
                ldsm4(b[fb][0], b[fb][1], b[fb][2], b[fb][3],
                      smB + (uint32_t)((brow + fb * 16) * AST + k0 + bkof) * 2);
            #pragma unroll
            for (int fm = 0; fm < 2; fm++)
                #pragma unroll
                for (int fn = 0; fn < 8; fn++)
                    mma16816(acc[fm][fn], a[fm], b[fn >> 1][(fn & 1) * 2],
                             b[fn >> 1][(fn & 1) * 2 + 1]);
        }
    }

    const int lr = lane >> 2, lc = (lane & 3) * 2;
    #pragma unroll
    for (int fm = 0; fm < 2; fm++) {
        #pragma unroll
        for (int fn = 0; fn < 8; fn++) {
            float* cc = acc[fm][fn];
            int m0 = bm + wm * 32 + fm * 16 + lr;
            int n0 = bn + wn * 64 + fn * 8 + lc;
            float b0 = bias[n0], b1 = bias[n0 + 1];
            float v00 = cc[0] + b0, v01 = cc[1] + b1;
            float v10 = cc[2] + b0, v11 = cc[3] + b1;
            if (EPI == 1) {
                v00 = 0.5f * v00 * (1.0f + erff(v00 * 0.70710678118654752f));
                v01 = 0.5f * v01 * (1.0f + erff(v01 * 0.70710678118654752f));
                v10 = 0.5f * v10 * (1.0f + erff(v10 * 0.70710678118654752f));
                v11 = 0.5f * v11 * (1.0f + erff(v11 * 0.70710678118654752f));
            }
            if (EPI == 2) {
                float2 r0 = *(const float2*)&C[(size_t)m0 * N + n0];
                float2 r1 = *(const float2*)&C[(size_t)(m0 + 8) * N + n0];
                *(float2*)&C[(size_t)m0 * N + n0]       = make_float2(v00 + r0.x, v01 + r0.y);
                *(float2*)&C[(size_t)(m0 + 8) * N + n0] = make_float2(v10 + r1.x, v11 + r1.y);
            } else {
                __nv_bfloat16 h0, l0, h1, l1;
                split2(v00, h0, l0); split2(v01, h1, l1);
                *(__nv_bfloat162*)&C2[(size_t)m0 * 2 * N + n0]     = __nv_bfloat162(h0, h1);
                *(__nv_bfloat162*)&C2[(size_t)m0 * 2 * N + N + n0] = __nv_bfloat162(l0, l1);
                split2(v10, h0, l0); split2(v11, h1, l1);
                *(__nv_bfloat162*)&C2[(size_t)(m0 + 8) * 2 * N + n0]     = __nv_bfloat162(h0, h1);
                *(__nv_bfloat162*)&C2[(size_t)(m0 + 8) * 2 * N + N + n0] = __nv_bfloat162(l0, l1);
            }
        }
    }
}

// ================= fused flash attention (HMMA, split bf16, no running max) =========
// Per block: 64 q rows (4 warps x 16), chunks of 64 keys, double-buffered cp.async.
// Logits are computed in base-2: t = qk*(0.125*log2e) + pm*log2e ; p = 2^t.
#define BQ 64
#define BKC 64
#define QST 72                       // halves per smem row (144B: conflict-free ldmatrix)
#define FTILE (64 * QST * 2)         // 9216 B
#define FA_SMEM (2 * FTILE + 2 * 4 * FTILE)   // Q(2) + 2 stages * (Kh,Kl,Vh,Vl) = 92160

__global__ __launch_bounds__(128)
void fattn(const __nv_bfloat16* __restrict__ Qp, int ldq, int oq,
           const __nv_bfloat16* __restrict__ Kp, int ldk, int ok,
           const __nv_bfloat16* __restrict__ Vp, int ldv, int ov,
           const float* __restrict__ pm, __nv_bfloat16* __restrict__ O2, int Tk)
{
    extern __shared__ __align__(256) char smraw[];
    const uint32_t base = smem_u32(smraw);
    const int tid = threadIdx.x, lane = tid & 31, warp = tid >> 5;
    const int bh = (int)blockIdx.y, b = bh >> 3, h = bh & 7;
    const int q0 = (int)blockIdx.x * BQ;

    const __nv_bfloat16* Qb = Qp + (size_t)(b * LQ + q0) * ldq + h * HD;
    const __nv_bfloat16* Kb = Kp + (size_t)b * Tk * ldk + h * HD;
    const __nv_bfloat16* Vb = Vp + (size_t)b * Tk * ldv + h * HD;

    // Q tiles (hi, lo) -> smem
    #pragma unroll
    for (int j = 0; j < 4; j++) {
        int u = j * 128 + tid, r = u >> 3, c8 = (u & 7) * 8;
        uint32_t off = (uint32_t)(r * QST + c8) * 2;
        cp16(base + off,         Qb + (size_t)r * ldq + c8);
        cp16(base + FTILE + off, Qb + (size_t)r * ldq + oq + c8);
    }
    asm volatile("cp.async.commit_group;\n" ::: "memory");

    const int nc = Tk / BKC;
    auto load_chunk = [&](int ci, int st) {
        uint32_t sb = base + 2 * FTILE + st * 4 * FTILE;
        const __nv_bfloat16* Kc = Kb + (size_t)ci * BKC * ldk;
        const __nv_bfloat16* Vc = Vb + (size_t)ci * BKC * ldv;
        #pragma unroll
        for (int j = 0; j < 4; j++) {
            int u = j * 128 + tid, r = u >> 3, c8 = (u & 7) * 8;
            uint32_t off = (uint32_t)(r * QST + c8) * 2;
            cp16(sb + off,             Kc + (size_t)r * ldk + c8);
            cp16(sb + FTILE + off,     Kc + (size_t)r * ldk + ok + c8);
            cp16(sb + 2 * FTILE + off, Vc + (size_t)r * ldv + c8);
            cp16(sb + 3 * FTILE + off, Vc + (size_t)r * ldv + ov + c8);
        }
        asm volatile("cp.async.commit_group;\n" ::: "memory");
    };

    load_chunk(0, 0);
    asm volatile("cp.async.wait_group 1;\n" ::: "memory");   // Q ready
    __syncthreads();

    // Q fragments (persist in registers)
    const int qrow = warp * 16 + ((lane >> 3) & 1) * 8 + (lane & 7);
    const int qko  = ((lane >> 4) & 1) * 8;
    uint32_t qf[2][4][4];
    #pragma unroll
    for (int p = 0; p < 2; p++)
        #pragma unroll
        for (int ds = 0; ds < 4; ds++)
            ldsm4(qf[p][ds][0], qf[p][ds][1], qf[p][ds][2], qf[p][ds][3],
                  base + p * FTILE + (uint32_t)(qrow * QST + ds * 16 + qko) * 2);

    load_chunk(1, 1);

    float o[8][4];
    #pragma unroll
    for (int i = 0; i < 8; i++)
        #pragma unroll
        for (int j = 0; j < 4; j++) o[i][j] = 0.f;
    float lsum0 = 0.f, lsum1 = 0.f;

    const float SC  = 0.125f * 1.44269504088896f;
    const float L2E = 1.44269504088896f;
    const int lr = lane >> 2, lc = (lane & 3) * 2;
    const int krow = ((lane >> 4) & 1) * 8 + (lane & 7);
    const int kko  = ((lane >> 3) & 1) * 8;
    const int vrow = lane & 15;
    const int vco  = ((lane >> 4) & 1) * 8;
    const int qr_g = q0 + warp * 16 + lr;

    for (int ci = 0; ci < nc; ci++) {
        if (ci == nc - 1) asm volatile("cp.async.wait_group 0;\n" ::: "memory");
        else              asm volatile("cp.async.wait_group 1;\n" ::: "memory");
        __syncthreads();

        uint32_t sb = base + 2 * FTILE + (ci & 1) * 4 * FTILE;

        // ---- S = Q·K^T (3 split passes) ----
        float s[8][4];
        #pragma unroll
        for (int i = 0; i < 8; i++)
            #pragma unroll
            for (int j = 0; j < 4; j++) s[i][j] = 0.f;
        #pragma unroll
        for (int ps = 0; ps < 3; ps++) {
            const int qp = (ps == 2) ? 1 : 0;
            const uint32_t kb = sb + ((ps == 1) ? FTILE : 0);
            #pragma unroll
            for (int ds = 0; ds < 4; ds++) {
                #pragma unroll
                for (int g = 0; g < 4; g++) {
                    uint32_t b0, b1, b2, b3;
                    ldsm4(b0, b1, b2, b3,
                          kb + (uint32_t)((g * 16 + krow) * QST + ds * 16 + kko) * 2);
                    mma16816(s[2 * g],     qf[qp][ds], b0, b1);
                    mma16816(s[2 * g + 1], qf[qp][ds], b2, b3);
                }
            }
        }

        // ---- softmax numerators + P fragments (hi/lo) ----
        uint32_t ph[4][4], pl[4][4];
        #pragma unroll
        for (int nt = 0; nt < 8; nt++) {
            float t0 = s[nt][0] * SC, t1 = s[nt][1] * SC;
            float t2 = s[nt][2] * SC, t3 = s[nt][3] * SC;
            if (pm) {
                const float* pmr = pm + (size_t)qr_g * Tk + ci * BKC + nt * 8 + lc;
                float2 m0 = *(const float2*)pmr;
                float2 m1 = *(const float2*)(pmr + (size_t)8 * Tk);
                t0 = fmaf(m0.x, L2E, t0); t1 = fmaf(m0.y, L2E, t1);
                t2 = fmaf(m1.x, L2E, t2); t3 = fmaf(m1.y, L2E, t3);
            }
            float p0 = ex2(t0), p1 = ex2(t1), p2 = ex2(t2), p3 = ex2(t3);
            lsum0 += p0 + p1;
            lsum1 += p2 + p3;
            __nv_bfloat16 h0, l0, h1, l1, h2, l2, h3, l3;
            split2(p0, h0, l0); split2(p1, h1, l1);
            split2(p2, h2, l2); split2(p3, h3, l3);
            int j = nt >> 1, qi = (nt & 1) * 2;
            ph[j][qi]     = pk2(h0, h1);
            ph[j][qi + 1] = pk2(h2, h3);
            pl[j][qi]     = pk2(l0, l1);
            pl[j][qi + 1] = pk2(l2, l3);
        }

        // ---- O += P·V (3 split passes) ----
        #pragma unroll
        for (int ps = 0; ps < 3; ps++) {
            const uint32_t vbb = sb + 2 * FTILE + ((ps == 2) ? FTILE : 0);
            #pragma unroll
            for (int ks = 0; ks < 4; ks++) {
                const uint32_t* pf = (ps == 1) ? pl[ks] : ph[ks];
                #pragma unroll
                for (int g = 0; g < 4; g++) {
                    uint32_t b0, b1, b2, b3;
                    ldsm4t(b0, b1, b2, b3,
                           vbb + (uint32_t)((ks * 16 + vrow) * QST + g * 16 + vco) * 2);
                    mma16816(o[2 * g],     pf, b0, b1);
                    mma16816(o[2 * g + 1], pf, b2, b3);
                }
            }
        }

        __syncthreads();
        if (ci + 2 < nc) load_chunk(ci + 2, ci & 1);
    }

    // ---- finalize: row sums across quad, normalize, split-write ----
    lsum0 += __shfl_xor_sync(0xffffffffu, lsum0, 1);
    lsum0 += __shfl_xor_sync(0xffffffffu, lsum0, 2);
    lsum1 += __shfl_xor_sync(0xffffffffu, lsum1, 1);
    lsum1 += __shfl_xor_sync(0xffffffffu, lsum1, 2);
    float inv0 = 1.0f / lsum0, inv1 = 1.0f / lsum1;

    const size_t row0 = (size_t)(b * LQ + qr_g);
    #pragma unroll
    for (int nt = 0; nt < 8; nt++) {
        int col = h * HD + nt * 8 + lc;
        float v0 = o[nt][0] * inv0, v1 = o[nt][1] * inv0;
        float v2 = o[nt][2] * inv1, v3 = o[nt][3] * inv1;
        __nv_bfloat16 h0, l0, h1, l1;
        split2(v0, h0, l0); split2(v1, h1, l1);
        *(__nv_bfloat162*)&O2[row0 * 2 * D + col]     = __nv_bfloat162(h0, h1);
        *(__nv_bfloat162*)&O2[row0 * 2 * D + D + col] = __nv_bfloat162(l0, l1);
        split2(v2, h0, l0); split2(v3, h1, l1);
        *(__nv_bfloat162*)&O2[(row0 + 8) * 2 * D + col]     = __nv_bfloat162(h0, h1);
        *(__nv_bfloat162*)&O2[(row0 + 8) * 2 * D + D + col] = __nv_bfloat162(l0, l1);
    }
}

// ---------------- elementwise split: src[rows,K] fp32 -> dst[rows,2K] bf16 ----------------
__global__ void split_pair(const float* __restrict__ src, __nv_bfloat16* __restrict__ dst, int K)
{
    int c = blockIdx.x * 256 + threadIdx.x;
    int r = blockIdx.y;
    float x = src[(size_t)r * K + c];
    __nv_bfloat16 h, l; split2(x, h, l);
    dst[(size_t)r * 2 * K + c] = h;
    dst[(size_t)r * 2 * K + K + c] = l;
}

// ---------------- LayerNorm -> split bf16 (D=512, one block/row) ----------------
__global__ void ln_split(const float* __restrict__ x, const float* __restrict__ g,
                         const float* __restrict__ b, __nv_bfloat16* __restrict__ y2)
{
    __shared__ float sh[32];
    const int row = blockIdx.x, tid = threadIdx.x;
    const float* xr = x + (size_t)row * D;
    float2 v = *(const float2*)&xr[tid * 2];
    float total = block_sum256(v.x + v.y, sh);
    float mean = total * (1.0f / D);
    float d0 = v.x - mean, d1 = v.y - mean;
    float sq = block_sum256(d0 * d0 + d1 * d1, sh);
    float inv = rsqrtf(sq * (1.0f / D) + 1e-5f);
    float2 go = *(const float2*)&g[tid * 2];
    float2 bo = *(const float2*)&b[tid * 2];
    float o0 = d0 * inv * go.x + bo.x;
    float o1 = d1 * inv * go.y + bo.y;
    __nv_bfloat16 h0, l0, h1, l1;
    split2(o0, h0, l0); split2(o1, h1, l1);
    __nv_bfloat16* dst = y2 + (size_t)row * 2 * D;
    ((__nv_bfloat162*)dst)[tid] = __nv_bfloat162(h0, h1);
    ((__nv_bfloat162*)(dst + D))[tid] = __nv_bfloat162(l0, l1);
}

// ---------------- plain LayerNorm (final) ----------------
__global__ void ln_kernel(const float* __restrict__ x, const float* __restrict__ g,
                          const float* __restrict__ b, float* __restrict__ y)
{
    __shared__ float sh[32];
    const int row = blockIdx.x, tid = threadIdx.x;
    const float* xr = x + (size_t)row * D;
    float2 v = *(const float2*)&xr[tid * 2];
    float total = block_sum256(v.x + v.y, sh);
    float mean = total * (1.0f / D);
    float d0 = v.x - mean, d1 = v.y - mean;
    float sq = block_sum256(d0 * d0 + d1 * d1, sh);
    float inv = rsqrtf(sq * (1.0f / D) + 1e-5f);
    float2 go = *(const float2*)&g[tid * 2];
    float2 bo = *(const float2*)&b[tid * 2];
    float2 o;
    o.x = d0 * inv * go.x + bo.x;
    o.y = d1 * inv * go.y + bo.y;
    *(float2*)&y[(size_t)row * D + tid * 2] = o;
}

// ---------------- precomputed relative-time mask (Lq,T) for one block ----------------
__global__ void mask_kernel(const float* __restrict__ relbias, const float* __restrict__ msp,
                            float* __restrict__ pm)
{
    int k = blockIdx.x * 256 + threadIdx.x;
    int q = blockIdx.y;
    float tau = (float)q * (4095.0f / 255.0f);
    float dt = (float)k - tau;
    float c = fminf(fmaxf(dt, -128.f), 128.f);
    int idx = (int)c + 128;
    float z = dt * (1.0f / 32.0f);
    float lg = logf(expf(-0.5f * z * z) + 1e-6f);
    pm[(size_t)q * T + k] = msp[0] * (relbias[idx] + lg);
}

// ---------------- misc ----------------
__global__ void bcast_latents(const float* __restrict__ src, float* __restrict__ dst)
{
    int i = blockIdx.x * 256 + threadIdx.x;
    dst[i] = src[i % (LQ * D)];
}

__global__ void mean_kernel(const float* __restrict__ x, float* __restrict__ out)
{
    int i = blockIdx.x * 256 + threadIdx.x;   // B*D total
    int b = i / D, d = i % D;
    float s = 0.f;
    for (int q = 0; q < LQ; q++) s += x[((size_t)b * LQ + q) * D + d];
    out[i] = s * (1.0f / LQ);
}

// ---------------- host orchestration ----------------
extern "C" void kernel_launch(void* const* d_in, const int* in_sizes, int n_in,
                              void* d_out, int out_size)
{
    (void)in_sizes; (void)n_in; (void)out_size;
    const float* tokens     = (const float*)d_in[0];
    const float* proj_w     = (const float*)d_in[1];
    const float* proj_b     = (const float*)d_in[2];
    const float* latents    = (const float*)d_in[3];
    const float* lnx_g      = (const float*)d_in[4];
    const float* lnx_b      = (const float*)d_in[5];
    const float* xw_qkv     = (const float*)d_in[6];
    const float* xb_qkv     = (const float*)d_in[7];
    const float* xw_o       = (const float*)d_in[8];
    const float* xb_o       = (const float*)d_in[9];
    const float* rel_bias   = (const float*)d_in[10];
    const float* mask_scale = (const float*)d_in[11];
    const float* mx_w1      = (const float*)d_in[12];
    const float* mx_b1      = (const float*)d_in[13];
    const float* mx_w2      = (const float*)d_in[14];
    const float* mx_b2      = (const float*)d_in[15];
    const float* lns_g      = (const float*)d_in[16];
    const float* lns_b      = (const float*)d_in[17];
    const float* sw_qkv     = (const float*)d_in[18];
    const float* sb_qkv     = (const float*)d_in[19];
    const float* sw_o       = (const float*)d_in[20];
    const float* sb_o       = (const float*)d_in[21];
    const float* ms_w1      = (const float*)d_in[22];
    const float* ms_b1      = (const float*)d_in[23];
    const float* ms_w2      = (const float*)d_in[24];
    const float* ms_b2      = (const float*)d_in[25];
    const float* lno_g      = (const float*)d_in[26];
    const float* lno_b      = (const float*)d_in[27];
    float* out = (float*)d_out;

    cudaFuncSetAttribute(gemm_mma<1>, cudaFuncAttributeMaxDynamicSharedMemorySize, GSM);
    cudaFuncSetAttribute(gemm_mma<2>, cudaFuncAttributeMaxDynamicSharedMemorySize, GSM);
    cudaFuncSetAttribute(gemm_mma<3>, cudaFuncAttributeMaxDynamicSharedMemorySize, GSM);
    cudaFuncSetAttribute(fattn,       cudaFuncAttributeMaxDynamicSharedMemorySize, FA_SMEM);

    float *plat, *ptmpf, *pmask;
    __nv_bfloat16 *ptok2, *px2, *ptmp2, *phid2, *pat2, *pq2, *pkv2, *psq2,
                  *pwproj, *pwxqkv, *pwxo, *pwmx1, *pwmx2, *pwsqkv, *pwso, *pwms1, *pwms2;
    cudaGetSymbolAddress((void**)&plat,  g_lat);
    cudaGetSymbolAddress((void**)&ptmpf, g_tmpf);
    cudaGetSymbolAddress((void**)&pmask, g_mask);
    cudaGetSymbolAddress((void**)&ptok2, g_tok2);
    cudaGetSymbolAddress((void**)&px2,   g_x2);
    cudaGetSymbolAddress((void**)&ptmp2, g_tmp2);
    cudaGetSymbolAddress((void**)&phid2, g_hid2);
    cudaGetSymbolAddress((void**)&pat2,  g_at2);
    cudaGetSymbolAddress((void**)&pq2,   g_q2);
    cudaGetSymbolAddress((void**)&pkv2,  g_kv2);
    cudaGetSymbolAddress((void**)&psq2,  g_sq2);
    cudaGetSymbolAddress((void**)&pwproj, g_wproj2);
    cudaGetSymbolAddress((void**)&pwxqkv, g_wxqkv2);
    cudaGetSymbolAddress((void**)&pwxo,   g_wxo2);
    cudaGetSymbolAddress((void**)&pwmx1,  g_wmx1);
    cudaGetSymbolAddress((void**)&pwmx2,  g_wmx2);
    cudaGetSymbolAddress((void**)&pwsqkv, g_wsqkv2);
    cudaGetSymbolAddress((void**)&pwso,   g_wso2);
    cudaGetSymbolAddress((void**)&pwms1,  g_wms1);
    cudaGetSymbolAddress((void**)&pwms2,  g_wms2);

    const int BT = B * T, BL = B * LQ;

    // ---- weight + token splits ----
    split_pair<<<dim3(D_IN / 256, D),         256>>>(proj_w, pwproj, D_IN);
    split_pair<<<dim3(D / 256,   NB * 3 * D), 256>>>(xw_qkv, pwxqkv, D);
    split_pair<<<dim3(D / 256,   NB * D),     256>>>(xw_o,   pwxo,   D);
    split_pair<<<dim3(D / 256,   NB * HID),   256>>>(mx_w1,  pwmx1,  D);
    split_pair<<<dim3(HID / 256, NB * D),     256>>>(mx_w2,  pwmx2,  HID);
    split_pair<<<dim3(D / 256,   NB * 3 * D), 256>>>(sw_qkv, pwsqkv, D);
    split_pair<<<dim3(D / 256,   NB * D),     256>>>(sw_o,   pwso,   D);
    split_pair<<<dim3(D / 256,   NB * HID),   256>>>(ms_w1,  pwms1,  D);
    split_pair<<<dim3(HID / 256, NB * D),     256>>>(ms_w2,  pwms2,  HID);
    split_pair<<<dim3(D_IN / 256, BT),        256>>>(tokens, ptok2,  D_IN);

    // x = tokens @ proj_w.T + proj_b -> split into x2
    gemm_mma<3><<<dim3(D / 128, BT / 128), 256, GSM>>>(
        ptok2, 2 * D_IN, pwproj, 2 * D_IN, proj_b, nullptr, px2, D, D_IN);
    bcast_latents<<<(BL * D) / 256, 256>>>(latents, plat);

    for (int i = 0; i < NB; i++) {
        const __nv_bfloat16* wq2 = pwxqkv + (size_t)i * 3 * D * 2 * D;
        const float* bqkv = xb_qkv + (size_t)i * 3 * D;

        // ---- cross attention ----
        mask_kernel<<<dim3(T / 256, LQ), 256>>>(rel_bias + i * (2 * 128 + 1), mask_scale + i, pmask);
        ln_split<<<BL, 256>>>(plat, lnx_g + i * D, lnx_b + i * D, ptmp2);
        gemm_mma<3><<<dim3(D / 128, BL / 128), 256, GSM>>>(
            ptmp2, 2 * D, wq2, 2 * D, bqkv, nullptr, pq2, D, D);
        gemm_mma<3><<<dim3((2 * D) / 128, BT / 128), 256, GSM>>>(
            px2, 2 * D, wq2 + (size_t)D * 2 * D, 2 * D, bqkv + D, nullptr, pkv2, 2 * D, D);
        fattn<<<dim3(LQ / BQ, B * H), 128, FA_SMEM>>>(
            pq2, 2 * D, D,                 // Q: [row, hi(D)|lo(D)]
            pkv2, 4 * D, 2 * D,            // K: hi cols [0,D), lo at +2D
            pkv2 + D, 4 * D, 2 * D,        // V: hi cols [D,2D), lo at +2D
            pmask, pat2, T);
        gemm_mma<2><<<dim3(D / 128, BL / 128), 256, GSM>>>(
            pat2, 2 * D, pwxo + (size_t)i * D * 2 * D, 2 * D, xb_o + i * D, plat, nullptr, D, D);

        // ---- cross MLP (pre-LN reuses lnx params) ----
        ln_split<<<BL, 256>>>(plat, lnx_g + i * D, lnx_b + i * D, ptmp2);
        gemm_mma<1><<<dim3(HID / 128, BL / 128), 256, GSM>>>(
            ptmp2, 2 * D, pwmx1 + (size_t)i * HID * 2 * D, 2 * D, mx_b1 + i * HID,
            nullptr, phid2, HID, D);
        gemm_mma<2><<<dim3(D / 128, BL / 128), 256, GSM>>>(
            phid2, 2 * HID, pwmx2 + (size_t)i * D * 2 * HID, 2 * HID, mx_b2 + i * D,
            plat, nullptr, D, HID);

        // ---- self attention ----
        ln_split<<<BL, 256>>>(plat, lns_g + i * D, lns_b + i * D, ptmp2);
        gemm_mma<3><<<dim3((3 * D) / 128, BL / 128), 256, GSM>>>(
            ptmp2, 2 * D, pwsqkv + (size_t)i * 3 * D * 2 * D, 2 * D,
            sb_qkv + (size_t)i * 3 * D, nullptr, psq2, 3 * D, D);
        fattn<<<dim3(LQ / BQ, B * H), 128, FA_SMEM>>>(
            psq2, 6 * D, 3 * D,            // Q: hi cols [0,D), lo at +3D
            psq2 + D, 6 * D, 3 * D,        // K: hi cols [D,2D)
            psq2 + 2 * D, 6 * D, 3 * D,    // V: hi cols [2D,3D)
            nullptr, pat2, LQ);
        gemm_mma<2><<<dim3(D / 128, BL / 128), 256, GSM>>>(
            pat2, 2 * D, pwso + (size_t)i * D * 2 * D, 2 * D, sb_o + i * D, plat, nullptr, D, D);

        // ---- self MLP ----
        ln_split<<<BL, 256>>>(plat, lns_g + i * D, lns_b + i * D, ptmp2);
        gemm_mma<1><<<dim3(HID / 128, BL / 128), 256, GSM>>>(
            ptmp2, 2 * D, pwms1 + (size_t)i * HID * 2 * D, 2 * D, ms_b1 + i * HID,
            nullptr, phid2, HID, D);
        gemm_mma<2><<<dim3(D / 128, BL / 128), 256, GSM>>>(
            phid2, 2 * HID, pwms2 + (size_t)i * D * 2 * HID, 2 * HID, ms_b2 + i * D,
            plat, nullptr, D, HID);
    }

    // final LN + mean over latents
    ln_kernel<<<BL, 256>>>(plat, lno_g, lno_b, ptmpf);
    mean_kernel<<<(B * D) / 256, 256>>>(ptmpf, out);
}

// round 6
// speedup vs baseline: 3.6544x; 1.3104x over previous
#include <cuda_runtime.h>
#include <cuda_bf16.h>
#include <cstdint>
#include <math.h>

// ---------------- problem constants ----------------
#define B   8
#define T   4096
#define D_IN 256
#define D   512
#define LQ  256
#define H   8
#define HD  64
#define NB  6
#define HID 2048
#define KVN (NB * 2 * D)          // 6144: all blocks' K|V columns

// ---------------- mma.sync helpers (sm_80+ PTX; no tcgen05) ----------------
__device__ __forceinline__ uint32_t smem_u32(const void* p) {
    uint32_t a;
    asm("{ .reg .u64 t; cvta.to.shared.u64 t, %1; cvt.u32.u64 %0, t; }" : "=r"(a) : "l"(p));
    return a;
}
__device__ __forceinline__ void cp16(uint32_t dst, const void* src) {
    asm volatile("cp.async.cg.shared.global [%0], [%1], 16;\n" :: "r"(dst), "l"(src));
}
__device__ __forceinline__ void ldsm4(uint32_t& r0, uint32_t& r1, uint32_t& r2, uint32_t& r3,
                                      uint32_t addr) {
    asm volatile("ldmatrix.sync.aligned.m8n8.x4.shared.b16 {%0,%1,%2,%3}, [%4];"
        : "=r"(r0), "=r"(r1), "=r"(r2), "=r"(r3) : "r"(addr));
}
__device__ __forceinline__ void ldsm4t(uint32_t& r0, uint32_t& r1, uint32_t& r2, uint32_t& r3,
                                       uint32_t addr) {
    asm volatile("ldmatrix.sync.aligned.m8n8.x4.trans.shared.b16 {%0,%1,%2,%3}, [%4];"
        : "=r"(r0), "=r"(r1), "=r"(r2), "=r"(r3) : "r"(addr));
}
__device__ __forceinline__ void mma16816(float* c, const uint32_t* a, uint32_t b0, uint32_t b1) {
    asm volatile("mma.sync.aligned.m16n8k16.row.col.f32.bf16.bf16.f32 "
        "{%0,%1,%2,%3}, {%4,%5,%6,%7}, {%8,%9}, {%0,%1,%2,%3};"
        : "+f"(c[0]), "+f"(c[1]), "+f"(c[2]), "+f"(c[3])
        : "r"(a[0]), "r"(a[1]), "r"(a[2]), "r"(a[3]), "r"(b0), "r"(b1));
}
__device__ __forceinline__ float ex2(float x) {
    float r; asm("ex2.approx.f32 %0, %1;" : "=f"(r) : "f"(x)); return r;
}

// ---------------- scratch (static device globals; no allocation) ----------------
__device__ float g_lat [B*LQ*D];
__device__ float g_tmpf[B*LQ*D];
__device__ float g_mask6[NB*LQ*T];
__device__ float g_bc  [KVN];             // folded KV bias
__device__ float g_zerob[D_IN];           // stays zero (statics are zero-init)

// bf16 hi|lo split buffers (row layout: [hi(K) | lo(K)])
__device__ __align__(256) __nv_bfloat16 g_tok2 [B*T*2*D_IN];
__device__ __align__(256) __nv_bfloat16 g_tmp2 [B*LQ*2*D];
__device__ __align__(256) __nv_bfloat16 g_hid2 [B*LQ*2*HID];
__device__ __align__(256) __nv_bfloat16 g_at2  [B*LQ*2*D];
__device__ __align__(256) __nv_bfloat16 g_q2   [B*LQ*2*D];
__device__ __align__(256) __nv_bfloat16 g_kvall2[(size_t)B*T*2*KVN];   // all-blocks K|V (805MB)
__device__ __align__(256) __nv_bfloat16 g_sq2  [B*LQ*2*(3*D)];
__device__ __align__(256) __nv_bfloat16 g_wpT2 [D_IN*2*D];             // proj_w transposed, split
__device__ __align__(256) __nv_bfloat16 g_wc2  [KVN*2*D_IN];           // combined KV weights
__device__ __align__(256) __nv_bfloat16 g_wxqkv2[NB*3*D*2*D];
__device__ __align__(256) __nv_bfloat16 g_wxo2  [NB*D*2*D];
__device__ __align__(256) __nv_bfloat16 g_wmx1  [NB*HID*2*D];
__device__ __align__(256) __nv_bfloat16 g_wmx2  [NB*D*2*HID];
__device__ __align__(256) __nv_bfloat16 g_wsqkv2[NB*3*D*2*D];
__device__ __align__(256) __nv_bfloat16 g_wso2  [NB*D*2*D];
__device__ __align__(256) __nv_bfloat16 g_wms1  [NB*HID*2*D];
__device__ __align__(256) __nv_bfloat16 g_wms2  [NB*D*2*HID];

__device__ __forceinline__ void split2(float x, __nv_bfloat16& h, __nv_bfloat16& l) {
    h = __float2bfloat16(x);
    l = __float2bfloat16(x - __bfloat162float(h));
}
__device__ __forceinline__ uint32_t pk2(__nv_bfloat16 a, __nv_bfloat16 b) {
    __nv_bfloat162 t(a, b);
    return *(uint32_t*)&t;
}

// ---------------- reductions ----------------
__device__ __forceinline__ float block_sum256(float v, float* sh) {
    #pragma unroll
    for (int o = 16; o; o >>= 1) v += __shfl_xor_sync(0xffffffffu, v, o);
    if ((threadIdx.x & 31) == 0) sh[threadIdx.x >> 5] = v;
    __syncthreads();
    float t = (threadIdx.x < 8) ? sh[threadIdx.x] : 0.f;
    if (threadIdx.x < 32) {
        #pragma unroll
        for (int o = 4; o; o >>= 1) t += __shfl_xor_sync(0xffffffffu, t, o);
        if (threadIdx.x == 0) sh[0] = t;
    }
    __syncthreads();
    float r = sh[0];
    __syncthreads();
    return r;
}

// ================= tensor-core GEMM (HMMA): C[M,N] = A·W^T + bias =================
// A2 [M, 2K] = [hi | lo] bf16, W2 [N, 2K] likewise. 3 K-passes (hh, hl, lh).
// EPI: 1 = bias+gelu->split C2   2 = bias+res(inplace fp32 C)   3 = bias->split C2
#define BK 32
#define AST 40
#define STG (128 * AST * 2)
#define NSTAGE 4
#define GSM (NSTAGE * 2 * STG)

template<int EPI>
__global__ __launch_bounds__(256)
void gemm_mma(const __nv_bfloat16* __restrict__ A2, int ldA,
              const __nv_bfloat16* __restrict__ W2, int ldW,
              const float* __restrict__ bias,
              float* __restrict__ C, __nv_bfloat16* __restrict__ C2,
              int N, int K)
{
    extern __shared__ __align__(256) char smraw[];
    const uint32_t base = smem_u32(smraw);
    const int tid = threadIdx.x;
    const int bm = blockIdx.y * 128, bn = blockIdx.x * 128;
    const int lane = tid & 31, warp = tid >> 5;
    const int wm = warp & 3, wn = warp >> 2;

    const int nkc = K / BK;
    const int nch = 3 * nkc;

    float acc[2][8][4];
    #pragma unroll
    for (int i = 0; i < 2; i++)
        #pragma unroll
        for (int j = 0; j < 8; j++)
            #pragma unroll
            for (int k = 0; k < 4; k++) acc[i][j][k] = 0.f;

    auto issue_load = [&](int i, int st) {
        int s = i / nkc, kc = i - s * nkc;
        int ao = ((s == 2) ? K : 0) + kc * BK;
        int wo = ((s == 1) ? K : 0) + kc * BK;
        uint32_t smA = base + st * (2 * STG);
        uint32_t smB = smA + STG;
        const __nv_bfloat16* As = A2 + (size_t)bm * ldA + ao;
        const __nv_bfloat16* Ws = W2 + (size_t)bn * ldW + wo;
        #pragma unroll
        for (int j = 0; j < 2; j++) {
            int u = j * 256 + tid;
            int r = u >> 2, cc = (u & 3) * 8;
            cp16(smA + (uint32_t)(r * AST + cc) * 2, As + (size_t)r * ldA + cc);
            cp16(smB + (uint32_t)(r * AST + cc) * 2, Ws + (size_t)r * ldW + cc);
        }
        asm volatile("cp.async.commit_group;\n" ::: "memory");
    };

    const int arow = wm * 32 + ((lane >> 3) & 1) * 8 + (lane & 7);
    const int akof = ((lane >> 4) & 1) * 8;
    const int brow = wn * 64 + ((lane >> 4) & 1) * 8 + (lane & 7);
    const int bkof = ((lane >> 3) & 1) * 8;

    #pragma unroll
    for (int s = 0; s < NSTAGE - 1; s++) issue_load(s, s);

    for (int i = 0; i < nch; i++) {
        int rem = nch - 1 - i;
        if (rem >= 2)      asm volatile("cp.async.wait_group 2;\n" ::: "memory");
        else if (rem == 1) asm volatile("cp.async.wait_group 1;\n" ::: "memory");
        else               asm volatile("cp.async.wait_group 0;\n" ::: "memory");
        __syncthreads();
        if (i + NSTAGE - 1 < nch) issue_load(i + NSTAGE - 1, (i + NSTAGE - 1) % NSTAGE);

        uint32_t smA = base + (i % NSTAGE) * (2 * STG);
        uint32_t smB = smA + STG;
        #pragma unroll
        for (int kk = 0; kk < 2; kk++) {
            const int k0 = kk * 16;
            uint32_t a[2][4], b[4][4];
            #pragma unroll
            for (int fm = 0; fm < 2; fm++)
                ldsm4(a[fm][0], a[fm][1], a[fm][2], a[fm][3],
                      smA + (uint32_t)((arow + fm * 16) * AST + k0 + akof) * 2);
            #pragma unroll
            for (int fb = 0; fb < 4; fb++)
                ldsm4(b[fb][0], b[fb][1], b[fb][2], b[fb][3],
                      smB + (uint32_t)((brow + fb * 16) * AST + k0 + bkof) * 2);
            #pragma unroll
            for (int fm = 0; fm < 2; fm++)
                #pragma unroll
                for (int fn = 0; fn < 8; fn++)
                    mma16816(acc[fm][fn], a[fm], b[fn >> 1][(fn & 1) * 2],
                             b[fn >> 1][(fn & 1) * 2 + 1]);
        }
    }

    const int lr = lane >> 2, lc = (lane & 3) * 2;
    #pragma unroll
    for (int fm = 0; fm < 2; fm++) {
        #pragma unroll
        for (int fn = 0; fn < 8; fn++) {
            float* cc = acc[fm][fn];
            int m0 = bm + wm * 32 + fm * 16 + lr;
            int n0 = bn + wn * 64 + fn * 8 + lc;
            float b0 = bias[n0], b1 = bias[n0 + 1];
            float v00 = cc[0] + b0, v01 = cc[1] + b1;
            float v10 = cc[2] + b0, v11 = cc[3] + b1;
            if (EPI == 1) {
                v00 = 0.5f * v00 * (1.0f + erff(v00 * 0.70710678118654752f));
                v01 = 0.5f * v01 * (1.0f + erff(v01 * 0.70710678118654752f));
                v10 = 0.5f * v10 * (1.0f + erff(v10 * 0.70710678118654752f));
                v11 = 0.5f * v11 * (1.0f + erff(v11 * 0.70710678118654752f));
            }
            if (EPI == 2) {
                float2 r0 = *(const float2*)&C[(size_t)m0 * N + n0];
                float2 r1 = *(const float2*)&C[(size_t)(m0 + 8) * N + n0];
                *(float2*)&C[(size_t)m0 * N + n0]       = make_float2(v00 + r0.x, v01 + r0.y);
                *(float2*)&C[(size_t)(m0 + 8) * N + n0] = make_float2(v10 + r1.x, v11 + r1.y);
            } else {
                __nv_bfloat16 h0, l0, h1, l1;
                split2(v00, h0, l0); split2(v01, h1, l1);
                *(__nv_bfloat162*)&C2[(size_t)m0 * 2 * N + n0]     = __nv_bfloat162(h0, h1);
                *(__nv_bfloat162*)&C2[(size_t)m0 * 2 * N + N + n0] = __nv_bfloat162(l0, l1);
                split2(v10, h0, l0); split2(v11, h1, l1);
                *(__nv_bfloat162*)&C2[(size_t)(m0 + 8) * 2 * N + n0]     = __nv_bfloat162(h0, h1);
                *(__nv_bfloat162*)&C2[(size_t)(m0 + 8) * 2 * N + N + n0] = __nv_bfloat162(l0, l1);
            }
        }
    }
}

// ---------- 64x128-tile variant (128 threads, higher CTA count for small M) ----------
#define ASTGH (64 * AST * 2)
#define BSTGH (128 * AST * 2)
#define GSMH (NSTAGE * (ASTGH + BSTGH))

template<int EPI>
__global__ __launch_bounds__(128)
void gemm_mma_h(const __nv_bfloat16* __restrict__ A2, int ldA,
                const __nv_bfloat16* __restrict__ W2, int ldW,
                const float* __restrict__ bias,
                float* __restrict__ C, __nv_bfloat16* __restrict__ C2,
                int N, int K)
{
    extern __shared__ __align__(256) char smraw[];
    const uint32_t base = smem_u32(smraw);
    const int tid = threadIdx.x;
    const int bm = blockIdx.y * 64, bn = blockIdx.x * 128;
    const int lane = tid & 31, warp = tid >> 5;
    const int wm = warp & 1, wn = warp >> 1;

    const int nkc = K / BK;
    const int nch = 3 * nkc;

    float acc[2][8][4];
    #pragma unroll
    for (int i = 0; i < 2; i++)
        #pragma unroll
        for (int j = 0; j < 8; j++)
            #pragma unroll
            for (int k = 0; k < 4; k++) acc[i][j][k] = 0.f;

    auto issue_load = [&](int i, int st) {
        int s = i / nkc, kc = i - s * nkc;
        int ao = ((s == 2) ? K : 0) + kc * BK;
        int wo = ((s == 1) ? K : 0) + kc * BK;
        uint32_t smA = base + st * (ASTGH + BSTGH);
        uint32_t smB = smA + ASTGH;
        const __nv_bfloat16* As = A2 + (size_t)bm * ldA + ao;
        const __nv_bfloat16* Ws = W2 + (size_t)bn * ldW + wo;
        #pragma unroll
        for (int j = 0; j < 2; j++) {
            int u = j * 128 + tid;
            int r = u >> 2, cc = (u & 3) * 8;
            cp16(smA + (uint32_t)(r * AST + cc) * 2, As + (size_t)r * ldA + cc);
        }
        #pragma unroll
        for (int j = 0; j < 4; j++) {
            int u = j * 128 + tid;
            int r = u >> 2, cc = (u & 3) * 8;
            cp16(smB + (uint32_t)(r * AST + cc) * 2, Ws + (size_t)r * ldW + cc);
        }
        asm volatile("cp.async.commit_group;\n" ::: "memory");
    };

    const int arow = wm * 32 + ((lane >> 3) & 1) * 8 + (lane & 7);
    const int akof = ((lane >> 4) & 1) * 8;
    const int brow = wn * 64 + ((lane >> 4) & 1) * 8 + (lane & 7);
    const int bkof = ((lane >> 3) & 1) * 8;

    #pragma unroll
    for (int s = 0; s < NSTAGE - 1; s++) issue_load(s, s);

    for (int i = 0; i < nch; i++) {
        int rem = nch - 1 - i;
        if (rem >= 2)      asm volatile("cp.async.wait_group 2;\n" ::: "memory");
        else if (rem == 1) asm volatile("cp.async.wait_group 1;\n" ::: "memory");
        else               asm volatile("cp.async.wait_group 0;\n" ::: "memory");
        __syncthreads();
        if (i + NSTAGE - 1 < nch) issue_load(i + NSTAGE - 1, (i + NSTAGE - 1) % NSTAGE);

        uint32_t smA = base + (i % NSTAGE) * (ASTGH + BSTGH);
        uint32_t smB = smA + ASTGH;
        #pragma unroll
        for (int kk = 0; kk < 2; kk++) {
            const int k0 = kk * 16;
            uint32_t a[2][4], b[4][4];
            #pragma unroll
            for (int fm = 0; fm < 2; fm++)
                ldsm4(a[fm][0], a[fm][1], a[fm][2], a[fm][3],
                      smA + (uint32_t)((arow + fm * 16) * AST + k0 + akof) * 2);
            #pragma unroll
            for (int fb = 0; fb < 4; fb++)
                ldsm4(b[fb][0], b[fb][1], b[fb][2], b[fb][3],
                      smB + (uint32_t)((brow + fb * 16) * AST + k0 + bkof) * 2);
            #pragma unroll
            for (int fm = 0; fm < 2; fm++)
                #pragma unroll
                for (int fn = 0; fn < 8; fn++)
                    mma16816(acc[fm][fn], a[fm], b[fn >> 1][(fn & 1) * 2],
                             b[fn >> 1][(fn & 1) * 2 + 1]);
        }
    }

    const int lr = lane >> 2, lc = (lane & 3) * 2;
    #pragma unroll
    for (int fm = 0; fm < 2; fm++) {
        #pragma unroll
        for (int fn = 0; fn < 8; fn++) {
            float* cc = acc[fm][fn];
            int m0 = bm + wm * 32 + fm * 16 + lr;
            int n0 = bn + wn * 64 + fn * 8 + lc;
            float b0 = bias[n0], b1 = bias[n0 + 1];
            float v00 = cc[0] + b0, v01 = cc[1] + b1;
            float v10 = cc[2] + b0, v11 = cc[3] + b1;
            if (EPI == 1) {
                v00 = 0.5f * v00 * (1.0f + erff(v00 * 0.70710678118654752f));
                v01 = 0.5f * v01 * (1.0f + erff(v01 * 0.70710678118654752f));
                v10 = 0.5f * v10 * (1.0f + erff(v10 * 0.70710678118654752f));
                v11 = 0.5f * v11 * (1.0f + erff(v11 * 0.70710678118654752f));
            }
            if (EPI == 2) {
                float2 r0 = *(const float2*)&C[(size_t)m0 * N + n0];
                float2 r1 = *(const float2*)&C[(size_t)(m0 + 8) * N + n0];
                *(float2*)&C[(size_t)m0 * N + n0]       = make_float2(v00 + r0.x, v01 + r0.y);
                *(float2*)&C[(size_t)(m0 + 8) * N + n0] = make_float2(v10 + r1.x, v11 + r1.y);
            } else {
                __nv_bfloat16 h0, l0, h1, l1;
                split2(v00, h0, l0); split2(v01, h1, l1);
                *(__nv_bfloat162*)&C2[(size_t)m0 * 2 * N + n0]     = __nv_bfloat162(h0, h1);
                *(__nv_bfloat162*)&C2[(size_t)m0 * 2 * N + N + n0] = __nv_bfloat162(l0, l1);
                split2(v10, h0, l0); split2(v11, h1, l1);
                *(__nv_bfloat162*)&C2[(size_t)(m0 + 8) * 2 * N + n0]     = __nv_bfloat162(h0, h1);
                *(__nv_bfloat162*)&C2[(size_t)(m0 + 8) * 2 * N + N + n0] = __nv_bfloat162(l0, l1);
            }
        }
    }
}

// ================= fused flash attention (HMMA, split bf16, no running max) =========
// 64 q rows / block (4 warps x 16), 64-key chunks, double-buffered. QK: 2 split passes
// (hh + h·lo). PV: 3 split passes. Base-2 exponent.
#define BQ 64
#define BKC 64
#define QST 72
#define FTILE (64 * QST * 2)                  // 9216 B
#define FA_SMEM (FTILE + 2 * 4 * FTILE)       // Qh + 2 stages * (Kh,Kl,Vh,Vl) = 82944

__global__ __launch_bounds__(128)
void fattn(const __nv_bfloat16* __restrict__ Qp, int ldq,
           const __nv_bfloat16* __restrict__ Kp, int ldk, int ok,
           const __nv_bfloat16* __restrict__ Vp, int ldv, int ov,
           const float* __restrict__ pm, __nv_bfloat16* __restrict__ O2, int Tk)
{
    extern __shared__ __align__(256) char smraw[];
    const uint32_t base = smem_u32(smraw);
    const int tid = threadIdx.x, lane = tid & 31, warp = tid >> 5;
    const int bh = (int)blockIdx.y, b = bh >> 3, h = bh & 7;
    const int q0 = (int)blockIdx.x * BQ;

    const __nv_bfloat16* Qb = Qp + (size_t)(b * LQ + q0) * ldq + h * HD;
    const __nv_bfloat16* Kb = Kp + (size_t)b * Tk * ldk + h * HD;
    const __nv_bfloat16* Vb = Vp + (size_t)b * Tk * ldv + h * HD;

    // Q hi tile -> smem
    #pragma unroll
    for (int j = 0; j < 4; j++) {
        int u = j * 128 + tid, r = u >> 3, c8 = (u & 7) * 8;
        cp16(base + (uint32_t)(r * QST + c8) * 2, Qb + (size_t)r * ldq + c8);
    }
    asm volatile("cp.async.commit_group;\n" ::: "memory");

    const int nc = Tk / BKC;
    auto load_chunk = [&](int ci, int st) {
        uint32_t sb = base + FTILE + st * 4 * FTILE;
        const __nv_bfloat16* Kc = Kb + (size_t)ci * BKC * ldk;
        const __nv_bfloat16* Vc = Vb + (size_t)ci * BKC * ldv;
        #pragma unroll
        for (int j = 0; j < 4; j++) {
            int u = j * 128 + tid, r = u >> 3, c8 = (u & 7) * 8;
            uint32_t off = (uint32_t)(r * QST + c8) * 2;
            cp16(sb + off,             Kc + (size_t)r * ldk + c8);
            cp16(sb + FTILE + off,     Kc + (size_t)r * ldk + ok + c8);
            cp16(sb + 2 * FTILE + off, Vc + (size_t)r * ldv + c8);
            cp16(sb + 3 * FTILE + off, Vc + (size_t)r * ldv + ov + c8);
        }
        asm volatile("cp.async.commit_group;\n" ::: "memory");
    };

    load_chunk(0, 0);
    asm volatile("cp.async.wait_group 1;\n" ::: "memory");   // Q ready
    __syncthreads();

    const int qrow = warp * 16 + ((lane >> 3) & 1) * 8 + (lane & 7);
    const int qko  = ((lane >> 4) & 1) * 8;
    uint32_t qf[4][4];
    #pragma unroll
    for (int ds = 0; ds < 4; ds++)
        ldsm4(qf[ds][0], qf[ds][1], qf[ds][2], qf[ds][3],
              base + (uint32_t)(qrow * QST + ds * 16 + qko) * 2);

    load_chunk(1, 1);

    float o[8][4];
    #pragma unroll
    for (int i = 0; i < 8; i++)
        #pragma unroll
        for (int j = 0; j < 4; j++) o[i][j] = 0.f;
    float lsum0 = 0.f, lsum1 = 0.f;

    const float SC  = 0.125f * 1.44269504088896f;
    const float L2E = 1.44269504088896f;
    const int lr = lane >> 2, lc = (lane & 3) * 2;
    const int krow = ((lane >> 4) & 1) * 8 + (lane & 7);
    const int kko  = ((lane >> 3) & 1) * 8;
    const int vrow = lane & 15;
    const int vco  = ((lane >> 4) & 1) * 8;
    const int qr_g = q0 + warp * 16 + lr;

    for (int ci = 0; ci < nc; ci++) {
        if (ci == nc - 1) asm volatile("cp.async.wait_group 0;\n" ::: "memory");
        else              asm volatile("cp.async.wait_group 1;\n" ::: "memory");
        __syncthreads();

        uint32_t sb = base + FTILE + (ci & 1) * 4 * FTILE;

        // ---- S = Q·K^T (2 split passes: Qh·Kh + Qh·Kl) ----
        float s[8][4];
        #pragma unroll
        for (int i = 0; i < 8; i++)
            #pragma unroll
            for (int j = 0; j < 4; j++) s[i][j] = 0.f;
        #pragma unroll
        for (int ps = 0; ps < 2; ps++) {
            const uint32_t kb = sb + ((ps == 1) ? FTILE : 0);
            #pragma unroll
            for (int ds = 0; ds < 4; ds++) {
                #pragma unroll
                for (int g = 0; g < 4; g++) {
                    uint32_t b0, b1, b2, b3;
                    ldsm4(b0, b1, b2, b3,
                          kb + (uint32_t)((g * 16 + krow) * QST + ds * 16 + kko) * 2);
                    mma16816(s[2 * g],     qf[ds], b0, b1);
                    mma16816(s[2 * g + 1], qf[ds], b2, b3);
                }
            }
        }

        // ---- softmax numerators + P fragments (hi/lo) ----
        uint32_t ph[4][4], pl[4][4];
        #pragma unroll
        for (int nt = 0; nt < 8; nt++) {
            float t0 = s[nt][0] * SC, t1 = s[nt][1] * SC;
            float t2 = s[nt][2] * SC, t3 = s[nt][3] * SC;
            if (pm) {
                const float* pmr = pm + (size_t)qr_g * Tk + ci * BKC + nt * 8 + lc;
                float2 m0 = *(const float2*)pmr;
                float2 m1 = *(const float2*)(pmr + (size_t)8 * Tk);
                t0 = fmaf(m0.x, L2E, t0); t1 = fmaf(m0.y, L2E, t1);
                t2 = fmaf(m1.x, L2E, t2); t3 = fmaf(m1.y, L2E, t3);
            }
            float p0 = ex2(t0), p1 = ex2(t1), p2 = ex2(t2), p3 = ex2(t3);
            lsum0 += p0 + p1;
            lsum1 += p2 + p3;
            __nv_bfloat16 h0, l0, h1, l1, h2, l2, h3, l3;
            split2(p0, h0, l0); split2(p1, h1, l1);
            split2(p2, h2, l2); split2(p3, h3, l3);
            int j = nt >> 1, qi = (nt & 1) * 2;
            ph[j][qi]     = pk2(h0, h1);
            ph[j][qi + 1] = pk2(h2, h3);
            pl[j][qi]     = pk2(l0, l1);
            pl[j][qi + 1] = pk2(l2, l3);
        }

        // ---- O += P·V (3 split passes) ----
        #pragma unroll
        for (int ps = 0; ps < 3; ps++) {
            const uint32_t vbb = sb + 2 * FTILE + ((ps == 2) ? FTILE : 0);
            #pragma unroll
            for (int ks = 0; ks < 4; ks++) {
                const uint32_t* pf = (ps == 1) ? pl[ks] : ph[ks];
                #pragma unroll
                for (int g = 0; g < 4; g++) {
                    uint32_t b0, b1, b2, b3;
                    ldsm4t(b0, b1, b2, b3,
                           vbb + (uint32_t)((ks * 16 + vrow) * QST + g * 16 + vco) * 2);
                    mma16816(o[2 * g],     pf, b0, b1);
                    mma16816(o[2 * g + 1], pf, b2, b3);
                }
            }
        }

        __syncthreads();
        if (ci + 2 < nc) load_chunk(ci + 2, ci & 1);
    }

    lsum0 += __shfl_xor_sync(0xffffffffu, lsum0, 1);
    lsum0 += __shfl_xor_sync(0xffffffffu, lsum0, 2);
    lsum1 += __shfl_xor_sync(0xffffffffu, lsum1, 1);
    lsum1 += __shfl_xor_sync(0xffffffffu, lsum1, 2);
    float inv0 = 1.0f / lsum0, inv1 = 1.0f / lsum1;

    const size_t row0 = (size_t)(b * LQ + qr_g);
    #pragma unroll
    for (int nt = 0; nt < 8; nt++) {
        int col = h * HD + nt * 8 + lc;
        float v0 = o[nt][0] * inv0, v1 = o[nt][1] * inv0;
        float v2 = o[nt][2] * inv1, v3 = o[nt][3] * inv1;
        __nv_bfloat16 h0, l0, h1, l1;
        split2(v0, h0, l0); split2(v1, h1, l1);
        *(__nv_bfloat162*)&O2[row0 * 2 * D + col]     = __nv_bfloat162(h0, h1);
        *(__nv_bfloat162*)&O2[row0 * 2 * D + D + col] = __nv_bfloat162(l0, l1);
        split2(v2, h0, l0); split2(v3, h1, l1);
        *(__nv_bfloat162*)&O2[(row0 + 8) * 2 * D + col]     = __nv_bfloat162(h0, h1);
        *(__nv_bfloat162*)&O2[(row0 + 8) * 2 * D + D + col] = __nv_bfloat162(l0, l1);
    }
}

// ---------------- elementwise split: src[rows,K] fp32 -> dst[rows,2K] bf16 ----------------
__global__ void split_pair(const float* __restrict__ src, __nv_bfloat16* __restrict__ dst, int K)
{
    int c = blockIdx.x * 256 + threadIdx.x;
    int r = blockIdx.y;
    float x = src[(size_t)r * K + c];
    __nv_bfloat16 h, l; split2(x, h, l);
    dst[(size_t)r * 2 * K + c] = h;
    dst[(size_t)r * 2 * K + K + c] = l;
}

// -------- transpose+split: proj_w[D, D_IN] -> wT2[D_IN, 2*D] (wT2[c,k]=pw[k,c]) --------
__global__ void tsplit_proj(const float* __restrict__ pw, __nv_bfloat16* __restrict__ wT2)
{
    int k = blockIdx.x * 256 + threadIdx.x;   // over D
    int c = blockIdx.y;                        // over D_IN
    float x = pw[(size_t)k * D_IN + c];
    __nv_bfloat16 h, l; split2(x, h, l);
    wT2[(size_t)c * 2 * D + k] = h;
    wT2[(size_t)c * 2 * D + D + k] = l;
}

// -------- folded KV bias: bc[i*1024+n] = Wkv_i[n,:]·proj_b + bkv_i[n] --------
__global__ void kvbias_kernel(const float* __restrict__ xw_qkv, const float* __restrict__ xb_qkv,
                              const float* __restrict__ proj_b, float* __restrict__ bc)
{
    __shared__ float sh[32];
    int g = blockIdx.x;                 // [0, KVN)
    int i = g >> 10, n = g & 1023;
    const float* wr = xw_qkv + ((size_t)i * 3 * D + D + n) * D;
    float s = 0.f;
    for (int k = threadIdx.x; k < D; k += 256) s += wr[k] * proj_b[k];
    float tot = block_sum256(s, sh);
    if (threadIdx.x == 0) bc[g] = tot + xb_qkv[(size_t)i * 3 * D + D + n];
}

// ---------------- LayerNorm -> split bf16 (D=512, one block/row) ----------------
__global__ void ln_split(const float* __restrict__ x, const float* __restrict__ g,
                         const float* __restrict__ b, __nv_bfloat16* __restrict__ y2)
{
    __shared__ float sh[32];
    const int row = blockIdx.x, tid = threadIdx.x;
    const float* xr = x + (size_t)row * D;
    float2 v = *(const float2*)&xr[tid * 2];
    float total = block_sum256(v.x + v.y, sh);
    float mean = total * (1.0f / D);
    float d0 = v.x - mean, d1 = v.y - mean;
    float sq = block_sum256(d0 * d0 + d1 * d1, sh);
    float inv = rsqrtf(sq * (1.0f / D) + 1e-5f);
    float2 go = *(const float2*)&g[tid * 2];
    float2 bo = *(const float2*)&b[tid * 2];
    float o0 = d0 * inv * go.x + bo.x;
    float o1 = d1 * inv * go.y + bo.y;
    __nv_bfloat16 h0, l0, h1, l1;
    split2(o0, h0, l0); split2(o1, h1, l1);
    __nv_bfloat16* dst = y2 + (size_t)row * 2 * D;
    ((__nv_bfloat162*)dst)[tid] = __nv_bfloat162(h0, h1);
    ((__nv_bfloat162*)(dst + D))[tid] = __nv_bfloat162(l0, l1);
}

// ---------------- plain LayerNorm (final) ----------------
__global__ void ln_kernel(const float* __restrict__ x, const float* __restrict__ g,
                          const float* __restrict__ b, float* __restrict__ y)
{
    __shared__ float sh[32];
    const int row = blockIdx.x, tid = threadIdx.x;
    const float* xr = x + (size_t)row * D;
    float2 v = *(const float2*)&xr[tid * 2];
    float total = block_sum256(v.x + v.y, sh);
    float mean = total * (1.0f / D);
    float d0 = v.x - mean, d1 = v.y - mean;
    float sq = block_sum256(d0 * d0 + d1 * d1, sh);
    float inv = rsqrtf(sq * (1.0f / D) + 1e-5f);
    float2 go = *(const float2*)&g[tid * 2];
    float2 bo = *(const float2*)&b[tid * 2];
    float2 o;
    o.x = d0 * inv * go.x + bo.x;
    o.y = d1 * inv * go.y + bo.y;
    *(float2*)&y[(size_t)row * D + tid * 2] = o;
}

// ---------------- all 6 relative-time masks in one launch ----------------
__global__ void mask6_kernel(const float* __restrict__ rel_bias, const float* __restrict__ ms,
                             float* __restrict__ pm6)
{
    int k = blockIdx.x * 256 + threadIdx.x;
    int q = blockIdx.y;
    int z = blockIdx.z;
    float tau = (float)q * (4095.0f / 255.0f);
    float dt = (float)k - tau;
    float c = fminf(fmaxf(dt, -128.f), 128.f);
    int idx = (int)c + 128;
    float zz = dt * (1.0f / 32.0f);
    float lg = logf(expf(-0.5f * zz * zz) + 1e-6f);
    pm6[(size_t)z * LQ * T + (size_t)q * T + k] = ms[z] * (rel_bias[z * 257 + idx] + lg);
}

// ---------------- misc ----------------
__global__ void bcast_latents(const float* __restrict__ src, float* __restrict__ dst)
{
    int i = blockIdx.x * 256 + threadIdx.x;
    dst[i] = src[i % (LQ * D)];
}

__global__ void mean_kernel(const float* __restrict__ x, float* __restrict__ out)
{
    int i = blockIdx.x * 256 + threadIdx.x;
    int b = i / D, d = i % D;
    float s = 0.f;
    for (int q = 0; q < LQ; q++) s += x[((size_t)b * LQ + q) * D + d];
    out[i] = s * (1.0f / LQ);
}

// ---------------- host orchestration ----------------
extern "C" void kernel_launch(void* const* d_in, const int* in_sizes, int n_in,
                              void* d_out, int out_size)
{
    (void)in_sizes; (void)n_in; (void)out_size;
    const float* tokens     = (const float*)d_in[0];
    const float* proj_w     = (const float*)d_in[1];
    const float* proj_b     = (const float*)d_in[2];
    const float* latents    = (const float*)d_in[3];
    const float* lnx_g      = (const float*)d_in[4];
    const float* lnx_b      = (const float*)d_in[5];
    const float* xw_qkv     = (const float*)d_in[6];
    const float* xb_qkv     = (const float*)d_in[7];
    const float* xw_o       = (const float*)d_in[8];
    const float* xb_o       = (const float*)d_in[9];
    const float* rel_bias   = (const float*)d_in[10];
    const float* mask_scale = (const float*)d_in[11];
    const float* mx_w1      = (const float*)d_in[12];
    const float* mx_b1      = (const float*)d_in[13];
    const float* mx_w2      = (const float*)d_in[14];
    const float* mx_b2      = (const float*)d_in[15];
    const float* lns_g      = (const float*)d_in[16];
    const float* lns_b      = (const float*)d_in[17];
    const float* sw_qkv     = (const float*)d_in[18];
    const float* sb_qkv     = (const float*)d_in[19];
    const float* sw_o       = (const float*)d_in[20];
    const float* sb_o       = (const float*)d_in[21];
    const float* ms_w1      = (const float*)d_in[22];
    const float* ms_b1      = (const float*)d_in[23];
    const float* ms_w2      = (const float*)d_in[24];
    const float* ms_b2      = (const float*)d_in[25];
    const float* lno_g      = (const float*)d_in[26];
    const float* lno_b      = (const float*)d_in[27];
    float* out = (float*)d_out;

    cudaFuncSetAttribute(gemm_mma<3>,   cudaFuncAttributeMaxDynamicSharedMemorySize, GSM);
    cudaFuncSetAttribute(gemm_mma_h<1>, cudaFuncAttributeMaxDynamicSharedMemorySize, GSMH);
    cudaFuncSetAttribute(gemm_mma_h<2>, cudaFuncAttributeMaxDynamicSharedMemorySize, GSMH);
    cudaFuncSetAttribute(gemm_mma_h<3>, cudaFuncAttributeMaxDynamicSharedMemorySize, GSMH);
    cudaFuncSetAttribute(fattn,         cudaFuncAttributeMaxDynamicSharedMemorySize, FA_SMEM);

    float *plat, *ptmpf, *pmask6, *pbc, *pzb;
    __nv_bfloat16 *ptok2, *ptmp2, *phid2, *pat2, *pq2, *pkvall, *psq2, *pwpT, *pwc,
                  *pwxqkv, *pwxo, *pwmx1, *pwmx2, *pwsqkv, *pwso, *pwms1, *pwms2;
    cudaGetSymbolAddress((void**)&plat,   g_lat);
    cudaGetSymbolAddress((void**)&ptmpf,  g_tmpf);
    cudaGetSymbolAddress((void**)&pmask6, g_mask6);
    cudaGetSymbolAddress((void**)&pbc,    g_bc);
    cudaGetSymbolAddress((void**)&pzb,    g_zerob);
    cudaGetSymbolAddress((void**)&ptok2,  g_tok2);
    cudaGetSymbolAddress((void**)&ptmp2,  g_tmp2);
    cudaGetSymbolAddress((void**)&phid2,  g_hid2);
    cudaGetSymbolAddress((void**)&pat2,   g_at2);
    cudaGetSymbolAddress((void**)&pq2,    g_q2);
    cudaGetSymbolAddress((void**)&pkvall, g_kvall2);
    cudaGetSymbolAddress((void**)&psq2,   g_sq2);
    cudaGetSymbolAddress((void**)&pwpT,   g_wpT2);
    cudaGetSymbolAddress((void**)&pwc,    g_wc2);
    cudaGetSymbolAddress((void**)&pwxqkv, g_wxqkv2);
    cudaGetSymbolAddress((void**)&pwxo,   g_wxo2);
    cudaGetSymbolAddress((void**)&pwmx1,  g_wmx1);
    cudaGetSymbolAddress((void**)&pwmx2,  g_wmx2);
    cudaGetSymbolAddress((void**)&pwsqkv, g_wsqkv2);
    cudaGetSymbolAddress((void**)&pwso,   g_wso2);
    cudaGetSymbolAddress((void**)&pwms1,  g_wms1);
    cudaGetSymbolAddress((void**)&pwms2,  g_wms2);

    const int BT = B * T, BL = B * LQ;

    // ---- upfront: splits, folded KV weights/bias, batched KV, masks ----
    split_pair<<<dim3(D / 256,   NB * 3 * D), 256>>>(xw_qkv, pwxqkv, D);
    split_pair<<<dim3(D / 256,   NB * D),     256>>>(xw_o,   pwxo,   D);
    split_pair<<<dim3(D / 256,   NB * HID),   256>>>(mx_w1,  pwmx1,  D);
    split_pair<<<dim3(HID / 256, NB * D),     256>>>(mx_w2,  pwmx2,  HID);
    split_pair<<<dim3(D / 256,   NB * 3 * D), 256>>>(sw_qkv, pwsqkv, D);
    split_pair<<<dim3(D / 256,   NB * D),     256>>>(sw_o,   pwso,   D);
    split_pair<<<dim3(D / 256,   NB * HID),   256>>>(ms_w1,  pwms1,  D);
    split_pair<<<dim3(HID / 256, NB * D),     256>>>(ms_w2,  pwms2,  HID);
    split_pair<<<dim3(D_IN / 256, BT),        256>>>(tokens, ptok2,  D_IN);
    tsplit_proj<<<dim3(D / 256, D_IN), 256>>>(proj_w, pwpT);

    // combined KV weights: Wc_i = Wkv_i @ Wp   (6 small split-GEMMs, exact assoc.)
    for (int i = 0; i < NB; i++)
        gemm_mma_h<3><<<dim3(D_IN / 128, 1024 / 64), 128, GSMH>>>(
            pwxqkv + ((size_t)i * 3 * D + D) * 2 * D, 2 * D,
            pwpT, 2 * D, pzb, nullptr, pwc + (size_t)i * 1024 * 2 * D_IN, D_IN, D);
    kvbias_kernel<<<KVN, 256>>>(xw_qkv, xb_qkv, proj_b, pbc);

    // all 6 blocks' K|V in one GEMM: [B*T, KVN] from tokens, K=256
    gemm_mma<3><<<dim3(KVN / 128, BT / 128), 256, GSM>>>(
        ptok2, 2 * D_IN, pwc, 2 * D_IN, pbc, nullptr, pkvall, KVN, D_IN);

    mask6_kernel<<<dim3(T / 256, LQ, NB), 256>>>(rel_bias, mask_scale, pmask6);
    bcast_latents<<<(BL * D) / 256, 256>>>(latents, plat);

    for (int i = 0; i < NB; i++) {
        const __nv_bfloat16* wq2 = pwxqkv + (size_t)i * 3 * D * 2 * D;
        const float* bqkv = xb_qkv + (size_t)i * 3 * D;

        // ---- cross attention ----
        ln_split<<<BL, 256>>>(plat, lnx_g + i * D, lnx_b + i * D, ptmp2);
        gemm_mma_h<3><<<dim3(D / 128, BL / 64), 128, GSMH>>>(
            ptmp2, 2 * D, wq2, 2 * D, bqkv, nullptr, pq2, D, D);
        fattn<<<dim3(LQ / BQ, B * H), 128, FA_SMEM>>>(
            pq2, 2 * D,
            pkvall + (size_t)i * 1024, 2 * KVN, KVN,       // K of block i
            pkvall + (size_t)i * 1024 + D, 2 * KVN, KVN,   // V of block i
            pmask6 + (size_t)i * LQ * T, pat2, T);
        gemm_mma_h<2><<<dim3(D / 128, BL / 64), 128, GSMH>>>(
            pat2, 2 * D, pwxo + (size_t)i * D * 2 * D, 2 * D, xb_o + i * D, plat, nullptr, D, D);

        // ---- cross MLP (pre-LN reuses lnx params) ----
        ln_split<<<BL, 256>>>(plat, lnx_g + i * D, lnx_b + i * D, ptmp2);
        gemm_mma_h<1><<<dim3(HID / 128, BL / 64), 128, GSMH>>>(
            ptmp2, 2 * D, pwmx1 + (size_t)i * HID * 2 * D, 2 * D, mx_b1 + i * HID,
            nullptr, phid2, HID, D);
        gemm_mma_h<2><<<dim3(D / 128, BL / 64), 128, GSMH>>>(
            phid2, 2 * HID, pwmx2 + (size_t)i * D * 2 * HID, 2 * HID, mx_b2 + i * D,
            plat, nullptr, D, HID);

        // ---- self attention ----
        ln_split<<<BL, 256>>>(plat, lns_g + i * D, lns_b + i * D, ptmp2);
        gemm_mma_h<3><<<dim3((3 * D) / 128, BL / 64), 128, GSMH>>>(
            ptmp2, 2 * D, pwsqkv + (size_t)i * 3 * D * 2 * D, 2 * D,
            sb_qkv + (size_t)i * 3 * D, nullptr, psq2, 3 * D, D);
        fattn<<<dim3(LQ / BQ, B * H), 128, FA_SMEM>>>(
            psq2, 6 * D,
            psq2 + D, 6 * D, 3 * D,
            psq2 + 2 * D, 6 * D, 3 * D,
            nullptr, pat2, LQ);
        gemm_mma_h<2><<<dim3(D / 128, BL / 64), 128, GSMH>>>(
            pat2, 2 * D, pwso + (size_t)i * D * 2 * D, 2 * D, sb_o + i * D, plat, nullptr, D, D);

        // ---- self MLP ----
        ln_split<<<BL, 256>>>(plat, lns_g + i * D, lns_b + i * D, ptmp2);
        gemm_mma_h<1><<<dim3(HID / 128, BL / 64), 128, GSMH>>>(
            ptmp2, 2 * D, pwms1 + (size_t)i * HID * 2 * D, 2 * D, ms_b1 + i * HID,
            nullptr, phid2, HID, D);
        gemm_mma_h<2><<<dim3(D / 128, BL / 64), 128, GSMH>>>(
            phid2, 2 * HID, pwms2 + (size_t)i * D * 2 * HID, 2 * HID, ms_b2 + i * D,
            plat, nullptr, D, HID);
    }

    // final LN + mean over latents
    ln_kernel<<<BL, 256>>>(plat, lno_g, lno_b, ptmpf);
    mean_kernel<<<(B * D) / 256, 256>>>(ptmpf, out);
}

// round 7
// speedup vs baseline: 3.7233x; 1.0189x over previous
#include <cuda_runtime.h>
#include <cuda_bf16.h>
#include <cuda_fp16.h>
#include <cstdint>
#include <math.h>

// ---------------- problem constants ----------------
#define B   8
#define T   4096
#define D_IN 256
#define D   512
#define LQ  256
#define H   8
#define HD  64
#define NB  6
#define HID 2048
#define KVN (NB * 2 * D)          // 6144 combined KV rows in wc

// ---------------- mma.sync helpers (sm_80+ PTX; no tcgen05) ----------------
__device__ __forceinline__ uint32_t smem_u32(const void* p) {
    uint32_t a;
    asm("{ .reg .u64 t; cvta.to.shared.u64 t, %1; cvt.u32.u64 %0, t; }" : "=r"(a) : "l"(p));
    return a;
}
__device__ __forceinline__ void cp16(uint32_t dst, const void* src) {
    asm volatile("cp.async.cg.shared.global [%0], [%1], 16;\n" :: "r"(dst), "l"(src));
}
__device__ __forceinline__ void ldsm4(uint32_t& r0, uint32_t& r1, uint32_t& r2, uint32_t& r3,
                                      uint32_t addr) {
    asm volatile("ldmatrix.sync.aligned.m8n8.x4.shared.b16 {%0,%1,%2,%3}, [%4];"
        : "=r"(r0), "=r"(r1), "=r"(r2), "=r"(r3) : "r"(addr));
}
__device__ __forceinline__ void ldsm4t(uint32_t& r0, uint32_t& r1, uint32_t& r2, uint32_t& r3,
                                       uint32_t addr) {
    asm volatile("ldmatrix.sync.aligned.m8n8.x4.trans.shared.b16 {%0,%1,%2,%3}, [%4];"
        : "=r"(r0), "=r"(r1), "=r"(r2), "=r"(r3) : "r"(addr));
}
__device__ __forceinline__ void mma16816(float* c, const uint32_t* a, uint32_t b0, uint32_t b1) {
    asm volatile("mma.sync.aligned.m16n8k16.row.col.f32.bf16.bf16.f32 "
        "{%0,%1,%2,%3}, {%4,%5,%6,%7}, {%8,%9}, {%0,%1,%2,%3};"
        : "+f"(c[0]), "+f"(c[1]), "+f"(c[2]), "+f"(c[3])
        : "r"(a[0]), "r"(a[1]), "r"(a[2]), "r"(a[3]), "r"(b0), "r"(b1));
}
__device__ __forceinline__ void mma16816h(float* c, const uint32_t* a, uint32_t b0, uint32_t b1) {
    asm volatile("mma.sync.aligned.m16n8k16.row.col.f32.f16.f16.f32 "
        "{%0,%1,%2,%3}, {%4,%5,%6,%7}, {%8,%9}, {%0,%1,%2,%3};"
        : "+f"(c[0]), "+f"(c[1]), "+f"(c[2]), "+f"(c[3])
        : "r"(a[0]), "r"(a[1]), "r"(a[2]), "r"(a[3]), "r"(b0), "r"(b1));
}
// pack two fp32 logits -> f16x2, one MUFU ex2 for both probs (low = tlo)
__device__ __forceinline__ uint32_t packex2h2(float tlo, float thi) {
    uint32_t t, r;
    asm("cvt.rn.f16x2.f32 %0, %1, %2;" : "=r"(t) : "f"(thi), "f"(tlo));
    asm("ex2.approx.f16x2 %0, %1;" : "=r"(r) : "r"(t));
    return r;
}

// ---------------- scratch (static device globals; no allocation) ----------------
__device__ float g_lat [B*LQ*D];
__device__ float g_tmpf[B*LQ*D];
__device__ float g_mask6[NB*LQ*T];
__device__ float g_bc  [KVN];
__device__ float g_zerob[D_IN];

__device__ __align__(256) __nv_bfloat16 g_tok2 [B*T*2*D_IN];
__device__ __align__(256) __nv_bfloat16 g_tmp2 [B*LQ*2*D];
__device__ __align__(256) __nv_bfloat16 g_hid2 [B*LQ*2*HID];
__device__ __align__(256) __nv_bfloat16 g_at2  [B*LQ*2*D];
__device__ __align__(256) __nv_bfloat16 g_q2   [B*LQ*2*D];
__device__ __align__(256) __nv_bfloat16 g_kall2[(size_t)B*T*2*(NB*D)];  // all-blocks K split (402MB)
__device__ __align__(256) __half        g_vallh[(size_t)B*T*(NB*D)];    // all-blocks V fp16 (201MB)
__device__ __align__(256) __nv_bfloat16 g_sq2  [B*LQ*2*(3*D)];
__device__ __align__(256) __half        g_sqh  [B*LQ*(3*D)];
__device__ __align__(256) __nv_bfloat16 g_wpT2 [D_IN*2*D];
__device__ __align__(256) __nv_bfloat16 g_wc2  [KVN*2*D_IN];            // [Kall(3072) | Vall(3072)]
__device__ __align__(256) __nv_bfloat16 g_wxqkv2[NB*3*D*2*D];
__device__ __align__(256) __nv_bfloat16 g_wxo2  [NB*D*2*D];
__device__ __align__(256) __nv_bfloat16 g_wmx1  [NB*HID*2*D];
__device__ __align__(256) __nv_bfloat16 g_wmx2  [NB*D*2*HID];
__device__ __align__(256) __nv_bfloat16 g_wsqkv2[NB*3*D*2*D];
__device__ __align__(256) __nv_bfloat16 g_wso2  [NB*D*2*D];
__device__ __align__(256) __nv_bfloat16 g_wms1  [NB*HID*2*D];
__device__ __align__(256) __nv_bfloat16 g_wms2  [NB*D*2*HID];

__device__ __forceinline__ void split2(float x, __nv_bfloat16& h, __nv_bfloat16& l) {
    h = __float2bfloat16(x);
    l = __float2bfloat16(x - __bfloat162float(h));
}

// ---------------- reductions ----------------
__device__ __forceinline__ float block_sum256(float v, float* sh) {
    #pragma unroll
    for (int o = 16; o; o >>= 1) v += __shfl_xor_sync(0xffffffffu, v, o);
    if ((threadIdx.x & 31) == 0) sh[threadIdx.x >> 5] = v;
    __syncthreads();
    float t = (threadIdx.x < 8) ? sh[threadIdx.x] : 0.f;
    if (threadIdx.x < 32) {
        #pragma unroll
        for (int o = 4; o; o >>= 1) t += __shfl_xor_sync(0xffffffffu, t, o);
        if (threadIdx.x == 0) sh[0] = t;
    }
    __syncthreads();
    float r = sh[0];
    __syncthreads();
    return r;
}

// ================= tensor-core GEMM (HMMA): C = A·W^T + bias =================
// A2 [M, 2K] = [hi | lo] bf16, W2 [N, 2K] likewise. 3 K-passes (hh, hl, lh).
// EPI: 1 = gelu->split C2   2 = res(inplace fp32 C)   3 = split C2
//      4 = split C2 + fp16 shadow C3   5 = fp16 C3 only
#define BK 32
#define AST 40
#define STG (128 * AST * 2)
#define NSTAGE 4
#define GSM (NSTAGE * 2 * STG)

template<int EPI>
__global__ __launch_bounds__(256)
void gemm_mma(const __nv_bfloat16* __restrict__ A2, int ldA,
              const __nv_bfloat16* __restrict__ W2, int ldW,
              const float* __restrict__ bias,
              float* __restrict__ C, __nv_bfloat16* __restrict__ C2,
              __half* __restrict__ C3, int N, int K)
{
    extern __shared__ __align__(256) char smraw[];
    const uint32_t base = smem_u32(smraw);
    const int tid = threadIdx.x;
    const int bm = blockIdx.y * 128, bn = blockIdx.x * 128;
    const int lane = tid & 31, warp = tid >> 5;
    const int wm = warp & 3, wn = warp >> 2;

    const int nkc = K / BK;
    const int nch = 3 * nkc;

    float acc[2][8][4];
    #pragma unroll
    for (int i = 0; i < 2; i++)
        #pragma unroll
        for (int j = 0; j < 8; j++)
            #pragma unroll
            for (int k = 0; k < 4; k++) acc[i][j][k] = 0.f;

    auto issue_load = [&](int i, int st) {
        int s = i / nkc, kc = i - s * nkc;
        int ao = ((s == 2) ? K : 0) + kc * BK;
        int wo = ((s == 1) ? K : 0) + kc * BK;
        uint32_t smA = base + st * (2 * STG);
        uint32_t smB = smA + STG;
        const __nv_bfloat16* As = A2 + (size_t)bm * ldA + ao;
        const __nv_bfloat16* Ws = W2 + (size_t)bn * ldW + wo;
        #pragma unroll
        for (int j = 0; j < 2; j++) {
            int u = j * 256 + tid;
            int r = u >> 2, cc = (u & 3) * 8;
            cp16(smA + (uint32_t)(r * AST + cc) * 2, As + (size_t)r * ldA + cc);
            cp16(smB + (uint32_t)(r * AST + cc) * 2, Ws + (size_t)r * ldW + cc);
        }
        asm volatile("cp.async.commit_group;\n" ::: "memory");
    };

    const int arow = wm * 32 + ((lane >> 3) & 1) * 8 + (lane & 7);
    const int akof = ((lane >> 4) & 1) * 8;
    const int brow = wn * 64 + ((lane >> 4) & 1) * 8 + (lane & 7);
    const int bkof = ((lane >> 3) & 1) * 8;

    #pragma unroll
    for (int s = 0; s < NSTAGE - 1; s++) issue_load(s, s);

    for (int i = 0; i < nch; i++) {
        int rem = nch - 1 - i;
        if (rem >= 2)      asm volatile("cp.async.wait_group 2;\n" ::: "memory");
        else if (rem == 1) asm volatile("cp.async.wait_group 1;\n" ::: "memory");
        else               asm volatile("cp.async.wait_group 0;\n" ::: "memory");
        __syncthreads();
        if (i + NSTAGE - 1 < nch) issue_load(i + NSTAGE - 1, (i + NSTAGE - 1) % NSTAGE);

        uint32_t smA = base + (i % NSTAGE) * (2 * STG);
        uint32_t smB = smA + STG;
        #pragma unroll
        for (int kk = 0; kk < 2; kk++) {
            const int k0 = kk * 16;
            uint32_t a[2][4], b[4][4];
            #pragma unroll
            for (int fm = 0; fm < 2; fm++)
                ldsm4(a[fm][0], a[fm][1], a[fm][2], a[fm][3],
                      smA + (uint32_t)((arow + fm * 16) * AST + k0 + akof) * 2);
            #pragma unroll
            for (int fb = 0; fb < 4; fb++)
                ldsm4(b[fb][0], b[fb][1], b[fb][2], b[fb][3],
                      smB + (uint32_t)((brow + fb * 16) * AST + k0 + bkof) * 2);
            #pragma unroll
            for (int fm = 0; fm < 2; fm++)
                #pragma unroll
                for (int fn = 0; fn < 8; fn++)
                    mma16816(acc[fm][fn], a[fm], b[fn >> 1][(fn & 1) * 2],
                             b[fn >> 1][(fn & 1) * 2 + 1]);
        }
    }

    const int lr = lane >> 2, lc = (lane & 3) * 2;
    #pragma unroll
    for (int fm = 0; fm < 2; fm++) {
        #pragma unroll
        for (int fn = 0; fn < 8; fn++) {
            float* cc = acc[fm][fn];
            int m0 = bm + wm * 32 + fm * 16 + lr;
            int n0 = bn + wn * 64 + fn * 8 + lc;
            float b0 = bias[n0], b1 = bias[n0 + 1];
            float v00 = cc[0] + b0, v01 = cc[1] + b1;
            float v10 = cc[2] + b0, v11 = cc[3] + b1;
            if (EPI == 1) {
                v00 = 0.5f * v00 * (1.0f + erff(v00 * 0.70710678118654752f));
                v01 = 0.5f * v01 * (1.0f + erff(v01 * 0.70710678118654752f));
                v10 = 0.5f * v10 * (1.0f + erff(v10 * 0.70710678118654752f));
                v11 = 0.5f * v11 * (1.0f + erff(v11 * 0.70710678118654752f));
            }
            if (EPI == 2) {
                float2 r0 = *(const float2*)&C[(size_t)m0 * N + n0];
                float2 r1 = *(const float2*)&C[(size_t)(m0 + 8) * N + n0];
                *(float2*)&C[(size_t)m0 * N + n0]       = make_float2(v00 + r0.x, v01 + r0.y);
                *(float2*)&C[(size_t)(m0 + 8) * N + n0] = make_float2(v10 + r1.x, v11 + r1.y);
            } else if (EPI == 5) {
                *(half2*)&C3[(size_t)m0 * N + n0]       = __floats2half2_rn(v00, v01);
                *(half2*)&C3[(size_t)(m0 + 8) * N + n0] = __floats2half2_rn(v10, v11);
            } else {
                __nv_bfloat16 h0, l0, h1, l1;
                split2(v00, h0, l0); split2(v01, h1, l1);
                *(__nv_bfloat162*)&C2[(size_t)m0 * 2 * N + n0]     = __nv_bfloat162(h0, h1);
                *(__nv_bfloat162*)&C2[(size_t)m0 * 2 * N + N + n0] = __nv_bfloat162(l0, l1);
                split2(v10, h0, l0); split2(v11, h1, l1);
                *(__nv_bfloat162*)&C2[(size_t)(m0 + 8) * 2 * N + n0]     = __nv_bfloat162(h0, h1);
                *(__nv_bfloat162*)&C2[(size_t)(m0 + 8) * 2 * N + N + n0] = __nv_bfloat162(l0, l1);
                if (EPI == 4) {
                    *(half2*)&C3[(size_t)m0 * N + n0]       = __floats2half2_rn(v00, v01);
                    *(half2*)&C3[(size_t)(m0 + 8) * N + n0] = __floats2half2_rn(v10, v11);
                }
            }
        }
    }
}

// ---------- 64x128-tile variant (128 threads) ----------
#define ASTGH (64 * AST * 2)
#define BSTGH (128 * AST * 2)
#define GSMH (NSTAGE * (ASTGH + BSTGH))

template<int EPI>
__global__ __launch_bounds__(128)
void gemm_mma_h(const __nv_bfloat16* __restrict__ A2, int ldA,
                const __nv_bfloat16* __restrict__ W2, int ldW,
                const float* __restrict__ bias,
                float* __restrict__ C, __nv_bfloat16* __restrict__ C2,
                __half* __restrict__ C3, int N, int K)
{
    extern __shared__ __align__(256) char smraw[];
    const uint32_t base = smem_u32(smraw);
    const int tid = threadIdx.x;
    const int bm = blockIdx.y * 64, bn = blockIdx.x * 128;
    const int lane = tid & 31, warp = tid >> 5;
    const int wm = warp & 1, wn = warp >> 1;

    const int nkc = K / BK;
    const int nch = 3 * nkc;

    float acc[2][8][4];
    #pragma unroll
    for (int i = 0; i < 2; i++)
        #pragma unroll
        for (int j = 0; j < 8; j++)
            #pragma unroll
            for (int k = 0; k < 4; k++) acc[i][j][k] = 0.f;

    auto issue_load = [&](int i, int st) {
        int s = i / nkc, kc = i - s * nkc;
        int ao = ((s == 2) ? K : 0) + kc * BK;
        int wo = ((s == 1) ? K : 0) + kc * BK;
        uint32_t smA = base + st * (ASTGH + BSTGH);
        uint32_t smB = smA + ASTGH;
        const __nv_bfloat16* As = A2 + (size_t)bm * ldA + ao;
        const __nv_bfloat16* Ws = W2 + (size_t)bn * ldW + wo;
        #pragma unroll
        for (int j = 0; j < 2; j++) {
            int u = j * 128 + tid;
            int r = u >> 2, cc = (u & 3) * 8;
            cp16(smA + (uint32_t)(r * AST + cc) * 2, As + (size_t)r * ldA + cc);
        }
        #pragma unroll
        for (int j = 0; j < 4; j++) {
            int u = j * 128 + tid;
            int r = u >> 2, cc = (u & 3) * 8;
            cp16(smB + (uint32_t)(r * AST + cc) * 2, Ws + (size_t)r * ldW + cc);
        }
        asm volatile("cp.async.commit_group;\n" ::: "memory");
    };

    const int arow = wm * 32 + ((lane >> 3) & 1) * 8 + (lane & 7);
    const int akof = ((lane >> 4) & 1) * 8;
    const int brow = wn * 64 + ((lane >> 4) & 1) * 8 + (lane & 7);
    const int bkof = ((lane >> 3) & 1) * 8;

    #pragma unroll
    for (int s = 0; s < NSTAGE - 1; s++) issue_load(s, s);

    for (int i = 0; i < nch; i++) {
        int rem = nch - 1 - i;
        if (rem >= 2)      asm volatile("cp.async.wait_group 2;\n" ::: "memory");
        else if (rem == 1) asm volatile("cp.async.wait_group 1;\n" ::: "memory");
        else               asm volatile("cp.async.wait_group 0;\n" ::: "memory");
        __syncthreads();
        if (i + NSTAGE - 1 < nch) issue_load(i + NSTAGE - 1, (i + NSTAGE - 1) % NSTAGE);

        uint32_t smA = base + (i % NSTAGE) * (ASTGH + BSTGH);
        uint32_t smB = smA + ASTGH;
        #pragma unroll
        for (int kk = 0; kk < 2; kk++) {
            const int k0 = kk * 16;
            uint32_t a[2][4], b[4][4];
            #pragma unroll
            for (int fm = 0; fm < 2; fm++)
                ldsm4(a[fm][0], a[fm][1], a[fm][2], a[fm][3],
                      smA + (uint32_t)((arow + fm * 16) * AST + k0 + akof) * 2);
            #pragma unroll
            for (int fb = 0; fb < 4; fb++)
                ldsm4(b[fb][0], b[fb][1], b[fb][2], b[fb][3],
                      smB + (uint32_t)((brow + fb * 16) * AST + k0 + bkof) * 2);
            #pragma unroll
            for (int fm = 0; fm < 2; fm++)
                #pragma unroll
                for (int fn = 0; fn < 8; fn++)
                    mma16816(acc[fm][fn], a[fm], b[fn >> 1][(fn & 1) * 2],
                             b[fn >> 1][(fn & 1) * 2 + 1]);
        }
    }

    const int lr = lane >> 2, lc = (lane & 3) * 2;
    #pragma unroll
    for (int fm = 0; fm < 2; fm++) {
        #pragma unroll
        for (int fn = 0; fn < 8; fn++) {
            float* cc = acc[fm][fn];
            int m0 = bm + wm * 32 + fm * 16 + lr;
            int n0 = bn + wn * 64 + fn * 8 + lc;
            float b0 = bias[n0], b1 = bias[n0 + 1];
            float v00 = cc[0] + b0, v01 = cc[1] + b1;
            float v10 = cc[2] + b0, v11 = cc[3] + b1;
            if (EPI == 1) {
                v00 = 0.5f * v00 * (1.0f + erff(v00 * 0.70710678118654752f));
                v01 = 0.5f * v01 * (1.0f + erff(v01 * 0.70710678118654752f));
                v10 = 0.5f * v10 * (1.0f + erff(v10 * 0.70710678118654752f));
                v11 = 0.5f * v11 * (1.0f + erff(v11 * 0.70710678118654752f));
            }
            if (EPI == 2) {
                float2 r0 = *(const float2*)&C[(size_t)m0 * N + n0];
                float2 r1 = *(const float2*)&C[(size_t)(m0 + 8) * N + n0];
                *(float2*)&C[(size_t)m0 * N + n0]       = make_float2(v00 + r0.x, v01 + r0.y);
                *(float2*)&C[(size_t)(m0 + 8) * N + n0] = make_float2(v10 + r1.x, v11 + r1.y);
            } else if (EPI == 5) {
                *(half2*)&C3[(size_t)m0 * N + n0]       = __floats2half2_rn(v00, v01);
                *(half2*)&C3[(size_t)(m0 + 8) * N + n0] = __floats2half2_rn(v10, v11);
            } else {
                __nv_bfloat16 h0, l0, h1, l1;
                split2(v00, h0, l0); split2(v01, h1, l1);
                *(__nv_bfloat162*)&C2[(size_t)m0 * 2 * N + n0]     = __nv_bfloat162(h0, h1);
                *(__nv_bfloat162*)&C2[(size_t)m0 * 2 * N + N + n0] = __nv_bfloat162(l0, l1);
                split2(v10, h0, l0); split2(v11, h1, l1);
                *(__nv_bfloat162*)&C2[(size_t)(m0 + 8) * 2 * N + n0]     = __nv_bfloat162(h0, h1);
                *(__nv_bfloat162*)&C2[(size_t)(m0 + 8) * 2 * N + N + n0] = __nv_bfloat162(l0, l1);
                if (EPI == 4) {
                    *(half2*)&C3[(size_t)m0 * N + n0]       = __floats2half2_rn(v00, v01);
                    *(half2*)&C3[(size_t)(m0 + 8) * N + n0] = __floats2half2_rn(v10, v11);
                }
            }
        }
    }
}

// ================= fused flash attention =================
// Q/K split bf16 (2-pass QK); P,V fp16 single-pass PV via ex2.approx.f16x2;
// row sums via ones-column mma. 64 q rows/block, 64-key chunks, double-buffered.
#define BQ 64
#define BKC 64
#define QST 72
#define FTILE (64 * QST * 2)          // 9216 B
#define FSTG (3 * FTILE)              // Kh, Kl, V(fp16 w/ ones cols)
#define FA_SMEM (FTILE + 2 * FSTG + 64)

__global__ __launch_bounds__(128)
void fattn(const __nv_bfloat16* __restrict__ Qp, int ldq,
           const __nv_bfloat16* __restrict__ Kp, int ldk, int ok,
           const __half* __restrict__ Vh, int ldv,
           const float* __restrict__ pm, __nv_bfloat16* __restrict__ O2, int Tk)
{
    extern __shared__ __align__(256) char smraw[];
    const uint32_t base = smem_u32(smraw);
    const int tid = threadIdx.x, lane = tid & 31, warp = tid >> 5;
    const int bh = (int)blockIdx.y, b = bh >> 3, h = bh & 7;
    const int q0 = (int)blockIdx.x * BQ;

    const __nv_bfloat16* Qb = Qp + (size_t)(b * LQ + q0) * ldq + h * HD;
    const __nv_bfloat16* Kb = Kp + (size_t)b * Tk * ldk + h * HD;
    const __half* Vb = Vh + (size_t)b * Tk * ldv + h * HD;

    // Q hi tile -> smem
    #pragma unroll
    for (int j = 0; j < 4; j++) {
        int u = j * 128 + tid, r = u >> 3, c8 = (u & 7) * 8;
        cp16(base + (uint32_t)(r * QST + c8) * 2, Qb + (size_t)r * ldq + c8);
    }
    asm volatile("cp.async.commit_group;\n" ::: "memory");

    // ones columns (64..71) in both stages' V tiles (cp.async only writes 0..63)
    {
        int r = tid >> 1, cq = (tid & 1) * 4;
        #pragma unroll
        for (int st = 0; st < 2; st++) {
            size_t off = (size_t)FTILE + (size_t)st * FSTG + 2 * FTILE
                       + (size_t)(r * QST + 64 + cq) * 2;
            *(uint2*)(smraw + off) = make_uint2(0x3C003C00u, 0x3C003C00u);
        }
    }

    const int nc = Tk / BKC;
    auto load_chunk = [&](int ci, int st) {
        uint32_t sb = base + FTILE + st * FSTG;
        const __nv_bfloat16* Kc = Kb + (size_t)ci * BKC * ldk;
        const __half* Vc = Vb + (size_t)ci * BKC * ldv;
        #pragma unroll
        for (int j = 0; j < 4; j++) {
            int u = j * 128 + tid, r = u >> 3, c8 = (u & 7) * 8;
            uint32_t off = (uint32_t)(r * QST + c8) * 2;
            cp16(sb + off,             Kc + (size_t)r * ldk + c8);
            cp16(sb + FTILE + off,     Kc + (size_t)r * ldk + ok + c8);
            cp16(sb + 2 * FTILE + off, Vc + (size_t)r * ldv + c8);
        }
        asm volatile("cp.async.commit_group;\n" ::: "memory");
    };

    load_chunk(0, 0);
    asm volatile("cp.async.wait_group 1;\n" ::: "memory");   // Q ready
    __syncthreads();

    const int qrow = warp * 16 + ((lane >> 3) & 1) * 8 + (lane & 7);
    const int qko  = ((lane >> 4) & 1) * 8;
    uint32_t qf[4][4];
    #pragma unroll
    for (int ds = 0; ds < 4; ds++)
        ldsm4(qf[ds][0], qf[ds][1], qf[ds][2], qf[ds][3],
              base + (uint32_t)(qrow * QST + ds * 16 + qko) * 2);

    load_chunk(1, 1);

    float o[8][4], osum[4];
    #pragma unroll
    for (int i = 0; i < 8; i++)
        #pragma unroll
        for (int j = 0; j < 4; j++) o[i][j] = 0.f;
    #pragma unroll
    for (int j = 0; j < 4; j++) osum[j] = 0.f;

    const float SC  = 0.125f * 1.44269504088896f;
    const float L2E = 1.44269504088896f;
    const int lr = lane >> 2, lc = (lane & 3) * 2;
    const int krow = ((lane >> 4) & 1) * 8 + (lane & 7);
    const int kko  = ((lane >> 3) & 1) * 8;
    const int vrow = lane & 15;
    const int vco  = ((lane >> 4) & 1) * 8;
    const int qr_g = q0 + warp * 16 + lr;

    for (int ci = 0; ci < nc; ci++) {
        if (ci == nc - 1) asm volatile("cp.async.wait_group 0;\n" ::: "memory");
        else              asm volatile("cp.async.wait_group 1;\n" ::: "memory");
        __syncthreads();

        uint32_t sb = base + FTILE + (ci & 1) * FSTG;

        // ---- S = Q·K^T (2 split passes) ----
        float s[8][4];
        #pragma unroll
        for (int i = 0; i < 8; i++)
            #pragma unroll
            for (int j = 0; j < 4; j++) s[i][j] = 0.f;
        #pragma unroll
        for (int ps = 0; ps < 2; ps++) {
            const uint32_t kb = sb + ((ps == 1) ? FTILE : 0);
            #pragma unroll
            for (int ds = 0; ds < 4; ds++) {
                #pragma unroll
                for (int g = 0; g < 4; g++) {
                    uint32_t b0, b1, b2, b3;
                    ldsm4(b0, b1, b2, b3,
                          kb + (uint32_t)((g * 16 + krow) * QST + ds * 16 + kko) * 2);
                    mma16816(s[2 * g],     qf[ds], b0, b1);
                    mma16816(s[2 * g + 1], qf[ds], b2, b3);
                }
            }
        }

        // ---- probs as fp16 fragments (one ex2.f16x2 per pair) ----
        uint32_t ph[4][4];
        #pragma unroll
        for (int nt = 0; nt < 8; nt++) {
            float t0 = s[nt][0] * SC, t1 = s[nt][1] * SC;
            float t2 = s[nt][2] * SC, t3 = s[nt][3] * SC;
            if (pm) {
                const float* pmr = pm + (size_t)qr_g * Tk + ci * BKC + nt * 8 + lc;
                float2 m0 = *(const float2*)pmr;
                float2 m1 = *(const float2*)(pmr + (size_t)8 * Tk);
                t0 = fmaf(m0.x, L2E, t0); t1 = fmaf(m0.y, L2E, t1);
                t2 = fmaf(m1.x, L2E, t2); t3 = fmaf(m1.y, L2E, t3);
            }
            int j = nt >> 1, qi = (nt & 1) * 2;
            ph[j][qi]     = packex2h2(t0, t1);
            ph[j][qi + 1] = packex2h2(t2, t3);
        }

        // ---- O += P·V (single fp16 pass) + row sums via ones columns ----
        uint32_t vb = sb + 2 * FTILE;
        #pragma unroll
        for (int ks = 0; ks < 4; ks++) {
            const uint32_t* pf = ph[ks];
            #pragma unroll
            for (int g = 0; g < 4; g++) {
                uint32_t b0, b1, b2, b3;
                ldsm4t(b0, b1, b2, b3,
                       vb + (uint32_t)((ks * 16 + vrow) * QST + g * 16 + vco) * 2);
                mma16816h(o[2 * g],     pf, b0, b1);
                mma16816h(o[2 * g + 1], pf, b2, b3);
            }
            {
                uint32_t b0, b1, b2, b3;
                ldsm4t(b0, b1, b2, b3,
                       vb + (uint32_t)((ks * 16 + vrow) * QST + 64 + vco) * 2);
                mma16816h(osum, pf, b0, b1);   // b2,b3 (wrapped cols) unused
            }
        }

        __syncthreads();
        if (ci + 2 < nc) load_chunk(ci + 2, ci & 1);
    }

    float inv0 = 1.0f / osum[0], inv1 = 1.0f / osum[2];

    const size_t row0 = (size_t)(b * LQ + qr_g);
    #pragma unroll
    for (int nt = 0; nt < 8; nt++) {
        int col = h * HD + nt * 8 + lc;
        float v0 = o[nt][0] * inv0, v1 = o[nt][1] * inv0;
        float v2 = o[nt][2] * inv1, v3 = o[nt][3] * inv1;
        __nv_bfloat16 h0, l0, h1, l1;
        split2(v0, h0, l0); split2(v1, h1, l1);
        *(__nv_bfloat162*)&O2[row0 * 2 * D + col]     = __nv_bfloat162(h0, h1);
        *(__nv_bfloat162*)&O2[row0 * 2 * D + D + col] = __nv_bfloat162(l0, l1);
        split2(v2, h0, l0); split2(v3, h1, l1);
        *(__nv_bfloat162*)&O2[(row0 + 8) * 2 * D + col]     = __nv_bfloat162(h0, h1);
        *(__nv_bfloat162*)&O2[(row0 + 8) * 2 * D + D + col] = __nv_bfloat162(l0, l1);
    }
}

// ---------------- elementwise split ----------------
__global__ void split_pair(const float* __restrict__ src, __nv_bfloat16* __restrict__ dst, int K)
{
    int c = blockIdx.x * 256 + threadIdx.x;
    int r = blockIdx.y;
    float x = src[(size_t)r * K + c];
    __nv_bfloat16 h, l; split2(x, h, l);
    dst[(size_t)r * 2 * K + c] = h;
    dst[(size_t)r * 2 * K + K + c] = l;
}

// -------- transpose+split: proj_w[D, D_IN] -> wT2[D_IN, 2*D] --------
__global__ void tsplit_proj(const float* __restrict__ pw, __nv_bfloat16* __restrict__ wT2)
{
    int k = blockIdx.x * 256 + threadIdx.x;
    int c = blockIdx.y;
    float x = pw[(size_t)k * D_IN + c];
    __nv_bfloat16 h, l; split2(x, h, l);
    wT2[(size_t)c * 2 * D + k] = h;
    wT2[(size_t)c * 2 * D + D + k] = l;
}

// -------- folded KV bias for rearranged [Kall | Vall] layout --------
__global__ void kvbias_kernel(const float* __restrict__ xw_qkv, const float* __restrict__ xb_qkv,
                              const float* __restrict__ proj_b, float* __restrict__ bc)
{
    __shared__ float sh[32];
    int g = blockIdx.x;                 // [0, 6144)
    int wrow;
    if (g < 3072) { int i = g >> 9, n = g & 511; wrow = i * 3 * D + D + n; }
    else          { int gg = g - 3072; int i = gg >> 9, n = gg & 511; wrow = i * 3 * D + 2 * D + n; }
    const float* wr = xw_qkv + (size_t)wrow * D;
    float s = 0.f;
    for (int k = threadIdx.x; k < D; k += 256) s += wr[k] * proj_b[k];
    float tot = block_sum256(s, sh);
    if (threadIdx.x == 0) bc[g] = tot + xb_qkv[wrow];
}

// ---------------- LayerNorm -> split bf16 ----------------
__global__ void ln_split(const float* __restrict__ x, const float* __restrict__ g,
                         const float* __restrict__ b, __nv_bfloat16* __restrict__ y2)
{
    __shared__ float sh[32];
    const int row = blockIdx.x, tid = threadIdx.x;
    const float* xr = x + (size_t)row * D;
    float2 v = *(const float2*)&xr[tid * 2];
    float total = block_sum256(v.x + v.y, sh);
    float mean = total * (1.0f / D);
    float d0 = v.x - mean, d1 = v.y - mean;
    float sq = block_sum256(d0 * d0 + d1 * d1, sh);
    float inv = rsqrtf(sq * (1.0f / D) + 1e-5f);
    float2 go = *(const float2*)&g[tid * 2];
    float2 bo = *(const float2*)&b[tid * 2];
    float o0 = d0 * inv * go.x + bo.x;
    float o1 = d1 * inv * go.y + bo.y;
    __nv_bfloat16 h0, l0, h1, l1;
    split2(o0, h0, l0); split2(o1, h1, l1);
    __nv_bfloat16* dst = y2 + (size_t)row * 2 * D;
    ((__nv_bfloat162*)dst)[tid] = __nv_bfloat162(h0, h1);
    ((__nv_bfloat162*)(dst + D))[tid] = __nv_bfloat162(l0, l1);
}

// ---------------- plain LayerNorm (final) ----------------
__global__ void ln_kernel(const float* __restrict__ x, const float* __restrict__ g,
                          const float* __restrict__ b, float* __restrict__ y)
{
    __shared__ float sh[32];
    const int row = blockIdx.x, tid = threadIdx.x;
    const float* xr = x + (size_t)row * D;
    float2 v = *(const float2*)&xr[tid * 2];
    float total = block_sum256(v.x + v.y, sh);
    float mean = total * (1.0f / D);
    float d0 = v.x - mean, d1 = v.y - mean;
    float sq = block_sum256(d0 * d0 + d1 * d1, sh);
    float inv = rsqrtf(sq * (1.0f / D) + 1e-5f);
    float2 go = *(const float2*)&g[tid * 2];
    float2 bo = *(const float2*)&b[tid * 2];
    float2 o;
    o.x = d0 * inv * go.x + bo.x;
    o.y = d1 * inv * go.y + bo.y;
    *(float2*)&y[(size_t)row * D + tid * 2] = o;
}

// ---------------- all 6 relative-time masks ----------------
__global__ void mask6_kernel(const float* __restrict__ rel_bias, const float* __restrict__ ms,
                             float* __restrict__ pm6)
{
    int k = blockIdx.x * 256 + threadIdx.x;
    int q = blockIdx.y;
    int z = blockIdx.z;
    float tau = (float)q * (4095.0f / 255.0f);
    float dt = (float)k - tau;
    float c = fminf(fmaxf(dt, -128.f), 128.f);
    int idx = (int)c + 128;
    float zz = dt * (1.0f / 32.0f);
    float lg = logf(expf(-0.5f * zz * zz) + 1e-6f);
    pm6[(size_t)z * LQ * T + (size_t)q * T + k] = ms[z] * (rel_bias[z * 257 + idx] + lg);
}

// ---------------- misc ----------------
__global__ void bcast_latents(const float* __restrict__ src, float* __restrict__ dst)
{
    int i = blockIdx.x * 256 + threadIdx.x;
    dst[i] = src[i % (LQ * D)];
}

__global__ void mean_kernel(const float* __restrict__ x, float* __restrict__ out)
{
    int i = blockIdx.x * 256 + threadIdx.x;
    int b = i / D, d = i % D;
    float s = 0.f;
    for (int q = 0; q < LQ; q++) s += x[((size_t)b * LQ + q) * D + d];
    out[i] = s * (1.0f / LQ);
}

// ---------------- host orchestration ----------------
extern "C" void kernel_launch(void* const* d_in, const int* in_sizes, int n_in,
                              void* d_out, int out_size)
{
    (void)in_sizes; (void)n_in; (void)out_size;
    const float* tokens     = (const float*)d_in[0];
    const float* proj_w     = (const float*)d_in[1];
    const float* proj_b     = (const float*)d_in[2];
    const float* latents    = (const float*)d_in[3];
    const float* lnx_g      = (const float*)d_in[4];
    const float* lnx_b      = (const float*)d_in[5];
    const float* xw_qkv     = (const float*)d_in[6];
    const float* xb_qkv     = (const float*)d_in[7];
    const float* xw_o       = (const float*)d_in[8];
    const float* xb_o       = (const float*)d_in[9];
    const float* rel_bias   = (const float*)d_in[10];
    const float* mask_scale = (const float*)d_in[11];
    const float* mx_w1      = (const float*)d_in[12];
    const float* mx_b1      = (const float*)d_in[13];
    const float* mx_w2      = (const float*)d_in[14];
    const float* mx_b2      = (const float*)d_in[15];
    const float* lns_g      = (const float*)d_in[16];
    const float* lns_b      = (const float*)d_in[17];
    const float* sw_qkv     = (const float*)d_in[18];
    const float* sb_qkv     = (const float*)d_in[19];
    const float* sw_o       = (const float*)d_in[20];
    const float* sb_o       = (const float*)d_in[21];
    const float* ms_w1      = (const float*)d_in[22];
    const float* ms_b1      = (const float*)d_in[23];
    const float* ms_w2      = (const float*)d_in[24];
    const float* ms_b2      = (const float*)d_in[25];
    const float* lno_g      = (const float*)d_in[26];
    const float* lno_b      = (const float*)d_in[27];
    float* out = (float*)d_out;

    cudaFuncSetAttribute(gemm_mma<3>,   cudaFuncAttributeMaxDynamicSharedMemorySize, GSM);
    cudaFuncSetAttribute(gemm_mma<5>,   cudaFuncAttributeMaxDynamicSharedMemorySize, GSM);
    cudaFuncSetAttribute(gemm_mma_h<1>, cudaFuncAttributeMaxDynamicSharedMemorySize, GSMH);
    cudaFuncSetAttribute(gemm_mma_h<2>, cudaFuncAttributeMaxDynamicSharedMemorySize, GSMH);
    cudaFuncSetAttribute(gemm_mma_h<3>, cudaFuncAttributeMaxDynamicSharedMemorySize, GSMH);
    cudaFuncSetAttribute(gemm_mma_h<4>, cudaFuncAttributeMaxDynamicSharedMemorySize, GSMH);
    cudaFuncSetAttribute(fattn,         cudaFuncAttributeMaxDynamicSharedMemorySize, FA_SMEM);

    float *plat, *ptmpf, *pmask6, *pbc, *pzb;
    __half *pvallh, *psqh;
    __nv_bfloat16 *ptok2, *ptmp2, *phid2, *pat2, *pq2, *pkall, *psq2, *pwpT, *pwc,
                  *pwxqkv, *pwxo, *pwmx1, *pwmx2, *pwsqkv, *pwso, *pwms1, *pwms2;
    cudaGetSymbolAddress((void**)&plat,   g_lat);
    cudaGetSymbolAddress((void**)&ptmpf,  g_tmpf);
    cudaGetSymbolAddress((void**)&pmask6, g_mask6);
    cudaGetSymbolAddress((void**)&pbc,    g_bc);
    cudaGetSymbolAddress((void**)&pzb,    g_zerob);
    cudaGetSymbolAddress((void**)&ptok2,  g_tok2);
    cudaGetSymbolAddress((void**)&ptmp2,  g_tmp2);
    cudaGetSymbolAddress((void**)&phid2,  g_hid2);
    cudaGetSymbolAddress((void**)&pat2,   g_at2);
    cudaGetSymbolAddress((void**)&pq2,    g_q2);
    cudaGetSymbolAddress((void**)&pkall,  g_kall2);
    cudaGetSymbolAddress((void**)&pvallh, g_vallh);
    cudaGetSymbolAddress((void**)&psq2,   g_sq2);
    cudaGetSymbolAddress((void**)&psqh,   g_sqh);
    cudaGetSymbolAddress((void**)&pwpT,   g_wpT2);
    cudaGetSymbolAddress((void**)&pwc,    g_wc2);
    cudaGetSymbolAddress((void**)&pwxqkv, g_wxqkv2);
    cudaGetSymbolAddress((void**)&pwxo,   g_wxo2);
    cudaGetSymbolAddress((void**)&pwmx1,  g_wmx1);
    cudaGetSymbolAddress((void**)&pwmx2,  g_wmx2);
    cudaGetSymbolAddress((void**)&pwsqkv, g_wsqkv2);
    cudaGetSymbolAddress((void**)&pwso,   g_wso2);
    cudaGetSymbolAddress((void**)&pwms1,  g_wms1);
    cudaGetSymbolAddress((void**)&pwms2,  g_wms2);

    const int BT = B * T, BL = B * LQ;

    // ---- upfront: splits, folded KV weights/bias, K/V batched GEMMs, masks ----
    split_pair<<<dim3(D / 256,   NB * 3 * D), 256>>>(xw_qkv, pwxqkv, D);
    split_pair<<<dim3(D / 256,   NB * D),     256>>>(xw_o,   pwxo,   D);
    split_pair<<<dim3(D / 256,   NB * HID),   256>>>(mx_w1,  pwmx1,  D);
    split_pair<<<dim3(HID / 256, NB * D),     256>>>(mx_w2,  pwmx2,  HID);
    split_pair<<<dim3(D / 256,   NB * 3 * D), 256>>>(sw_qkv, pwsqkv, D);
    split_pair<<<dim3(D / 256,   NB * D),     256>>>(sw_o,   pwso,   D);
    split_pair<<<dim3(D / 256,   NB * HID),   256>>>(ms_w1,  pwms1,  D);
    split_pair<<<dim3(HID / 256, NB * D),     256>>>(ms_w2,  pwms2,  HID);
    split_pair<<<dim3(D_IN / 256, BT),        256>>>(tokens, ptok2,  D_IN);
    tsplit_proj<<<dim3(D / 256, D_IN), 256>>>(proj_w, pwpT);

    // combined KV weights, rearranged [Kall(3072) | Vall(3072)]
    for (int i = 0; i < NB; i++) {
        gemm_mma_h<3><<<dim3(D_IN / 128, 512 / 64), 128, GSMH>>>(
            pwxqkv + ((size_t)i * 3 * D + D) * 2 * D, 2 * D,
            pwpT, 2 * D, pzb, nullptr, pwc + (size_t)(i * 512) * 2 * D_IN, nullptr, D_IN, D);
        gemm_mma_h<3><<<dim3(D_IN / 128, 512 / 64), 128, GSMH>>>(
            pwxqkv + ((size_t)i * 3 * D + 2 * D) * 2 * D, 2 * D,
            pwpT, 2 * D, pzb, nullptr, pwc + (size_t)(3072 + i * 512) * 2 * D_IN, nullptr, D_IN, D);
    }
    kvbias_kernel<<<KVN, 256>>>(xw_qkv, xb_qkv, proj_b, pbc);

    // Kall (split bf16) and Vall (fp16) for all 6 blocks, from tokens (K=256)
    gemm_mma<3><<<dim3(3072 / 128, BT / 128), 256, GSM>>>(
        ptok2, 2 * D_IN, pwc, 2 * D_IN, pbc, nullptr, pkall, nullptr, 3072, D_IN);
    gemm_mma<5><<<dim3(3072 / 128, BT / 128), 256, GSM>>>(
        ptok2, 2 * D_IN, pwc + (size_t)3072 * 2 * D_IN, 2 * D_IN, pbc + 3072,
        nullptr, nullptr, pvallh, 3072, D_IN);

    mask6_kernel<<<dim3(T / 256, LQ, NB), 256>>>(rel_bias, mask_scale, pmask6);
    bcast_latents<<<(BL * D) / 256, 256>>>(latents, plat);

    for (int i = 0; i < NB; i++) {
        const __nv_bfloat16* wq2 = pwxqkv + (size_t)i * 3 * D * 2 * D;
        const float* bqkv = xb_qkv + (size_t)i * 3 * D;

        // ---- cross attention ----
        ln_split<<<BL, 256>>>(plat, lnx_g + i * D, lnx_b + i * D, ptmp2);
        gemm_mma_h<3><<<dim3(D / 128, BL / 64), 128, GSMH>>>(
            ptmp2, 2 * D, wq2, 2 * D, bqkv, nullptr, pq2, nullptr, D, D);
        fattn<<<dim3(LQ / BQ, B * H), 128, FA_SMEM>>>(
            pq2, 2 * D,
            pkall + (size_t)i * 512, 2 * 3072, 3072,
            pvallh + (size_t)i * 512, 3072,
            pmask6 + (size_t)i * LQ * T, pat2, T);
        gemm_mma_h<2><<<dim3(D / 128, BL / 64), 128, GSMH>>>(
            pat2, 2 * D, pwxo + (size_t)i * D * 2 * D, 2 * D, xb_o + i * D,
            plat, nullptr, nullptr, D, D);

        // ---- cross MLP (pre-LN reuses lnx params) ----
        ln_split<<<BL, 256>>>(plat, lnx_g + i * D, lnx_b + i * D, ptmp2);
        gemm_mma_h<1><<<dim3(HID / 128, BL / 64), 128, GSMH>>>(
            ptmp2, 2 * D, pwmx1 + (size_t)i * HID * 2 * D, 2 * D, mx_b1 + i * HID,
            nullptr, phid2, nullptr, HID, D);
        gemm_mma_h<2><<<dim3(D / 128, BL / 64), 128, GSMH>>>(
            phid2, 2 * HID, pwmx2 + (size_t)i * D * 2 * HID, 2 * HID, mx_b2 + i * D,
            plat, nullptr, nullptr, D, HID);

        // ---- self attention ----
        ln_split<<<BL, 256>>>(plat, lns_g + i * D, lns_b + i * D, ptmp2);
        gemm_mma_h<4><<<dim3((3 * D) / 128, BL / 64), 128, GSMH>>>(
            ptmp2, 2 * D, pwsqkv + (size_t)i * 3 * D * 2 * D, 2 * D,
            sb_qkv + (size_t)i * 3 * D, nullptr, psq2, psqh, 3 * D, D);
        fattn<<<dim3(LQ / BQ, B * H), 128, FA_SMEM>>>(
            psq2, 6 * D,
            psq2 + D, 6 * D, 3 * D,
            psqh + 2 * D, 3 * D,
            nullptr, pat2, LQ);
        gemm_mma_h<2><<<dim3(D / 128, BL / 64), 128, GSMH>>>(
            pat2, 2 * D, pwso + (size_t)i * D * 2 * D, 2 * D, sb_o + i * D,
            plat, nullptr, nullptr, D, D);

        // ---- self MLP ----
        ln_split<<<BL, 256>>>(plat, lns_g + i * D, lns_b + i * D, ptmp2);
        gemm_mma_h<1><<<dim3(HID / 128, BL / 64), 128, GSMH>>>(
            ptmp2, 2 * D, pwms1 + (size_t)i * HID * 2 * D, 2 * D, ms_b1 + i * HID,
            nullptr, phid2, nullptr, HID, D);
        gemm_mma_h<2><<<dim3(D / 128, BL / 64), 128, GSMH>>>(
            phid2, 2 * HID, pwms2 + (size_t)i * D * 2 * HID, 2 * HID, ms_b2 + i * D,
            plat, nullptr, nullptr, D, HID);
    }

    // final LN + mean over latents
    ln_kernel<<<BL, 256>>>(plat, lno_g, lno_b, ptmpf);
    mean_kernel<<<(B * D) / 256, 256>>>(ptmpf, out);
}

// round 8
// speedup vs baseline: 4.6861x; 1.2586x over previous
#include <cuda_runtime.h>
#include <cuda_bf16.h>
#include <cuda_fp16.h>
#include <cstdint>
#include <math.h>

// ---------------- problem constants ----------------
#define B   8
#define T   4096
#define D_IN 256
#define D   512
#define LQ  256
#define H   8
#define HD  64
#define NB  6
#define HID 2048
#define KVN (NB * 2 * D)          // 6144 combined KV rows in wc

// ---------------- mma.sync helpers (sm_80+ PTX; no tcgen05) ----------------
__device__ __forceinline__ uint32_t smem_u32(const void* p) {
    uint32_t a;
    asm("{ .reg .u64 t; cvta.to.shared.u64 t, %1; cvt.u32.u64 %0, t; }" : "=r"(a) : "l"(p));
    return a;
}
__device__ __forceinline__ void cp16(uint32_t dst, const void* src) {
    asm volatile("cp.async.cg.shared.global [%0], [%1], 16;\n" :: "r"(dst), "l"(src));
}
__device__ __forceinline__ void ldsm4(uint32_t& r0, uint32_t& r1, uint32_t& r2, uint32_t& r3,
                                      uint32_t addr) {
    asm volatile("ldmatrix.sync.aligned.m8n8.x4.shared.b16 {%0,%1,%2,%3}, [%4];"
        : "=r"(r0), "=r"(r1), "=r"(r2), "=r"(r3) : "r"(addr));
}
__device__ __forceinline__ void ldsm4t(uint32_t& r0, uint32_t& r1, uint32_t& r2, uint32_t& r3,
                                       uint32_t addr) {
    asm volatile("ldmatrix.sync.aligned.m8n8.x4.trans.shared.b16 {%0,%1,%2,%3}, [%4];"
        : "=r"(r0), "=r"(r1), "=r"(r2), "=r"(r3) : "r"(addr));
}
__device__ __forceinline__ void mma16816(float* c, const uint32_t* a, uint32_t b0, uint32_t b1) {
    asm volatile("mma.sync.aligned.m16n8k16.row.col.f32.bf16.bf16.f32 "
        "{%0,%1,%2,%3}, {%4,%5,%6,%7}, {%8,%9}, {%0,%1,%2,%3};"
        : "+f"(c[0]), "+f"(c[1]), "+f"(c[2]), "+f"(c[3])
        : "r"(a[0]), "r"(a[1]), "r"(a[2]), "r"(a[3]), "r"(b0), "r"(b1));
}
__device__ __forceinline__ void mma16816h(float* c, const uint32_t* a, uint32_t b0, uint32_t b1) {
    asm volatile("mma.sync.aligned.m16n8k16.row.col.f32.f16.f16.f32 "
        "{%0,%1,%2,%3}, {%4,%5,%6,%7}, {%8,%9}, {%0,%1,%2,%3};"
        : "+f"(c[0]), "+f"(c[1]), "+f"(c[2]), "+f"(c[3])
        : "r"(a[0]), "r"(a[1]), "r"(a[2]), "r"(a[3]), "r"(b0), "r"(b1));
}
// pack two fp32 logits -> f16x2, one MUFU ex2 for both probs (low = tlo)
__device__ __forceinline__ uint32_t packex2h2(float tlo, float thi) {
    uint32_t t, r;
    asm("cvt.rn.f16x2.f32 %0, %1, %2;" : "=r"(t) : "f"(thi), "f"(tlo));
    asm("ex2.approx.f16x2 %0, %1;" : "=r"(r) : "r"(t));
    return r;
}

// ---------------- scratch (static device globals; no allocation) ----------------
__device__ float g_lat [B*LQ*D];
__device__ float g_tmpf[B*LQ*D];
__device__ float g_mask6[NB*LQ*T];
__device__ float g_bc  [KVN];
__device__ float g_zerob[D_IN];

__device__ __align__(256) __nv_bfloat16 g_tok2 [B*T*2*D_IN];
__device__ __align__(256) __nv_bfloat16 g_tmp2 [B*LQ*2*D];
__device__ __align__(256) __nv_bfloat16 g_hid2 [B*LQ*2*HID];
__device__ __align__(256) __nv_bfloat16 g_at2  [B*LQ*2*D];
__device__ __align__(256) __nv_bfloat16 g_q2   [B*LQ*2*D];
__device__ __align__(256) __nv_bfloat16 g_kall2[(size_t)B*T*2*(NB*D)];  // all-blocks K split
__device__ __align__(256) __half        g_vallh[(size_t)B*T*(NB*D)];    // all-blocks V fp16
__device__ __align__(256) __nv_bfloat16 g_sq2  [B*LQ*2*(3*D)];
__device__ __align__(256) __half        g_sqh  [B*LQ*(3*D)];
__device__ __align__(256) __nv_bfloat16 g_wpT2 [D_IN*2*D];
__device__ __align__(256) __nv_bfloat16 g_wc2  [KVN*2*D_IN];            // [Kall(3072) | Vall(3072)]
__device__ __align__(256) __nv_bfloat16 g_wxqkv2[NB*3*D*2*D];
__device__ __align__(256) __nv_bfloat16 g_wxo2  [NB*D*2*D];
__device__ __align__(256) __nv_bfloat16 g_wmx1  [NB*HID*2*D];
__device__ __align__(256) __nv_bfloat16 g_wmx2  [NB*D*2*HID];
__device__ __align__(256) __nv_bfloat16 g_wsqkv2[NB*3*D*2*D];
__device__ __align__(256) __nv_bfloat16 g_wso2  [NB*D*2*D];
__device__ __align__(256) __nv_bfloat16 g_wms1  [NB*HID*2*D];
__device__ __align__(256) __nv_bfloat16 g_wms2  [NB*D*2*HID];

__device__ __forceinline__ void split2(float x, __nv_bfloat16& h, __nv_bfloat16& l) {
    h = __float2bfloat16(x);
    l = __float2bfloat16(x - __bfloat162float(h));
}

// ---------------- reductions ----------------
__device__ __forceinline__ float block_sum256(float v, float* sh) {
    #pragma unroll
    for (int o = 16; o; o >>= 1) v += __shfl_xor_sync(0xffffffffu, v, o);
    if ((threadIdx.x & 31) == 0) sh[threadIdx.x >> 5] = v;
    __syncthreads();
    float t = (threadIdx.x < 8) ? sh[threadIdx.x] : 0.f;
    if (threadIdx.x < 32) {
        #pragma unroll
        for (int o = 4; o; o >>= 1) t += __shfl_xor_sync(0xffffffffu, t, o);
        if (threadIdx.x == 0) sh[0] = t;
    }
    __syncthreads();
    float r = sh[0];
    __syncthreads();
    return r;
}

// ================= tensor-core GEMM (HMMA): C = A·W^T + bias =================
// A2 [M, 2K] = [hi | lo] bf16, W2 [N, 2K] likewise. 2 K-passes (hh, h·lo).
// EPI: 1 = gelu->split C2   2 = res(inplace fp32 C)   3 = split C2
//      4 = split C2 + fp16 shadow C3   5 = fp16 C3 only
#define BK 32
#define AST 40
#define STG (128 * AST * 2)
#define NSTAGE 4
#define GSM (NSTAGE * 2 * STG)
#define NPASS 2

template<int EPI>
__global__ __launch_bounds__(256)
void gemm_mma(const __nv_bfloat16* __restrict__ A2, int ldA,
              const __nv_bfloat16* __restrict__ W2, int ldW,
              const float* __restrict__ bias,
              float* __restrict__ C, __nv_bfloat16* __restrict__ C2,
              __half* __restrict__ C3, int N, int K)
{
    extern __shared__ __align__(256) char smraw[];
    const uint32_t base = smem_u32(smraw);
    const int tid = threadIdx.x;
    const int bm = blockIdx.y * 128, bn = blockIdx.x * 128;
    const int lane = tid & 31, warp = tid >> 5;
    const int wm = warp & 3, wn = warp >> 2;

    const int nkc = K / BK;
    const int nch = NPASS * nkc;

    float acc[2][8][4];
    #pragma unroll
    for (int i = 0; i < 2; i++)
        #pragma unroll
        for (int j = 0; j < 8; j++)
            #pragma unroll
            for (int k = 0; k < 4; k++) acc[i][j][k] = 0.f;

    auto issue_load = [&](int i, int st) {
        int s = i / nkc, kc = i - s * nkc;
        int ao = kc * BK;
        int wo = ((s == 1) ? K : 0) + kc * BK;
        uint32_t smA = base + st * (2 * STG);
        uint32_t smB = smA + STG;
        const __nv_bfloat16* As = A2 + (size_t)bm * ldA + ao;
        const __nv_bfloat16* Ws = W2 + (size_t)bn * ldW + wo;
        #pragma unroll
        for (int j = 0; j < 2; j++) {
            int u = j * 256 + tid;
            int r = u >> 2, cc = (u & 3) * 8;
            cp16(smA + (uint32_t)(r * AST + cc) * 2, As + (size_t)r * ldA + cc);
            cp16(smB + (uint32_t)(r * AST + cc) * 2, Ws + (size_t)r * ldW + cc);
        }
        asm volatile("cp.async.commit_group;\n" ::: "memory");
    };

    const int arow = wm * 32 + ((lane >> 3) & 1) * 8 + (lane & 7);
    const int akof = ((lane >> 4) & 1) * 8;
    const int brow = wn * 64 + ((lane >> 4) & 1) * 8 + (lane & 7);
    const int bkof = ((lane >> 3) & 1) * 8;

    #pragma unroll
    for (int s = 0; s < NSTAGE - 1; s++) issue_load(s, s);

    for (int i = 0; i < nch; i++) {
        int rem = nch - 1 - i;
        if (rem >= 2)      asm volatile("cp.async.wait_group 2;\n" ::: "memory");
        else if (rem == 1) asm volatile("cp.async.wait_group 1;\n" ::: "memory");
        else               asm volatile("cp.async.wait_group 0;\n" ::: "memory");
        __syncthreads();
        if (i + NSTAGE - 1 < nch) issue_load(i + NSTAGE - 1, (i + NSTAGE - 1) % NSTAGE);

        uint32_t smA = base + (i % NSTAGE) * (2 * STG);
        uint32_t smB = smA + STG;
        #pragma unroll
        for (int kk = 0; kk < 2; kk++) {
            const int k0 = kk * 16;
            uint32_t a[2][4], b[4][4];
            #pragma unroll
            for (int fm = 0; fm < 2; fm++)
                ldsm4(a[fm][0], a[fm][1], a[fm][2], a[fm][3],
                      smA + (uint32_t)((arow + fm * 16) * AST + k0 + akof) * 2);
            #pragma unroll
            for (int fb = 0; fb < 4; fb++)
                ldsm4(b[fb][0], b[fb][1], b[fb][2], b[fb][3],
                      smB + (uint32_t)((brow + fb * 16) * AST + k0 + bkof) * 2);
            #pragma unroll
            for (int fm = 0; fm < 2; fm++)
                #pragma unroll
                for (int fn = 0; fn < 8; fn++)
                    mma16816(acc[fm][fn], a[fm], b[fn >> 1][(fn & 1) * 2],
                             b[fn >> 1][(fn & 1) * 2 + 1]);
        }
    }

    const int lr = lane >> 2, lc = (lane & 3) * 2;
    #pragma unroll
    for (int fm = 0; fm < 2; fm++) {
        #pragma unroll
        for (int fn = 0; fn < 8; fn++) {
            float* cc = acc[fm][fn];
            int m0 = bm + wm * 32 + fm * 16 + lr;
            int n0 = bn + wn * 64 + fn * 8 + lc;
            float b0 = bias[n0], b1 = bias[n0 + 1];
            float v00 = cc[0] + b0, v01 = cc[1] + b1;
            float v10 = cc[2] + b0, v11 = cc[3] + b1;
            if (EPI == 1) {
                v00 = 0.5f * v00 * (1.0f + erff(v00 * 0.70710678118654752f));
                v01 = 0.5f * v01 * (1.0f + erff(v01 * 0.70710678118654752f));
                v10 = 0.5f * v10 * (1.0f + erff(v10 * 0.70710678118654752f));
                v11 = 0.5f * v11 * (1.0f + erff(v11 * 0.70710678118654752f));
            }
            if (EPI == 2) {
                float2 r0 = *(const float2*)&C[(size_t)m0 * N + n0];
                float2 r1 = *(const float2*)&C[(size_t)(m0 + 8) * N + n0];
                *(float2*)&C[(size_t)m0 * N + n0]       = make_float2(v00 + r0.x, v01 + r0.y);
                *(float2*)&C[(size_t)(m0 + 8) * N + n0] = make_float2(v10 + r1.x, v11 + r1.y);
            } else if (EPI == 5) {
                *(half2*)&C3[(size_t)m0 * N + n0]       = __floats2half2_rn(v00, v01);
                *(half2*)&C3[(size_t)(m0 + 8) * N + n0] = __floats2half2_rn(v10, v11);
            } else {
                __nv_bfloat16 h0, l0, h1, l1;
                split2(v00, h0, l0); split2(v01, h1, l1);
                *(__nv_bfloat162*)&C2[(size_t)m0 * 2 * N + n0]     = __nv_bfloat162(h0, h1);
                *(__nv_bfloat162*)&C2[(size_t)m0 * 2 * N + N + n0] = __nv_bfloat162(l0, l1);
                split2(v10, h0, l0); split2(v11, h1, l1);
                *(__nv_bfloat162*)&C2[(size_t)(m0 + 8) * 2 * N + n0]     = __nv_bfloat162(h0, h1);
                *(__nv_bfloat162*)&C2[(size_t)(m0 + 8) * 2 * N + N + n0] = __nv_bfloat162(l0, l1);
                if (EPI == 4) {
                    *(half2*)&C3[(size_t)m0 * N + n0]       = __floats2half2_rn(v00, v01);
                    *(half2*)&C3[(size_t)(m0 + 8) * N + n0] = __floats2half2_rn(v10, v11);
                }
            }
        }
    }
}

// ---------- 64x128-tile variant (128 threads) ----------
#define ASTGH (64 * AST * 2)
#define BSTGH (128 * AST * 2)
#define GSMH (NSTAGE * (ASTGH + BSTGH))

template<int EPI>
__global__ __launch_bounds__(128)
void gemm_mma_h(const __nv_bfloat16* __restrict__ A2, int ldA,
                const __nv_bfloat16* __restrict__ W2, int ldW,
                const float* __restrict__ bias,
                float* __restrict__ C, __nv_bfloat16* __restrict__ C2,
                __half* __restrict__ C3, int N, int K)
{
    extern __shared__ __align__(256) char smraw[];
    const uint32_t base = smem_u32(smraw);
    const int tid = threadIdx.x;
    const int bm = blockIdx.y * 64, bn = blockIdx.x * 128;
    const int lane = tid & 31, warp = tid >> 5;
    const int wm = warp & 1, wn = warp >> 1;

    const int nkc = K / BK;
    const int nch = NPASS * nkc;

    float acc[2][8][4];
    #pragma unroll
    for (int i = 0; i < 2; i++)
        #pragma unroll
        for (int j = 0; j < 8; j++)
            #pragma unroll
            for (int k = 0; k < 4; k++) acc[i][j][k] = 0.f;

    auto issue_load = [&](int i, int st) {
        int s = i / nkc, kc = i - s * nkc;
        int ao = kc * BK;
        int wo = ((s == 1) ? K : 0) + kc * BK;
        uint32_t smA = base + st * (ASTGH + BSTGH);
        uint32_t smB = smA + ASTGH;
        const __nv_bfloat16* As = A2 + (size_t)bm * ldA + ao;
        const __nv_bfloat16* Ws = W2 + (size_t)bn * ldW + wo;
        #pragma unroll
        for (int j = 0; j < 2; j++) {
            int u = j * 128 + tid;
            int r = u >> 2, cc = (u & 3) * 8;
            cp16(smA + (uint32_t)(r * AST + cc) * 2, As + (size_t)r * ldA + cc);
        }
        #pragma unroll
        for (int j = 0; j < 4; j++) {
            int u = j * 128 + tid;
            int r = u >> 2, cc = (u & 3) * 8;
            cp16(smB + (uint32_t)(r * AST + cc) * 2, Ws + (size_t)r * ldW + cc);
        }
        asm volatile("cp.async.commit_group;\n" ::: "memory");
    };

    const int arow = wm * 32 + ((lane >> 3) & 1) * 8 + (lane & 7);
    const int akof = ((lane >> 4) & 1) * 8;
    const int brow = wn * 64 + ((lane >> 4) & 1) * 8 + (lane & 7);
    const int bkof = ((lane >> 3) & 1) * 8;

    #pragma unroll
    for (int s = 0; s < NSTAGE - 1; s++) issue_load(s, s);

    for (int i = 0; i < nch; i++) {
        int rem = nch - 1 - i;
        if (rem >= 2)      asm volatile("cp.async.wait_group 2;\n" ::: "memory");
        else if (rem == 1) asm volatile("cp.async.wait_group 1;\n" ::: "memory");
        else               asm volatile("cp.async.wait_group 0;\n" ::: "memory");
        __syncthreads();
        if (i + NSTAGE - 1 < nch) issue_load(i + NSTAGE - 1, (i + NSTAGE - 1) % NSTAGE);

        uint32_t smA = base + (i % NSTAGE) * (ASTGH + BSTGH);
        uint32_t smB = smA + ASTGH;
        #pragma unroll
        for (int kk = 0; kk < 2; kk++) {
            const int k0 = kk * 16;
            uint32_t a[2][4], b[4][4];
            #pragma unroll
            for (int fm = 0; fm < 2; fm++)
                ldsm4(a[fm][0], a[fm][1], a[fm][2], a[fm][3],
                      smA + (uint32_t)((arow + fm * 16) * AST + k0 + akof) * 2);
            #pragma unroll
            for (int fb = 0; fb < 4; fb++)
                ldsm4(b[fb][0], b[fb][1], b[fb][2], b[fb][3],
                      smB + (uint32_t)((brow + fb * 16) * AST + k0 + bkof) * 2);
            #pragma unroll
            for (int fm = 0; fm < 2; fm++)
                #pragma unroll
                for (int fn = 0; fn < 8; fn++)
                    mma16816(acc[fm][fn], a[fm], b[fn >> 1][(fn & 1) * 2],
                             b[fn >> 1][(fn & 1) * 2 + 1]);
        }
    }

    const int lr = lane >> 2, lc = (lane & 3) * 2;
    #pragma unroll
    for (int fm = 0; fm < 2; fm++) {
        #pragma unroll
        for (int fn = 0; fn < 8; fn++) {
            float* cc = acc[fm][fn];
            int m0 = bm + wm * 32 + fm * 16 + lr;
            int n0 = bn + wn * 64 + fn * 8 + lc;
            float b0 = bias[n0], b1 = bias[n0 + 1];
            float v00 = cc[0] + b0, v01 = cc[1] + b1;
            float v10 = cc[2] + b0, v11 = cc[3] + b1;
            if (EPI == 1) {
                v00 = 0.5f * v00 * (1.0f + erff(v00 * 0.70710678118654752f));
                v01 = 0.5f * v01 * (1.0f + erff(v01 * 0.70710678118654752f));
                v10 = 0.5f * v10 * (1.0f + erff(v10 * 0.70710678118654752f));
                v11 = 0.5f * v11 * (1.0f + erff(v11 * 0.70710678118654752f));
            }
            if (EPI == 2) {
                float2 r0 = *(const float2*)&C[(size_t)m0 * N + n0];
                float2 r1 = *(const float2*)&C[(size_t)(m0 + 8) * N + n0];
                *(float2*)&C[(size_t)m0 * N + n0]       = make_float2(v00 + r0.x, v01 + r0.y);
                *(float2*)&C[(size_t)(m0 + 8) * N + n0] = make_float2(v10 + r1.x, v11 + r1.y);
            } else if (EPI == 5) {
                *(half2*)&C3[(size_t)m0 * N + n0]       = __floats2half2_rn(v00, v01);
                *(half2*)&C3[(size_t)(m0 + 8) * N + n0] = __floats2half2_rn(v10, v11);
            } else {
                __nv_bfloat16 h0, l0, h1, l1;
                split2(v00, h0, l0); split2(v01, h1, l1);
                *(__nv_bfloat162*)&C2[(size_t)m0 * 2 * N + n0]     = __nv_bfloat162(h0, h1);
                *(__nv_bfloat162*)&C2[(size_t)m0 * 2 * N + N + n0] = __nv_bfloat162(l0, l1);
                split2(v10, h0, l0); split2(v11, h1, l1);
                *(__nv_bfloat162*)&C2[(size_t)(m0 + 8) * 2 * N + n0]     = __nv_bfloat162(h0, h1);
                *(__nv_bfloat162*)&C2[(size_t)(m0 + 8) * 2 * N + N + n0] = __nv_bfloat162(l0, l1);
                if (EPI == 4) {
                    *(half2*)&C3[(size_t)m0 * N + n0]       = __floats2half2_rn(v00, v01);
                    *(half2*)&C3[(size_t)(m0 + 8) * N + n0] = __floats2half2_rn(v10, v11);
                }
            }
        }
    }
}

// ================= fused flash attention =================
// Q/K split bf16 (2-pass QK); P,V fp16 single-pass PV via ex2.approx.f16x2;
// row sums via ones-column mma. 128 q rows/block (8 warps), 64-key chunks,
// double-buffered — halves K/V/mask re-read traffic vs BQ=64.
#define BQ 128
#define BKC 64
#define QST 72
#define FTILEQ (128 * QST * 2)        // 18432 B (Q hi)
#define FTILE (64 * QST * 2)          // 9216 B
#define FSTG (3 * FTILE)              // Kh, Kl, V(fp16 w/ ones cols)
#define FA_SMEM (FTILEQ + 2 * FSTG + 64)

__global__ __launch_bounds__(256)
void fattn(const __nv_bfloat16* __restrict__ Qp, int ldq,
           const __nv_bfloat16* __restrict__ Kp, int ldk, int ok,
           const __half* __restrict__ Vh, int ldv,
           const float* __restrict__ pm, __nv_bfloat16* __restrict__ O2, int Tk)
{
    extern __shared__ __align__(256) char smraw[];
    const uint32_t base = smem_u32(smraw);
    const int tid = threadIdx.x, lane = tid & 31, warp = tid >> 5;
    const int bh = (int)blockIdx.y, b = bh >> 3, h = bh & 7;
    const int q0 = (int)blockIdx.x * BQ;

    const __nv_bfloat16* Qb = Qp + (size_t)(b * LQ + q0) * ldq + h * HD;
    const __nv_bfloat16* Kb = Kp + (size_t)b * Tk * ldk + h * HD;
    const __half* Vb = Vh + (size_t)b * Tk * ldv + h * HD;

    // Q hi tile (128 rows) -> smem
    #pragma unroll
    for (int j = 0; j < 4; j++) {
        int u = j * 256 + tid, r = u >> 3, c8 = (u & 7) * 8;
        cp16(base + (uint32_t)(r * QST + c8) * 2, Qb + (size_t)r * ldq + c8);
    }
    asm volatile("cp.async.commit_group;\n" ::: "memory");

    // ones columns (64..71) in both stages' V tiles
    if (tid < 128) {
        int r = tid >> 1, cq = (tid & 1) * 4;
        #pragma unroll
        for (int st = 0; st < 2; st++) {
            size_t off = (size_t)FTILEQ + (size_t)st * FSTG + 2 * FTILE
                       + (size_t)(r * QST + 64 + cq) * 2;
            *(uint2*)(smraw + off) = make_uint2(0x3C003C00u, 0x3C003C00u);
        }
    }

    const int nc = Tk / BKC;
    auto load_chunk = [&](int ci, int st) {
        uint32_t sb = base + FTILEQ + st * FSTG;
        const __nv_bfloat16* Kc = Kb + (size_t)ci * BKC * ldk;
        const __half* Vc = Vb + (size_t)ci * BKC * ldv;
        #pragma unroll
        for (int j = 0; j < 2; j++) {
            int u = j * 256 + tid, r = u >> 3, c8 = (u & 7) * 8;
            uint32_t off = (uint32_t)(r * QST + c8) * 2;
            cp16(sb + off,             Kc + (size_t)r * ldk + c8);
            cp16(sb + FTILE + off,     Kc + (size_t)r * ldk + ok + c8);
            cp16(sb + 2 * FTILE + off, Vc + (size_t)r * ldv + c8);
        }
        asm volatile("cp.async.commit_group;\n" ::: "memory");
    };

    load_chunk(0, 0);
    asm volatile("cp.async.wait_group 1;\n" ::: "memory");   // Q ready
    __syncthreads();

    const int qrow = warp * 16 + ((lane >> 3) & 1) * 8 + (lane & 7);
    const int qko  = ((lane >> 4) & 1) * 8;
    uint32_t qf[4][4];
    #pragma unroll
    for (int ds = 0; ds < 4; ds++)
        ldsm4(qf[ds][0], qf[ds][1], qf[ds][2], qf[ds][3],
              base + (uint32_t)(qrow * QST + ds * 16 + qko) * 2);

    load_chunk(1, 1);

    float o[8][4], osum[4];
    #pragma unroll
    for (int i = 0; i < 8; i++)
        #pragma unroll
        for (int j = 0; j < 4; j++) o[i][j] = 0.f;
    #pragma unroll
    for (int j = 0; j < 4; j++) osum[j] = 0.f;

    const float SC  = 0.125f * 1.44269504088896f;
    const float L2E = 1.44269504088896f;
    const int lr = lane >> 2, lc = (lane & 3) * 2;
    const int krow = ((lane >> 4) & 1) * 8 + (lane & 7);
    const int kko  = ((lane >> 3) & 1) * 8;
    const int vrow = lane & 15;
    const int vco  = ((lane >> 4) & 1) * 8;
    const int qr_g = q0 + warp * 16 + lr;

    for (int ci = 0; ci < nc; ci++) {
        if (ci == nc - 1) asm volatile("cp.async.wait_group 0;\n" ::: "memory");
        else              asm volatile("cp.async.wait_group 1;\n" ::: "memory");
        __syncthreads();

        uint32_t sb = base + FTILEQ + (ci & 1) * FSTG;

        // ---- S = Q·K^T (2 split passes) ----
        float s[8][4];
        #pragma unroll
        for (int i = 0; i < 8; i++)
            #pragma unroll
            for (int j = 0; j < 4; j++) s[i][j] = 0.f;
        #pragma unroll
        for (int ps = 0; ps < 2; ps++) {
            const uint32_t kb = sb + ((ps == 1) ? FTILE : 0);
            #pragma unroll
            for (int ds = 0; ds < 4; ds++) {
                #pragma unroll
                for (int g = 0; g < 4; g++) {
                    uint32_t b0, b1, b2, b3;
                    ldsm4(b0, b1, b2, b3,
                          kb + (uint32_t)((g * 16 + krow) * QST + ds * 16 + kko) * 2);
                    mma16816(s[2 * g],     qf[ds], b0, b1);
                    mma16816(s[2 * g + 1], qf[ds], b2, b3);
                }
            }
        }

        // ---- probs as fp16 fragments (one ex2.f16x2 per pair) ----
        uint32_t ph[4][4];
        #pragma unroll
        for (int nt = 0; nt < 8; nt++) {
            float t0 = s[nt][0] * SC, t1 = s[nt][1] * SC;
            float t2 = s[nt][2] * SC, t3 = s[nt][3] * SC;
            if (pm) {
                const float* pmr = pm + (size_t)qr_g * Tk + ci * BKC + nt * 8 + lc;
                float2 m0 = *(const float2*)pmr;
                float2 m1 = *(const float2*)(pmr + (size_t)8 * Tk);
                t0 = fmaf(m0.x, L2E, t0); t1 = fmaf(m0.y, L2E, t1);
                t2 = fmaf(m1.x, L2E, t2); t3 = fmaf(m1.y, L2E, t3);
            }
            int j = nt >> 1, qi = (nt & 1) * 2;
            ph[j][qi]     = packex2h2(t0, t1);
            ph[j][qi + 1] = packex2h2(t2, t3);
        }

        // ---- O += P·V (single fp16 pass) + row sums via ones columns ----
        uint32_t vb = sb + 2 * FTILE;
        #pragma unroll
        for (int ks = 0; ks < 4; ks++) {
            const uint32_t* pf = ph[ks];
            #pragma unroll
            for (int g = 0; g < 4; g++) {
                uint32_t b0, b1, b2, b3;
                ldsm4t(b0, b1, b2, b3,
                       vb + (uint32_t)((ks * 16 + vrow) * QST + g * 16 + vco) * 2);
                mma16816h(o[2 * g],     pf, b0, b1);
                mma16816h(o[2 * g + 1], pf, b2, b3);
            }
            {
                uint32_t b0, b1, b2, b3;
                ldsm4t(b0, b1, b2, b3,
                       vb + (uint32_t)((ks * 16 + vrow) * QST + 64 + vco) * 2);
                mma16816h(osum, pf, b0, b1);
            }
        }

        __syncthreads();
        if (ci + 2 < nc) load_chunk(ci + 2, ci & 1);
    }

    float inv0 = 1.0f / osum[0], inv1 = 1.0f / osum[2];

    const size_t row0 = (size_t)(b * LQ + qr_g);
    #pragma unroll
    for (int nt = 0; nt < 8; nt++) {
        int col = h * HD + nt * 8 + lc;
        float v0 = o[nt][0] * inv0, v1 = o[nt][1] * inv0;
        float v2 = o[nt][2] * inv1, v3 = o[nt][3] * inv1;
        __nv_bfloat16 h0, l0, h1, l1;
        split2(v0, h0, l0); split2(v1, h1, l1);
        *(__nv_bfloat162*)&O2[row0 * 2 * D + col]     = __nv_bfloat162(h0, h1);
        *(__nv_bfloat162*)&O2[row0 * 2 * D + D + col] = __nv_bfloat162(l0, l1);
        split2(v2, h0, l0); split2(v3, h1, l1);
        *(__nv_bfloat162*)&O2[(row0 + 8) * 2 * D + col]     = __nv_bfloat162(h0, h1);
        *(__nv_bfloat162*)&O2[(row0 + 8) * 2 * D + D + col] = __nv_bfloat162(l0, l1);
    }
}

// ---------------- elementwise split ----------------
__global__ void split_pair(const float* __restrict__ src, __nv_bfloat16* __restrict__ dst, int K)
{
    int c = blockIdx.x * 256 + threadIdx.x;
    int r = blockIdx.y;
    float x = src[(size_t)r * K + c];
    __nv_bfloat16 h, l; split2(x, h, l);
    dst[(size_t)r * 2 * K + c] = h;
    dst[(size_t)r * 2 * K + K + c] = l;
}

// -------- transpose+split: proj_w[D, D_IN] -> wT2[D_IN, 2*D] --------
__global__ void tsplit_proj(const float* __restrict__ pw, __nv_bfloat16* __restrict__ wT2)
{
    int k = blockIdx.x * 256 + threadIdx.x;
    int c = blockIdx.y;
    float x = pw[(size_t)k * D_IN + c];
    __nv_bfloat16 h, l; split2(x, h, l);
    wT2[(size_t)c * 2 * D + k] = h;
    wT2[(size_t)c * 2 * D + D + k] = l;
}

// -------- folded KV bias for rearranged [Kall | Vall] layout --------
__global__ void kvbias_kernel(const float* __restrict__ xw_qkv, const float* __restrict__ xb_qkv,
                              const float* __restrict__ proj_b, float* __restrict__ bc)
{
    __shared__ float sh[32];
    int g = blockIdx.x;                 // [0, 6144)
    int wrow;
    if (g < 3072) { int i = g >> 9, n = g & 511; wrow = i * 3 * D + D + n; }
    else          { int gg = g - 3072; int i = gg >> 9, n = gg & 511; wrow = i * 3 * D + 2 * D + n; }
    const float* wr = xw_qkv + (size_t)wrow * D;
    float s = 0.f;
    for (int k = threadIdx.x; k < D; k += 256) s += wr[k] * proj_b[k];
    float tot = block_sum256(s, sh);
    if (threadIdx.x == 0) bc[g] = tot + xb_qkv[wrow];
}

// ---------------- LayerNorm -> split bf16 ----------------
__global__ void ln_split(const float* __restrict__ x, const float* __restrict__ g,
                         const float* __restrict__ b, __nv_bfloat16* __restrict__ y2)
{
    __shared__ float sh[32];
    const int row = blockIdx.x, tid = threadIdx.x;
    const float* xr = x + (size_t)row * D;
    float2 v = *(const float2*)&xr[tid * 2];
    float total = block_sum256(v.x + v.y, sh);
    float mean = total * (1.0f / D);
    float d0 = v.x - mean, d1 = v.y - mean;
    float sq = block_sum256(d0 * d0 + d1 * d1, sh);
    float inv = rsqrtf(sq * (1.0f / D) + 1e-5f);
    float2 go = *(const float2*)&g[tid * 2];
    float2 bo = *(const float2*)&b[tid * 2];
    float o0 = d0 * inv * go.x + bo.x;
    float o1 = d1 * inv * go.y + bo.y;
    __nv_bfloat16 h0, l0, h1, l1;
    split2(o0, h0, l0); split2(o1, h1, l1);
    __nv_bfloat16* dst = y2 + (size_t)row * 2 * D;
    ((__nv_bfloat162*)dst)[tid] = __nv_bfloat162(h0, h1);
    ((__nv_bfloat162*)(dst + D))[tid] = __nv_bfloat162(l0, l1);
}

// ---------------- plain LayerNorm (final) ----------------
__global__ void ln_kernel(const float* __restrict__ x, const float* __restrict__ g,
                          const float* __restrict__ b, float* __restrict__ y)
{
    __shared__ float sh[32];
    const int row = blockIdx.x, tid = threadIdx.x;
    const float* xr = x + (size_t)row * D;
    float2 v = *(const float2*)&xr[tid * 2];
    float total = block_sum256(v.x + v.y, sh);
    float mean = total * (1.0f / D);
    float d0 = v.x - mean, d1 = v.y - mean;
    float sq = block_sum256(d0 * d0 + d1 * d1, sh);
    float inv = rsqrtf(sq * (1.0f / D) + 1e-5f);
    float2 go = *(const float2*)&g[tid * 2];
    float2 bo = *(const float2*)&b[tid * 2];
    float2 o;
    o.x = d0 * inv * go.x + bo.x;
    o.y = d1 * inv * go.y + bo.y;
    *(float2*)&y[(size_t)row * D + tid * 2] = o;
}

// ---------------- all 6 relative-time masks ----------------
__global__ void mask6_kernel(const float* __restrict__ rel_bias, const float* __restrict__ ms,
                             float* __restrict__ pm6)
{
    int k = blockIdx.x * 256 + threadIdx.x;
    int q = blockIdx.y;
    int z = blockIdx.z;
    float tau = (float)q * (4095.0f / 255.0f);
    float dt = (float)k - tau;
    float c = fminf(fmaxf(dt, -128.f), 128.f);
    int idx = (int)c + 128;
    float zz = dt * (1.0f / 32.0f);
    float lg = logf(expf(-0.5f * zz * zz) + 1e-6f);
    pm6[(size_t)z * LQ * T + (size_t)q * T + k] = ms[z] * (rel_bias[z * 257 + idx] + lg);
}

// ---------------- misc ----------------
__global__ void bcast_latents(const float* __restrict__ src, float* __restrict__ dst)
{
    int i = blockIdx.x * 256 + threadIdx.x;
    dst[i] = src[i % (LQ * D)];
}

__global__ void mean_kernel(const float* __restrict__ x, float* __restrict__ out)
{
    int i = blockIdx.x * 256 + threadIdx.x;
    int b = i / D, d = i % D;
    float s = 0.f;
    for (int q = 0; q < LQ; q++) s += x[((size_t)b * LQ + q) * D + d];
    out[i] = s * (1.0f / LQ);
}

// ---------------- host orchestration ----------------
extern "C" void kernel_launch(void* const* d_in, const int* in_sizes, int n_in,
                              void* d_out, int out_size)
{
    (void)in_sizes; (void)n_in; (void)out_size;
    const float* tokens     = (const float*)d_in[0];
    const float* proj_w     = (const float*)d_in[1];
    const float* proj_b     = (const float*)d_in[2];
    const float* latents    = (const float*)d_in[3];
    const float* lnx_g      = (const float*)d_in[4];
    const float* lnx_b      = (const float*)d_in[5];
    const float* xw_qkv     = (const float*)d_in[6];
    const float* xb_qkv     = (const float*)d_in[7];
    const float* xw_o       = (const float*)d_in[8];
    const float* xb_o       = (const float*)d_in[9];
    const float* rel_bias   = (const float*)d_in[10];
    const float* mask_scale = (const float*)d_in[11];
    const float* mx_w1      = (const float*)d_in[12];
    const float* mx_b1      = (const float*)d_in[13];
    const float* mx_w2      = (const float*)d_in[14];
    const float* mx_b2      = (const float*)d_in[15];
    const float* lns_g      = (const float*)d_in[16];
    const float* lns_b      = (const float*)d_in[17];
    const float* sw_qkv     = (const float*)d_in[18];
    const float* sb_qkv     = (const float*)d_in[19];
    const float* sw_o       = (const float*)d_in[20];
    const float* sb_o       = (const float*)d_in[21];
    const float* ms_w1      = (const float*)d_in[22];
    const float* ms_b1      = (const float*)d_in[23];
    const float* ms_w2      = (const float*)d_in[24];
    const float* ms_b2      = (const float*)d_in[25];
    const float* lno_g      = (const float*)d_in[26];
    const float* lno_b      = (const float*)d_in[27];
    float* out = (float*)d_out;

    cudaFuncSetAttribute(gemm_mma<3>,   cudaFuncAttributeMaxDynamicSharedMemorySize, GSM);
    cudaFuncSetAttribute(gemm_mma<5>,   cudaFuncAttributeMaxDynamicSharedMemorySize, GSM);
    cudaFuncSetAttribute(gemm_mma_h<1>, cudaFuncAttributeMaxDynamicSharedMemorySize, GSMH);
    cudaFuncSetAttribute(gemm_mma_h<2>, cudaFuncAttributeMaxDynamicSharedMemorySize, GSMH);
    cudaFuncSetAttribute(gemm_mma_h<3>, cudaFuncAttributeMaxDynamicSharedMemorySize, GSMH);
    cudaFuncSetAttribute(gemm_mma_h<4>, cudaFuncAttributeMaxDynamicSharedMemorySize, GSMH);
    cudaFuncSetAttribute(fattn,         cudaFuncAttributeMaxDynamicSharedMemorySize, FA_SMEM);

    float *plat, *ptmpf, *pmask6, *pbc, *pzb;
    __half *pvallh, *psqh;
    __nv_bfloat16 *ptok2, *ptmp2, *phid2, *pat2, *pq2, *pkall, *psq2, *pwpT, *pwc,
                  *pwxqkv, *pwxo, *pwmx1, *pwmx2, *pwsqkv, *pwso, *pwms1, *pwms2;
    cudaGetSymbolAddress((void**)&plat,   g_lat);
    cudaGetSymbolAddress((void**)&ptmpf,  g_tmpf);
    cudaGetSymbolAddress((void**)&pmask6, g_mask6);
    cudaGetSymbolAddress((void**)&pbc,    g_bc);
    cudaGetSymbolAddress((void**)&pzb,    g_zerob);
    cudaGetSymbolAddress((void**)&ptok2,  g_tok2);
    cudaGetSymbolAddress((void**)&ptmp2,  g_tmp2);
    cudaGetSymbolAddress((void**)&phid2,  g_hid2);
    cudaGetSymbolAddress((void**)&pat2,   g_at2);
    cudaGetSymbolAddress((void**)&pq2,    g_q2);
    cudaGetSymbolAddress((void**)&pkall,  g_kall2);
    cudaGetSymbolAddress((void**)&pvallh, g_vallh);
    cudaGetSymbolAddress((void**)&psq2,   g_sq2);
    cudaGetSymbolAddress((void**)&psqh,   g_sqh);
    cudaGetSymbolAddress((void**)&pwpT,   g_wpT2);
    cudaGetSymbolAddress((void**)&pwc,    g_wc2);
    cudaGetSymbolAddress((void**)&pwxqkv, g_wxqkv2);
    cudaGetSymbolAddress((void**)&pwxo,   g_wxo2);
    cudaGetSymbolAddress((void**)&pwmx1,  g_wmx1);
    cudaGetSymbolAddress((void**)&pwmx2,  g_wmx2);
    cudaGetSymbolAddress((void**)&pwsqkv, g_wsqkv2);
    cudaGetSymbolAddress((void**)&pwso,   g_wso2);
    cudaGetSymbolAddress((void**)&pwms1,  g_wms1);
    cudaGetSymbolAddress((void**)&pwms2,  g_wms2);

    const int BT = B * T, BL = B * LQ;

    // ---- upfront: splits, folded KV weights/bias, K/V batched GEMMs, masks ----
    split_pair<<<dim3(D / 256,   NB * 3 * D), 256>>>(xw_qkv, pwxqkv, D);
    split_pair<<<dim3(D / 256,   NB * D),     256>>>(xw_o,   pwxo,   D);
    split_pair<<<dim3(D / 256,   NB * HID),   256>>>(mx_w1,  pwmx1,  D);
    split_pair<<<dim3(HID / 256, NB * D),     256>>>(mx_w2,  pwmx2,  HID);
    split_pair<<<dim3(D / 256,   NB * 3 * D), 256>>>(sw_qkv, pwsqkv, D);
    split_pair<<<dim3(D / 256,   NB * D),     256>>>(sw_o,   pwso,   D);
    split_pair<<<dim3(D / 256,   NB * HID),   256>>>(ms_w1,  pwms1,  D);
    split_pair<<<dim3(HID / 256, NB * D),     256>>>(ms_w2,  pwms2,  HID);
    split_pair<<<dim3(D_IN / 256, BT),        256>>>(tokens, ptok2,  D_IN);
    tsplit_proj<<<dim3(D / 256, D_IN), 256>>>(proj_w, pwpT);

    // combined KV weights, rearranged [Kall(3072) | Vall(3072)]
    for (int i = 0; i < NB; i++) {
        gemm_mma_h<3><<<dim3(D_IN / 128, 512 / 64), 128, GSMH>>>(
            pwxqkv + ((size_t)i * 3 * D + D) * 2 * D, 2 * D,
            pwpT, 2 * D, pzb, nullptr, pwc + (size_t)(i * 512) * 2 * D_IN, nullptr, D_IN, D);
        gemm_mma_h<3><<<dim3(D_IN / 128, 512 / 64), 128, GSMH>>>(
            pwxqkv + ((size_t)i * 3 * D + 2 * D) * 2 * D, 2 * D,
            pwpT, 2 * D, pzb, nullptr, pwc + (size_t)(3072 + i * 512) * 2 * D_IN, nullptr, D_IN, D);
    }
    kvbias_kernel<<<KVN, 256>>>(xw_qkv, xb_qkv, proj_b, pbc);

    // Kall (split bf16) and Vall (fp16) for all 6 blocks, from tokens (K=256)
    gemm_mma<3><<<dim3(3072 / 128, BT / 128), 256, GSM>>>(
        ptok2, 2 * D_IN, pwc, 2 * D_IN, pbc, nullptr, pkall, nullptr, 3072, D_IN);
    gemm_mma<5><<<dim3(3072 / 128, BT / 128), 256, GSM>>>(
        ptok2, 2 * D_IN, pwc + (size_t)3072 * 2 * D_IN, 2 * D_IN, pbc + 3072,
        nullptr, nullptr, pvallh, 3072, D_IN);

    mask6_kernel<<<dim3(T / 256, LQ, NB), 256>>>(rel_bias, mask_scale, pmask6);
    bcast_latents<<<(BL * D) / 256, 256>>>(latents, plat);

    for (int i = 0; i < NB; i++) {
        const __nv_bfloat16* wq2 = pwxqkv + (size_t)i * 3 * D * 2 * D;
        const float* bqkv = xb_qkv + (size_t)i * 3 * D;

        // ---- cross attention ----
        ln_split<<<BL, 256>>>(plat, lnx_g + i * D, lnx_b + i * D, ptmp2);
        gemm_mma_h<3><<<dim3(D / 128, BL / 64), 128, GSMH>>>(
            ptmp2, 2 * D, wq2, 2 * D, bqkv, nullptr, pq2, nullptr, D, D);
        fattn<<<dim3(LQ / BQ, B * H), 256, FA_SMEM>>>(
            pq2, 2 * D,
            pkall + (size_t)i * 512, 2 * 3072, 3072,
            pvallh + (size_t)i * 512, 3072,
            pmask6 + (size_t)i * LQ * T, pat2, T);
        gemm_mma_h<2><<<dim3(D / 128, BL / 64), 128, GSMH>>>(
            pat2, 2 * D, pwxo + (size_t)i * D * 2 * D, 2 * D, xb_o + i * D,
            plat, nullptr, nullptr, D, D);

        // ---- cross MLP (pre-LN reuses lnx params) ----
        ln_split<<<BL, 256>>>(plat, lnx_g + i * D, lnx_b + i * D, ptmp2);
        gemm_mma_h<1><<<dim3(HID / 128, BL / 64), 128, GSMH>>>(
            ptmp2, 2 * D, pwmx1 + (size_t)i * HID * 2 * D, 2 * D, mx_b1 + i * HID,
            nullptr, phid2, nullptr, HID, D);
        gemm_mma_h<2><<<dim3(D / 128, BL / 64), 128, GSMH>>>(
            phid2, 2 * HID, pwmx2 + (size_t)i * D * 2 * HID, 2 * HID, mx_b2 + i * D,
            plat, nullptr, nullptr, D, HID);

        // ---- self attention ----
        ln_split<<<BL, 256>>>(plat, lns_g + i * D, lns_b + i * D, ptmp2);
        gemm_mma_h<4><<<dim3((3 * D) / 128, BL / 64), 128, GSMH>>>(
            ptmp2, 2 * D, pwsqkv + (size_t)i * 3 * D * 2 * D, 2 * D,
            sb_qkv + (size_t)i * 3 * D, nullptr, psq2, psqh, 3 * D, D);
        fattn<<<dim3(LQ / BQ, B * H), 256, FA_SMEM>>>(
            psq2, 6 * D,
            psq2 + D, 6 * D, 3 * D,
            psqh + 2 * D, 3 * D,
            nullptr, pat2, LQ);
        gemm_mma_h<2><<<dim3(D / 128, BL / 64), 128, GSMH>>>(
            pat2, 2 * D, pwso + (size_t)i * D * 2 * D, 2 * D, sb_o + i * D,
            plat, nullptr, nullptr, D, D);

        // ---- self MLP ----
        ln_split<<<BL, 256>>>(plat, lns_g + i * D, lns_b + i * D, ptmp2);
        gemm_mma_h<1><<<dim3(HID / 128, BL / 64), 128, GSMH>>>(
            ptmp2, 2 * D, pwms1 + (size_t)i * HID * 2 * D, 2 * D, ms_b1 + i * HID,
            nullptr, phid2, nullptr, HID, D);
        gemm_mma_h<2><<<dim3(D / 128, BL / 64), 128, GSMH>>>(
            phid2, 2 * HID, pwms2 + (size_t)i * D * 2 * HID, 2 * HID, ms_b2 + i * D,
            plat, nullptr, nullptr, D, HID);
    }

    // final LN + mean over latents
    ln_kernel<<<BL, 256>>>(plat, lno_g, lno_b, ptmpf);
    mean_kernel<<<(B * D) / 256, 256>>>(ptmpf, out);
}